// round 10
// baseline (speedup 1.0000x reference)
#include <cuda_runtime.h>
#include <cuda_bf16.h>
#include <math.h>
#include <stdint.h>

#define BSZ  2
#define SEQ  1024
#define DM   1024
#define NH   16
#define HDIM 64
#define NL   4
#define VOC  32000
#define NFR  50
#define DLAT 512
#define ROWS (BSZ*SEQ)   // 2048
#define KT   16

// ---------------- scratch (device globals; no allocation allowed) ----------
__device__ float g_h [ROWS*DM];
__device__ float g_q [ROWS*DM];
__device__ float g_k [ROWS*DM];
__device__ float g_v [ROWS*DM];
__device__ float g_kv[ROWS*DM];
__device__ float g_kr[ROWS*DM];
__device__ float g_vr[ROWS*DM];
__device__ float g_lat[ROWS*DLAT];
__device__ float g_four[ROWS*NFR];
__device__ float g_sc[(size_t)BSZ*NH*SEQ*SEQ];   // 134 MB score tensor

// transposed + split weights: [N][K] bf16, hi and lo halves
#define WSZ_DD   (1024*1024)
#define WSZ_HALF (512*1024)
#define LSTRIDE  (4*WSZ_DD + 3*WSZ_HALF)
#define OFF_RULE 0
#define OFF_L(l) ((size_t)WSZ_DD + (size_t)(l)*LSTRIDE)
#define OFF_WOUT ((size_t)WSZ_DD + 4*(size_t)LSTRIDE)
#define WTOT     (OFF_WOUT + (size_t)VOC*DM)
__device__ __align__(16) __nv_bfloat16 g_wbh[WTOT];
__device__ __align__(16) __nv_bfloat16 g_wbl[WTOT];

// ---------------- f32x2 packed helpers (Blackwell FFMA2) -------------------
__device__ __forceinline__ unsigned long long pk2(float lo, float hi) {
    unsigned long long r;
    asm("mov.b64 %0, {%1, %2};" : "=l"(r) : "f"(lo), "f"(hi));
    return r;
}
__device__ __forceinline__ unsigned long long ffma2(
    unsigned long long a, unsigned long long b, unsigned long long c) {
    unsigned long long d;
    asm("fma.rn.f32x2 %0, %1, %2, %3;" : "=l"(d) : "l"(a), "l"(b), "l"(c));
    return d;
}
__device__ __forceinline__ float2 up2(unsigned long long v) {
    float2 f;
    asm("mov.b64 {%0, %1}, %2;" : "=f"(f.x), "=f"(f.y) : "l"(v));
    return f;
}

// ---------------- misc helpers ---------------------------------------------
__device__ __forceinline__ uint32_t smem_to_u32(const void* p) {
    uint32_t a;
    asm("{ .reg .u64 t; cvta.to.shared.u64 t, %1; cvt.u32.u64 %0, t; }" : "=r"(a) : "l"(p));
    return a;
}
__device__ __forceinline__ uint32_t bfpack(float lo, float hi) {
    uint32_t r;
    asm("cvt.rn.bf16x2.f32 %0, %1, %2;" : "=r"(r) : "f"(hi), "f"(lo));
    return r;
}
__device__ __forceinline__ float bflo(uint32_t p) { return __uint_as_float(p << 16); }
__device__ __forceinline__ float bfhi(uint32_t p) { return __uint_as_float(p & 0xffff0000u); }
#define STS128(addr, a, b, c, d) \
    asm volatile("st.shared.v4.b32 [%0], {%1, %2, %3, %4};" \
        :: "r"(addr), "r"(a), "r"(b), "r"(c), "r"(d) : "memory")
#define LDSM_X4(r0, r1, r2, r3, addr) \
    asm volatile("ldmatrix.sync.aligned.m8n8.x4.shared.b16 {%0,%1,%2,%3}, [%4];" \
        : "=r"(r0), "=r"(r1), "=r"(r2), "=r"(r3) : "r"(addr))
#define LDSM_X2(r0, r1, addr) \
    asm volatile("ldmatrix.sync.aligned.m8n8.x2.shared.b16 {%0,%1}, [%2];" \
        : "=r"(r0), "=r"(r1) : "r"(addr))
#define LDSM_X2T(r0, r1, addr) \
    asm volatile("ldmatrix.sync.aligned.m8n8.x2.trans.shared.b16 {%0,%1}, [%2];" \
        : "=r"(r0), "=r"(r1) : "r"(addr))
#define MMA16816(d, a0, a1, a2, a3, b0, b1) \
    asm volatile("mma.sync.aligned.m16n8k16.row.col.f32.bf16.bf16.f32 " \
        "{%0,%1,%2,%3}, {%4,%5,%6,%7}, {%8,%9}, {%0,%1,%2,%3};" \
        : "+f"((d)[0]), "+f"((d)[1]), "+f"((d)[2]), "+f"((d)[3]) \
        : "r"(a0), "r"(a1), "r"(a2), "r"(a3), "r"(b0), "r"(b1))
#define CPASYNC16(smem, gptr) \
    asm volatile("cp.async.cg.shared.global [%0], [%1], 16;" \
        :: "r"(smem), "l"(gptr) : "memory")
#define CPCOMMIT() asm volatile("cp.async.commit_group;" ::: "memory")
#define CPWAIT0()  asm volatile("cp.async.wait_group 0;" ::: "memory")

// ================= weight transpose + bf16 split: W[K,N] -> T[N,K] =========
__global__ __launch_bounds__(256) void wsplit_k(
    const float* __restrict__ W, int K, int N,
    __nv_bfloat16* __restrict__ Th, __nv_bfloat16* __restrict__ Tl)
{
    __shared__ float t[32][33];
    const int k0 = blockIdx.y * 32, n0 = blockIdx.x * 32;
    const int tx = threadIdx.x, ty = threadIdx.y;   // (32,8)
#pragma unroll
    for (int i = 0; i < 4; i++)
        t[ty + 8 * i][tx] = W[(size_t)(k0 + ty + 8 * i) * N + n0 + tx];
    __syncthreads();
#pragma unroll
    for (int i = 0; i < 4; i++) {
        int n = n0 + ty + 8 * i, k = k0 + tx;
        float w = t[tx][ty + 8 * i];
        __nv_bfloat16 h = __float2bfloat16(w);
        float lo = w - __bfloat162float(h);
        Th[(size_t)n * K + k] = h;
        Tl[(size_t)n * K + k] = __float2bfloat16(lo);
    }
}

// ================= HMMA bf16-split GEMM (B via cp.async) ===================
#define ASTR   40                       // bf16 elems per smem row (80 bytes)
#define TILEB  (128*80)
#define OAH    0
#define OAL    (TILEB)
#define OBH    (2*TILEB)
#define OBL    (3*TILEB)
#define BUFSTR (4*TILEB)
#define DSMG   (2*BUFSTR)               // 81920

__global__ __launch_bounds__(256) void gemm_mma(
    int M, int N, int K,
    const float* __restrict__ A,
    const __nv_bfloat16* __restrict__ Bh, const __nv_bfloat16* __restrict__ Bl,
    const float* __restrict__ bias, float* __restrict__ C)
{
    extern __shared__ char smem[];
    const uint32_t sb = smem_to_u32(smem);
    const int tid = threadIdx.x, lane = tid & 31, wid = tid >> 5;
    const int brow = blockIdx.y * 128, bcol = blockIdx.x * 128;
    const int wm = wid & 1, wn = wid >> 1;

    const int lrow = tid >> 1, lhalf = tid & 1;
    const float* Ap          = A  + (size_t)(brow + lrow) * K + lhalf * 16;
    const __nv_bfloat16* Bhp = Bh + (size_t)(bcol + lrow) * K + lhalf * 16;
    const __nv_bfloat16* Blp = Bl + (size_t)(bcol + lrow) * K + lhalf * 16;
    const uint32_t soff = (uint32_t)(lrow * ASTR + lhalf * 16) * 2;

    float acc[4][4][4];
#pragma unroll
    for (int i = 0; i < 4; i++)
#pragma unroll
        for (int j = 0; j < 4; j++)
#pragma unroll
            for (int e = 0; e < 4; e++) acc[i][j][e] = 0.f;

    float4 pa[4];

#define LOADA(k0) do { \
    pa[0] = *(const float4*)(Ap + (k0));      pa[1] = *(const float4*)(Ap + (k0) + 4); \
    pa[2] = *(const float4*)(Ap + (k0) + 8);  pa[3] = *(const float4*)(Ap + (k0) + 12); \
} while (0)

#define LOADB_ASYNC(k0, b) do { \
    uint32_t base_ = sb + (uint32_t)(b) * BUFSTR; \
    CPASYNC16(base_ + OBH + soff,      Bhp + (k0)); \
    CPASYNC16(base_ + OBH + soff + 16, Bhp + (k0) + 8); \
    CPASYNC16(base_ + OBL + soff,      Blp + (k0)); \
    CPASYNC16(base_ + OBL + soff + 16, Blp + (k0) + 8); \
} while (0)

#define STOREA(b) do { \
    uint32_t hh[8], ll[8]; \
    _Pragma("unroll") \
    for (int i = 0; i < 4; i++) { \
        float4 x = pa[i]; \
        uint32_t h0 = bfpack(x.x, x.y), h1 = bfpack(x.z, x.w); \
        uint32_t l0 = bfpack(x.x - bflo(h0), x.y - bfhi(h0)); \
        uint32_t l1 = bfpack(x.z - bflo(h1), x.w - bfhi(h1)); \
        hh[2*i] = h0; hh[2*i+1] = h1; ll[2*i] = l0; ll[2*i+1] = l1; \
    } \
    uint32_t base_ = sb + (uint32_t)(b) * BUFSTR; \
    STS128(base_ + OAH + soff,      hh[0], hh[1], hh[2], hh[3]); \
    STS128(base_ + OAH + soff + 16, hh[4], hh[5], hh[6], hh[7]); \
    STS128(base_ + OAL + soff,      ll[0], ll[1], ll[2], ll[3]); \
    STS128(base_ + OAL + soff + 16, ll[4], ll[5], ll[6], ll[7]); \
} while (0)

    const int nchunk = K / 32;
    LOADB_ASYNC(0, 0);
    CPCOMMIT();
    LOADA(0);
    STOREA(0);
    CPWAIT0();
    __syncthreads();

    const uint32_t arow = (uint32_t)(wm * 64 + (lane & 15));
    const uint32_t acol = (uint32_t)((lane >> 4) * 8);
    const uint32_t brw  = (uint32_t)(wn * 32 + (lane & 7));
    const uint32_t bcl  = (uint32_t)(((lane >> 3) & 1) * 8);

    int buf = 0;
    for (int ck = 0; ck < nchunk; ck++) {
        if (ck + 1 < nchunk) {
            LOADB_ASYNC((ck + 1) * 32, buf ^ 1);
            CPCOMMIT();
            LOADA((ck + 1) * 32);
        }

        const uint32_t base = sb + (uint32_t)buf * BUFSTR;
#pragma unroll
        for (int ks = 0; ks < 2; ks++) {
            uint32_t ah[4][4], al[4][4];
#pragma unroll
            for (int mt = 0; mt < 4; mt++) {
                uint32_t aoff = ((arow + mt * 16) * ASTR + acol + ks * 16) * 2;
                LDSM_X4(ah[mt][0], ah[mt][1], ah[mt][2], ah[mt][3], base + OAH + aoff);
                LDSM_X4(al[mt][0], al[mt][1], al[mt][2], al[mt][3], base + OAL + aoff);
            }
#pragma unroll
            for (int nt = 0; nt < 4; nt++) {
                uint32_t boff = ((brw + nt * 8) * ASTR + bcl + ks * 16) * 2;
                uint32_t bh0, bh1, bl0, bl1;
                LDSM_X2(bh0, bh1, base + OBH + boff);
                LDSM_X2(bl0, bl1, base + OBL + boff);
#pragma unroll
                for (int mt = 0; mt < 4; mt++) {
                    MMA16816(acc[mt][nt], ah[mt][0], ah[mt][1], ah[mt][2], ah[mt][3], bh0, bh1);
                    MMA16816(acc[mt][nt], ah[mt][0], ah[mt][1], ah[mt][2], ah[mt][3], bl0, bl1);
                    MMA16816(acc[mt][nt], al[mt][0], al[mt][1], al[mt][2], al[mt][3], bh0, bh1);
                }
            }
        }
        if (ck + 1 < nchunk) STOREA(buf ^ 1);
        CPWAIT0();
        __syncthreads();
        buf ^= 1;
    }

#pragma unroll
    for (int mt = 0; mt < 4; mt++) {
        int r0 = brow + wm * 64 + mt * 16 + (lane >> 2);
#pragma unroll
        for (int nt = 0; nt < 4; nt++) {
            int c = bcol + wn * 32 + nt * 8 + (lane & 3) * 2;
            float bx = 0.f, by = 0.f;
            if (bias) { bx = bias[c]; by = bias[c + 1]; }
            float2 o0, o1;
            o0.x = acc[mt][nt][0] + bx; o0.y = acc[mt][nt][1] + by;
            o1.x = acc[mt][nt][2] + bx; o1.y = acc[mt][nt][3] + by;
            *(float2*)(C + (size_t)r0 * N + c)       = o0;
            *(float2*)(C + (size_t)(r0 + 8) * N + c) = o1;
        }
    }
#undef LOADA
#undef LOADB_ASYNC
#undef STOREA
}

// ================= HMMA split attention: scores ============================
#define SCTAB 40960
#define DSMS  (40960 + 1024)

__global__ __launch_bounds__(256) void scores_hmma(
    const float* __restrict__ Q, const float* __restrict__ Kc, float* __restrict__ Sc)
{
    extern __shared__ char smem[];
    const uint32_t sb = smem_to_u32(smem);
    float* tab = (float*)(smem + SCTAB);
    const int OQH = 0, OQL = 10240, OKH = 20480, OKL = 30720;
    const int tid = threadIdx.x, lane = tid & 31, wid = tid >> 5;
    const int bh = blockIdx.z, b = bh >> 4, h = bh & 15;
    const int i0 = blockIdx.y * 128, j0 = blockIdx.x * 128;
    const int wm = wid & 1, wn = wid >> 1;

    tab[tid] = __expf(-0.01f * fabsf((float)(i0 - j0 + tid - 128)));

    const int lrow = tid >> 1, lseg = tid & 1;
    {
        const float* qp = Q  + (size_t)(b * SEQ + i0 + lrow) * DM + h * HDIM + lseg * 32;
        const float* kp = Kc + (size_t)(b * SEQ + j0 + lrow) * DM + h * HDIM + lseg * 32;
        const uint32_t off = (uint32_t)(lrow * ASTR + lseg * 32) * 2;
#pragma unroll
        for (int half = 0; half < 2; half++) {
            const float* p = half ? kp : qp;
            const uint32_t oh = half ? OKH : OQH, ol = half ? OKL : OQL;
            uint32_t hh[16], ll[16];
#pragma unroll
            for (int i = 0; i < 8; i++) {
                float4 x = *(const float4*)(p + i * 4);
                uint32_t h0 = bfpack(x.x, x.y), h1 = bfpack(x.z, x.w);
                hh[2*i] = h0; hh[2*i+1] = h1;
                ll[2*i]   = bfpack(x.x - bflo(h0), x.y - bfhi(h0));
                ll[2*i+1] = bfpack(x.z - bflo(h1), x.w - bfhi(h1));
            }
#pragma unroll
            for (int i = 0; i < 4; i++) {
                STS128(sb + oh + off + i * 16, hh[4*i], hh[4*i+1], hh[4*i+2], hh[4*i+3]);
                STS128(sb + ol + off + i * 16, ll[4*i], ll[4*i+1], ll[4*i+2], ll[4*i+3]);
            }
        }
    }
    __syncthreads();

    float acc[4][4][4];
#pragma unroll
    for (int i = 0; i < 4; i++)
#pragma unroll
        for (int j = 0; j < 4; j++)
#pragma unroll
            for (int e = 0; e < 4; e++) acc[i][j][e] = 0.f;

    const uint32_t arow = (uint32_t)(wm * 64 + (lane & 15));
    const uint32_t acol = (uint32_t)((lane >> 4) * 8);
    const uint32_t brw  = (uint32_t)(wn * 32 + (lane & 7));
    const uint32_t bcl  = (uint32_t)(((lane >> 3) & 1) * 8);

#pragma unroll
    for (int ks = 0; ks < 4; ks++) {
        uint32_t ah[4][4], al[4][4];
#pragma unroll
        for (int mt = 0; mt < 4; mt++) {
            uint32_t aoff = ((arow + mt * 16) * ASTR + acol + ks * 16) * 2;
            LDSM_X4(ah[mt][0], ah[mt][1], ah[mt][2], ah[mt][3], sb + OQH + aoff);
            LDSM_X4(al[mt][0], al[mt][1], al[mt][2], al[mt][3], sb + OQL + aoff);
        }
#pragma unroll
        for (int nt = 0; nt < 4; nt++) {
            uint32_t boff = ((brw + nt * 8) * ASTR + bcl + ks * 16) * 2;
            uint32_t bh0, bh1, bl0, bl1;
            LDSM_X2(bh0, bh1, sb + OKH + boff);
            LDSM_X2(bl0, bl1, sb + OKL + boff);
#pragma unroll
            for (int mt = 0; mt < 4; mt++) {
                MMA16816(acc[mt][nt], ah[mt][0], ah[mt][1], ah[mt][2], ah[mt][3], bh0, bh1);
                MMA16816(acc[mt][nt], ah[mt][0], ah[mt][1], ah[mt][2], ah[mt][3], bl0, bl1);
                MMA16816(acc[mt][nt], al[mt][0], al[mt][1], al[mt][2], al[mt][3], bh0, bh1);
            }
        }
    }

    const float scale = 0.03125f;
#pragma unroll
    for (int mt = 0; mt < 4; mt++) {
        int ri = wm * 64 + mt * 16 + (lane >> 2);
#pragma unroll
        for (int nt = 0; nt < 4; nt++) {
            int cj = wn * 32 + nt * 8 + (lane & 3) * 2;
            int d0 = ri - cj + 128;
            float2 o0, o1;
            o0.x = acc[mt][nt][0] * scale * tab[d0];
            o0.y = acc[mt][nt][1] * scale * tab[d0 - 1];
            o1.x = acc[mt][nt][2] * scale * tab[d0 + 8];
            o1.y = acc[mt][nt][3] * scale * tab[d0 + 7];
            *(float2*)(Sc + ((size_t)bh * SEQ + i0 + ri) * SEQ + j0 + cj)       = o0;
            *(float2*)(Sc + ((size_t)bh * SEQ + i0 + ri + 8) * SEQ + j0 + cj)   = o1;
        }
    }
}

// ================= HMMA split attention: O = P @ V =========================
#define VSTR  72
#define OPH2  0
#define OPL2  10240
#define OVH2  20480
#define OVL2  25088
#define BUF2  29696
#define DSMA  (2*BUF2)

__global__ __launch_bounds__(256) void av_hmma(
    const float* __restrict__ P, const float* __restrict__ V, float* __restrict__ O)
{
    extern __shared__ char smem[];
    const uint32_t sb = smem_to_u32(smem);
    const int tid = threadIdx.x, lane = tid & 31, wid = tid >> 5;
    const int bh = blockIdx.y, b = bh >> 4, h = bh & 15;
    const int i0 = blockIdx.x * 128;
    const int wm = wid & 3, wn = wid >> 2;

    const int lrow = tid >> 1, lseg = tid & 1;
    const float* Pp = P + ((size_t)bh * SEQ + i0 + lrow) * SEQ + lseg * 16;
    const uint32_t poff = (uint32_t)(lrow * ASTR + lseg * 16) * 2;

    const int vj = tid >> 3, vd = (tid & 7) * 8;
    const float* Vp = V + (size_t)(b * SEQ + vj) * DM + h * HDIM + vd;
    const uint32_t voff = (uint32_t)(vj * VSTR + vd) * 2;

    float acc[2][4][4];
#pragma unroll
    for (int i = 0; i < 2; i++)
#pragma unroll
        for (int j = 0; j < 4; j++)
#pragma unroll
            for (int e = 0; e < 4; e++) acc[i][j][e] = 0.f;

    float4 pa[4], pv[2];

#define LOADG2(k0) do { \
    pa[0] = *(const float4*)(Pp + (k0));      pa[1] = *(const float4*)(Pp + (k0) + 4); \
    pa[2] = *(const float4*)(Pp + (k0) + 8);  pa[3] = *(const float4*)(Pp + (k0) + 12); \
    pv[0] = *(const float4*)(Vp + (size_t)(k0) * DM); \
    pv[1] = *(const float4*)(Vp + (size_t)(k0) * DM + 4); \
} while (0)

#define STOREBUF2(bf) do { \
    uint32_t hh[8], ll[8]; \
    _Pragma("unroll") \
    for (int i = 0; i < 4; i++) { \
        float4 x = pa[i]; \
        uint32_t h0 = bfpack(x.x, x.y), h1 = bfpack(x.z, x.w); \
        hh[2*i] = h0; hh[2*i+1] = h1; \
        ll[2*i]   = bfpack(x.x - bflo(h0), x.y - bfhi(h0)); \
        ll[2*i+1] = bfpack(x.z - bflo(h1), x.w - bfhi(h1)); \
    } \
    uint32_t vh[4], vl[4]; \
    _Pragma("unroll") \
    for (int i = 0; i < 2; i++) { \
        float4 x = pv[i]; \
        uint32_t h0 = bfpack(x.x, x.y), h1 = bfpack(x.z, x.w); \
        vh[2*i] = h0; vh[2*i+1] = h1; \
        vl[2*i]   = bfpack(x.x - bflo(h0), x.y - bfhi(h0)); \
        vl[2*i+1] = bfpack(x.z - bflo(h1), x.w - bfhi(h1)); \
    } \
    uint32_t base_ = sb + (uint32_t)(bf) * BUF2; \
    STS128(base_ + OPH2 + poff,      hh[0], hh[1], hh[2], hh[3]); \
    STS128(base_ + OPH2 + poff + 16, hh[4], hh[5], hh[6], hh[7]); \
    STS128(base_ + OPL2 + poff,      ll[0], ll[1], ll[2], ll[3]); \
    STS128(base_ + OPL2 + poff + 16, ll[4], ll[5], ll[6], ll[7]); \
    STS128(base_ + OVH2 + voff, vh[0], vh[1], vh[2], vh[3]); \
    STS128(base_ + OVL2 + voff, vl[0], vl[1], vl[2], vl[3]); \
} while (0)

    const int nchunk = SEQ / 32;
    LOADG2(0);
    STOREBUF2(0);
    __syncthreads();

    const uint32_t arow = (uint32_t)(wm * 32 + (lane & 15));
    const uint32_t acol = (uint32_t)((lane >> 4) * 8);
    const uint32_t kl   = (uint32_t)(lane & 15);

    int buf = 0;
    for (int ck = 0; ck < nchunk; ck++) {
        if (ck + 1 < nchunk) LOADG2((ck + 1) * 32);

        const uint32_t base = sb + (uint32_t)buf * BUF2;
#pragma unroll
        for (int ks = 0; ks < 2; ks++) {
            uint32_t ah[2][4], al[2][4];
#pragma unroll
            for (int mt = 0; mt < 2; mt++) {
                uint32_t aoff = ((arow + mt * 16) * ASTR + acol + ks * 16) * 2;
                LDSM_X4(ah[mt][0], ah[mt][1], ah[mt][2], ah[mt][3], base + OPH2 + aoff);
                LDSM_X4(al[mt][0], al[mt][1], al[mt][2], al[mt][3], base + OPL2 + aoff);
            }
#pragma unroll
            for (int nt = 0; nt < 4; nt++) {
                uint32_t boff = ((ks * 16 + kl) * VSTR + wn * 32 + nt * 8) * 2;
                uint32_t bh0, bh1, bl0, bl1;
                LDSM_X2T(bh0, bh1, base + OVH2 + boff);
                LDSM_X2T(bl0, bl1, base + OVL2 + boff);
#pragma unroll
                for (int mt = 0; mt < 2; mt++) {
                    MMA16816(acc[mt][nt], ah[mt][0], ah[mt][1], ah[mt][2], ah[mt][3], bh0, bh1);
                    MMA16816(acc[mt][nt], ah[mt][0], ah[mt][1], ah[mt][2], ah[mt][3], bl0, bl1);
                    MMA16816(acc[mt][nt], al[mt][0], al[mt][1], al[mt][2], al[mt][3], bh0, bh1);
                }
            }
        }
        if (ck + 1 < nchunk) STOREBUF2(buf ^ 1);
        __syncthreads();
        buf ^= 1;
    }

#pragma unroll
    for (int mt = 0; mt < 2; mt++) {
        int r0 = i0 + wm * 32 + mt * 16 + (lane >> 2);
#pragma unroll
        for (int nt = 0; nt < 4; nt++) {
            int c = h * HDIM + wn * 32 + nt * 8 + (lane & 3) * 2;
            float2 o0, o1;
            o0.x = acc[mt][nt][0]; o0.y = acc[mt][nt][1];
            o1.x = acc[mt][nt][2]; o1.y = acc[mt][nt][3];
            *(float2*)(O + (size_t)(b * SEQ + r0) * DM + c)       = o0;
            *(float2*)(O + (size_t)(b * SEQ + r0 + 8) * DM + c)   = o1;
        }
    }
#undef LOADG2
#undef STOREBUF2
}

// ---------------- FFMA2 SGEMM (kept for the K=50 embedding GEMM) -----------
__global__ __launch_bounds__(256) void sgemm2_k(
    int M, int N, int K,
    const float* __restrict__ A, const float* __restrict__ B,
    const float* __restrict__ bias, float* __restrict__ C)
{
    __shared__ __align__(16) float As[KT][128];
    __shared__ __align__(16) float Bs[KT][128];
    const int tid  = threadIdx.x;
    const int brow = blockIdx.y * 128;
    const int bcol = blockIdx.x * 128;
    const int ty = tid >> 4, tx = tid & 15;
    const int ar = tid >> 1, aks = (tid & 1) * 8;

    unsigned long long acc[8][4];
#pragma unroll
    for (int i = 0; i < 8; i++)
#pragma unroll
        for (int j = 0; j < 4; j++) acc[i][j] = 0ULL;

    for (int k0 = 0; k0 < K; k0 += KT) {
#pragma unroll
        for (int i = 0; i < 8; i++) {
            int kk = aks + i;
            As[kk][ar] = (k0 + kk < K) ? A[(size_t)(brow + ar) * K + k0 + kk] : 0.f;
        }
#pragma unroll
        for (int p = 0; p < 2; p++) {
            int id = p * 256 + tid;
            int kk = id >> 5, c4 = (id & 31) * 4;
            float4 bv = make_float4(0.f, 0.f, 0.f, 0.f);
            if (k0 + kk < K) bv = *(const float4*)(B + (size_t)(k0 + kk) * N + bcol + c4);
            *(float4*)&Bs[kk][c4] = bv;
        }
        __syncthreads();
#pragma unroll
        for (int kk = 0; kk < KT; kk++) {
            float4 a0 = *(const float4*)&As[kk][ty * 4];
            float4 a1 = *(const float4*)&As[kk][64 + ty * 4];
            float4 b0 = *(const float4*)&Bs[kk][tx * 4];
            float4 b1 = *(const float4*)&Bs[kk][64 + tx * 4];
            unsigned long long rb[4] = { pk2(b0.x, b0.y), pk2(b0.z, b0.w),
                                         pk2(b1.x, b1.y), pk2(b1.z, b1.w) };
            float ra[8] = { a0.x, a0.y, a0.z, a0.w, a1.x, a1.y, a1.z, a1.w };
#pragma unroll
            for (int i = 0; i < 8; i++) {
                unsigned long long ad = pk2(ra[i], ra[i]);
#pragma unroll
                for (int j = 0; j < 4; j++) acc[i][j] = ffma2(ad, rb[j], acc[i][j]);
            }
        }
        __syncthreads();
    }
#pragma unroll
    for (int ih = 0; ih < 2; ih++)
#pragma unroll
    for (int ii = 0; ii < 4; ii++) {
        int i = ih * 4 + ii;
        int r = brow + ih * 64 + ty * 4 + ii;
#pragma unroll
        for (int jh = 0; jh < 2; jh++) {
            int c = bcol + jh * 64 + tx * 4;
            float2 p0 = up2(acc[i][jh * 2]);
            float2 p1 = up2(acc[i][jh * 2 + 1]);
            float4 o; o.x = p0.x; o.y = p0.y; o.z = p1.x; o.w = p1.y;
            if (bias) { o.x += bias[c]; o.y += bias[c+1]; o.z += bias[c+2]; o.w += bias[c+3]; }
            *(float4*)(C + (size_t)r * N + c) = o;
        }
    }
}

// ---------------- Fourier token features -----------------------------------
__global__ void fourier_k(const int* __restrict__ src, const float* __restrict__ a_n,
                          const float* __restrict__ b_n, float* __restrict__ F)
{
    int idx = blockIdx.x * blockDim.x + threadIdx.x;
    if (idx >= ROWS * NFR) return;
    int bs = idx / NFR, n = idx % NFR;
    int tok = src[bs];
    float x   = (float)tok * (1.0f / (float)VOC);
    float ang = 6.28318530717958647692f * (float)(n + 1) * x;
    F[idx] = a_n[tok * NFR + n] * cosf(ang) + b_n[tok * NFR + n] * sinf(ang);
}

// ---------------- h += sinusoidal PE ---------------------------------------
__global__ void addpe_k(float* __restrict__ h)
{
    int idx = blockIdx.x * blockDim.x + threadIdx.x;
    if (idx >= ROWS * DM) return;
    int d = idx & (DM - 1);
    int s = (idx / DM) & (SEQ - 1);
    float div = expf(-(float)(d & ~1) * 8.99447301948846e-3f);
    float ang = (float)s * div;
    h[idx] += (d & 1) ? cosf(ang) : sinf(ang);
}

__global__ void add_k(const float* __restrict__ a, const float* __restrict__ b,
                      float* __restrict__ c, int n)
{
    int i = blockIdx.x * blockDim.x + threadIdx.x;
    if (i < n) c[i] = a[i] + b[i];
}

// ---------------- row softmax ----------------------------------------------
__global__ __launch_bounds__(256) void softmax_k(float* __restrict__ Sc)
{
    __shared__ float red[256];
    float* p = Sc + (size_t)blockIdx.x * SEQ;
    const int t = threadIdx.x;
    float v0 = p[t], v1 = p[t + 256], v2 = p[t + 512], v3 = p[t + 768];
    float mx = fmaxf(fmaxf(v0, v1), fmaxf(v2, v3));
    red[t] = mx; __syncthreads();
    for (int s = 128; s > 0; s >>= 1) { if (t < s) red[t] = fmaxf(red[t], red[t + s]); __syncthreads(); }
    mx = red[0]; __syncthreads();
    v0 = __expf(v0 - mx); v1 = __expf(v1 - mx); v2 = __expf(v2 - mx); v3 = __expf(v3 - mx);
    float sm = v0 + v1 + v2 + v3;
    red[t] = sm; __syncthreads();
    for (int s = 128; s > 0; s >>= 1) { if (t < s) red[t] += red[t + s]; __syncthreads(); }
    float inv = 1.0f / red[0];
    p[t] = v0 * inv; p[t + 256] = v1 * inv; p[t + 512] = v2 * inv; p[t + 768] = v3 * inv;
}

// ---------------------------------------------------------------------------
extern "C" void kernel_launch(void* const* d_in, const int* in_sizes, int n_in,
                              void* d_out, int out_size)
{
    const int*   src    = (const int*)  d_in[0];
    const float* a_n    = (const float*)d_in[2];
    const float* b_n    = (const float*)d_in[3];
    const float* proj_w = (const float*)d_in[4];
    const float* proj_b = (const float*)d_in[5];
    const float* rule   = (const float*)d_in[6];
    const float* Wq     = (const float*)d_in[7];
    const float* Wk     = (const float*)d_in[8];
    const float* Wv     = (const float*)d_in[9];
    const float* Wo     = (const float*)d_in[10];
    const float* Wdown  = (const float*)d_in[11];
    const float* Wup_k  = (const float*)d_in[12];
    const float* Wup_v  = (const float*)d_in[13];
    const float* Wout   = (const float*)d_in[14];
    const float* bout   = (const float*)d_in[15];
    float* out = (float*)d_out;

    float *h, *q, *k, *v, *kv, *kr, *vr, *lat, *four, *sc;
    __nv_bfloat16 *wbh, *wbl;
    cudaGetSymbolAddress((void**)&h,    g_h);
    cudaGetSymbolAddress((void**)&q,    g_q);
    cudaGetSymbolAddress((void**)&k,    g_k);
    cudaGetSymbolAddress((void**)&v,    g_v);
    cudaGetSymbolAddress((void**)&kv,   g_kv);
    cudaGetSymbolAddress((void**)&kr,   g_kr);
    cudaGetSymbolAddress((void**)&vr,   g_vr);
    cudaGetSymbolAddress((void**)&lat,  g_lat);
    cudaGetSymbolAddress((void**)&four, g_four);
    cudaGetSymbolAddress((void**)&sc,   g_sc);
    cudaGetSymbolAddress((void**)&wbh,  g_wbh);
    cudaGetSymbolAddress((void**)&wbl,  g_wbl);

    cudaFuncSetAttribute(gemm_mma,    cudaFuncAttributeMaxDynamicSharedMemorySize, DSMG);
    cudaFuncSetAttribute(scores_hmma, cudaFuncAttributeMaxDynamicSharedMemorySize, DSMS);
    cudaFuncSetAttribute(av_hmma,     cudaFuncAttributeMaxDynamicSharedMemorySize, DSMA);

    // ---- transpose + split all weights into [N,K] bf16 hi/lo ----
    {
        const dim3 b(32, 8);
        wsplit_k<<<dim3(DM/32, DM/32), b>>>(rule, DM, DM, wbh + OFF_RULE, wbl + OFF_RULE);
        for (int l = 0; l < NL; l++) {
            size_t o = OFF_L(l);
            wsplit_k<<<dim3(DM/32, DM/32), b>>>(Wq + (size_t)l*DM*DM, DM, DM, wbh+o, wbl+o);
            wsplit_k<<<dim3(DM/32, DM/32), b>>>(Wk + (size_t)l*DM*DM, DM, DM, wbh+o+WSZ_DD, wbl+o+WSZ_DD);
            wsplit_k<<<dim3(DM/32, DM/32), b>>>(Wv + (size_t)l*DM*DM, DM, DM, wbh+o+2*WSZ_DD, wbl+o+2*WSZ_DD);
            wsplit_k<<<dim3(DM/32, DM/32), b>>>(Wo + (size_t)l*DM*DM, DM, DM, wbh+o+3*WSZ_DD, wbl+o+3*WSZ_DD);
            wsplit_k<<<dim3(DLAT/32, DM/32), b>>>(Wdown + (size_t)l*DM*DLAT, DM, DLAT,
                                                  wbh+o+4*WSZ_DD, wbl+o+4*WSZ_DD);
            wsplit_k<<<dim3(DM/32, DLAT/32), b>>>(Wup_k + (size_t)l*DLAT*DM, DLAT, DM,
                                                  wbh+o+4*WSZ_DD+WSZ_HALF, wbl+o+4*WSZ_DD+WSZ_HALF);
            wsplit_k<<<dim3(DM/32, DLAT/32), b>>>(Wup_v + (size_t)l*DLAT*DM, DLAT, DM,
                                                  wbh+o+4*WSZ_DD+2*WSZ_HALF, wbl+o+4*WSZ_DD+2*WSZ_HALF);
        }
        wsplit_k<<<dim3(VOC/32, DM/32), b>>>(Wout, DM, VOC, wbh + OFF_WOUT, wbl + OFF_WOUT);
    }

    const dim3 g_d  (DM   / 128, ROWS / 128);
    const dim3 g_dl (DLAT / 128, ROWS / 128);
    const dim3 g_voc(VOC  / 128, ROWS / 128);

    // ---- embedding ----
    fourier_k<<<(ROWS * NFR + 255) / 256, 256>>>(src, a_n, b_n, four);
    sgemm2_k<<<g_d, 256>>>(ROWS, DM, NFR, four, proj_w, proj_b, q);
    gemm_mma<<<g_d, 256, DSMG>>>(ROWS, DM, DM, q, wbh + OFF_RULE, wbl + OFF_RULE, nullptr, h);
    addpe_k<<<(ROWS * DM + 255) / 256, 256>>>(h);

    // ---- layers ----
    for (int l = 0; l < NL; l++) {
        size_t o = OFF_L(l);
        const __nv_bfloat16 *qh = wbh+o,             *ql = wbl+o;
        const __nv_bfloat16 *kh = wbh+o+WSZ_DD,      *kl = wbl+o+WSZ_DD;
        const __nv_bfloat16 *vh = wbh+o+2*WSZ_DD,    *vl = wbl+o+2*WSZ_DD;
        const __nv_bfloat16 *oh = wbh+o+3*WSZ_DD,    *ol = wbl+o+3*WSZ_DD;
        const __nv_bfloat16 *dh = wbh+o+4*WSZ_DD,    *dl = wbl+o+4*WSZ_DD;
        const __nv_bfloat16 *ukh= wbh+o+4*WSZ_DD+WSZ_HALF,   *ukl= wbl+o+4*WSZ_DD+WSZ_HALF;
        const __nv_bfloat16 *uvh= wbh+o+4*WSZ_DD+2*WSZ_HALF, *uvl= wbl+o+4*WSZ_DD+2*WSZ_HALF;

        gemm_mma<<<g_d, 256, DSMG>>>(ROWS, DM, DM, h, qh, ql, nullptr, q);
        gemm_mma<<<g_d, 256, DSMG>>>(ROWS, DM, DM, h, kh, kl, nullptr, k);
        gemm_mma<<<g_d, 256, DSMG>>>(ROWS, DM, DM, h, vh, vl, nullptr, v);
        add_k<<<(ROWS * DM + 255) / 256, 256>>>(k, v, kv, ROWS * DM);
        gemm_mma<<<g_dl, 256, DSMG>>>(ROWS, DLAT, DM, kv, dh, dl, nullptr, lat);
        gemm_mma<<<g_d, 256, DSMG>>>(ROWS, DM, DLAT, lat, ukh, ukl, nullptr, kr);
        gemm_mma<<<g_d, 256, DSMG>>>(ROWS, DM, DLAT, lat, uvh, uvl, nullptr, vr);

        scores_hmma<<<dim3(SEQ/128, SEQ/128, BSZ*NH), 256, DSMS>>>(q, kr, sc);
        softmax_k<<<BSZ*NH*SEQ, 256>>>(sc);
        av_hmma<<<dim3(SEQ/128, BSZ*NH), 256, DSMA>>>(sc, vr, kv);

        gemm_mma<<<g_d, 256, DSMG>>>(ROWS, DM, DM, kv, oh, ol, nullptr, h);
    }

    // ---- vocab projection ----
    gemm_mma<<<g_voc, 256, DSMG>>>(ROWS, VOC, DM, h, wbh + OFF_WOUT, wbl + OFF_WOUT, bout, out);
}

// round 12
// speedup vs baseline: 1.1349x; 1.1349x over previous
#include <cuda_runtime.h>
#include <cuda_bf16.h>
#include <math.h>
#include <stdint.h>

#define BSZ  2
#define SEQ  1024
#define DM   1024
#define NH   16
#define HDIM 64
#define NL   4
#define VOC  32000
#define NFR  50
#define DLAT 512
#define ROWS (BSZ*SEQ)   // 2048
#define KT   16

// ---------------- scratch (device globals; no allocation allowed) ----------
__device__ float g_h [ROWS*DM];
__device__ float g_q [ROWS*DM];
__device__ float g_k [ROWS*DM];
__device__ float g_v [ROWS*DM];
__device__ float g_kv[ROWS*DM];
__device__ float g_kr[ROWS*DM];
__device__ float g_vr[ROWS*DM];
__device__ float g_lat[ROWS*DLAT];
__device__ float g_four[ROWS*NFR];

// transposed + split weights: [N][K] bf16, hi and lo halves
#define WSZ_DD   (1024*1024)
#define WSZ_HALF (512*1024)
#define LSTRIDE  (4*WSZ_DD + 3*WSZ_HALF)
#define OFF_RULE 0
#define OFF_L(l) ((size_t)WSZ_DD + (size_t)(l)*LSTRIDE)
#define OFF_WOUT ((size_t)WSZ_DD + 4*(size_t)LSTRIDE)
#define WTOT     (OFF_WOUT + (size_t)VOC*DM)
__device__ __align__(16) __nv_bfloat16 g_wbh[WTOT];
__device__ __align__(16) __nv_bfloat16 g_wbl[WTOT];

// ---------------- f32x2 packed helpers (Blackwell FFMA2) -------------------
__device__ __forceinline__ unsigned long long pk2(float lo, float hi) {
    unsigned long long r;
    asm("mov.b64 %0, {%1, %2};" : "=l"(r) : "f"(lo), "f"(hi));
    return r;
}
__device__ __forceinline__ unsigned long long ffma2(
    unsigned long long a, unsigned long long b, unsigned long long c) {
    unsigned long long d;
    asm("fma.rn.f32x2 %0, %1, %2, %3;" : "=l"(d) : "l"(a), "l"(b), "l"(c));
    return d;
}
__device__ __forceinline__ float2 up2(unsigned long long v) {
    float2 f;
    asm("mov.b64 {%0, %1}, %2;" : "=f"(f.x), "=f"(f.y) : "l"(v));
    return f;
}

// ---------------- misc helpers ---------------------------------------------
__device__ __forceinline__ uint32_t smem_to_u32(const void* p) {
    uint32_t a;
    asm("{ .reg .u64 t; cvta.to.shared.u64 t, %1; cvt.u32.u64 %0, t; }" : "=r"(a) : "l"(p));
    return a;
}
__device__ __forceinline__ uint32_t bfpack(float lo, float hi) {
    uint32_t r;
    asm("cvt.rn.bf16x2.f32 %0, %1, %2;" : "=r"(r) : "f"(hi), "f"(lo));
    return r;
}
__device__ __forceinline__ float bflo(uint32_t p) { return __uint_as_float(p << 16); }
__device__ __forceinline__ float bfhi(uint32_t p) { return __uint_as_float(p & 0xffff0000u); }
#define STS128(addr, a, b, c, d) \
    asm volatile("st.shared.v4.b32 [%0], {%1, %2, %3, %4};" \
        :: "r"(addr), "r"(a), "r"(b), "r"(c), "r"(d) : "memory")
#define STS32(addr, v) \
    asm volatile("st.shared.b32 [%0], %1;" :: "r"(addr), "r"(v) : "memory")
#define LDSM_X4(r0, r1, r2, r3, addr) \
    asm volatile("ldmatrix.sync.aligned.m8n8.x4.shared.b16 {%0,%1,%2,%3}, [%4];" \
        : "=r"(r0), "=r"(r1), "=r"(r2), "=r"(r3) : "r"(addr))
#define LDSM_X2(r0, r1, addr) \
    asm volatile("ldmatrix.sync.aligned.m8n8.x2.shared.b16 {%0,%1}, [%2];" \
        : "=r"(r0), "=r"(r1) : "r"(addr))
#define LDSM_X2T(r0, r1, addr) \
    asm volatile("ldmatrix.sync.aligned.m8n8.x2.trans.shared.b16 {%0,%1}, [%2];" \
        : "=r"(r0), "=r"(r1) : "r"(addr))
#define MMA16816(d, a0, a1, a2, a3, b0, b1) \
    asm volatile("mma.sync.aligned.m16n8k16.row.col.f32.bf16.bf16.f32 " \
        "{%0,%1,%2,%3}, {%4,%5,%6,%7}, {%8,%9}, {%0,%1,%2,%3};" \
        : "+f"((d)[0]), "+f"((d)[1]), "+f"((d)[2]), "+f"((d)[3]) \
        : "r"(a0), "r"(a1), "r"(a2), "r"(a3), "r"(b0), "r"(b1))

// ===== weight transpose + bf16 split, vectorized stores ====================
__global__ __launch_bounds__(256) void wsplit_k(
    const float* __restrict__ W, int K, int N,
    __nv_bfloat16* __restrict__ Th, __nv_bfloat16* __restrict__ Tl)
{
    __shared__ float t[32][33];
    const int k0 = blockIdx.y * 32, n0 = blockIdx.x * 32;
    const int tx = threadIdx.x, ty = threadIdx.y;   // (32,8)
    const int tid = ty * 32 + tx;
#pragma unroll
    for (int i = 0; i < 4; i++)
        t[ty + 8 * i][tx] = W[(size_t)(k0 + ty + 8 * i) * N + n0 + tx];
    __syncthreads();
    const int half = tid >> 7;
    const int r = tid & 127;
    const int nl = r >> 2;
    const int kg = r & 3;
    uint32_t h[4], l[4];
#pragma unroll
    for (int i = 0; i < 4; i++) {
        float x0 = t[kg * 8 + 2 * i][nl];
        float x1 = t[kg * 8 + 2 * i + 1][nl];
        uint32_t hp = bfpack(x0, x1);
        uint32_t lp = bfpack(x0 - bflo(hp), x1 - bfhi(hp));
        h[i] = hp; l[i] = lp;
    }
    size_t o = (size_t)(n0 + nl) * K + k0 + kg * 8;
    if (half == 0) *(uint4*)(Th + o) = make_uint4(h[0], h[1], h[2], h[3]);
    else           *(uint4*)(Tl + o) = make_uint4(l[0], l[1], l[2], l[3]);
}

// ================= HMMA bf16-split GEMM (R8 proven version) ================
#define ASTR   40                       // 32-elem rows + pad (GEMM tiles only)
#define TILEB  (128*80)
#define OAH    0
#define OAL    (TILEB)
#define OBH    (2*TILEB)
#define OBL    (3*TILEB)
#define BUFSTR (4*TILEB)
#define DSMG   (2*BUFSTR)               // 81920

__global__ __launch_bounds__(256) void gemm_mma(
    int M, int N, int K,
    const float* __restrict__ A,
    const __nv_bfloat16* __restrict__ Bh, const __nv_bfloat16* __restrict__ Bl,
    const float* __restrict__ bias, float* __restrict__ C)
{
    extern __shared__ char smem[];
    const uint32_t sb = smem_to_u32(smem);
    const int tid = threadIdx.x, lane = tid & 31, wid = tid >> 5;
    const int brow = blockIdx.y * 128, bcol = blockIdx.x * 128;
    const int wm = wid & 1, wn = wid >> 1;

    const int lrow = tid >> 1, lhalf = tid & 1;
    const float* Ap          = A  + (size_t)(brow + lrow) * K + lhalf * 16;
    const __nv_bfloat16* Bhp = Bh + (size_t)(bcol + lrow) * K + lhalf * 16;
    const __nv_bfloat16* Blp = Bl + (size_t)(bcol + lrow) * K + lhalf * 16;
    const uint32_t soff = (uint32_t)(lrow * ASTR + lhalf * 16) * 2;

    float acc[4][4][4];
#pragma unroll
    for (int i = 0; i < 4; i++)
#pragma unroll
        for (int j = 0; j < 4; j++)
#pragma unroll
            for (int e = 0; e < 4; e++) acc[i][j][e] = 0.f;

    float4 pa[4]; uint4 pbh[2], pbl[2];

#define LOADG(k0) do { \
    pa[0] = *(const float4*)(Ap + (k0));      pa[1] = *(const float4*)(Ap + (k0) + 4); \
    pa[2] = *(const float4*)(Ap + (k0) + 8);  pa[3] = *(const float4*)(Ap + (k0) + 12); \
    pbh[0] = *(const uint4*)(Bhp + (k0));     pbh[1] = *(const uint4*)(Bhp + (k0) + 8); \
    pbl[0] = *(const uint4*)(Blp + (k0));     pbl[1] = *(const uint4*)(Blp + (k0) + 8); \
} while (0)

#define STOREBUF(b) do { \
    uint32_t hh[8], ll[8]; \
    _Pragma("unroll") \
    for (int i = 0; i < 4; i++) { \
        float4 x = pa[i]; \
        uint32_t h0 = bfpack(x.x, x.y), h1 = bfpack(x.z, x.w); \
        uint32_t l0 = bfpack(x.x - bflo(h0), x.y - bfhi(h0)); \
        uint32_t l1 = bfpack(x.z - bflo(h1), x.w - bfhi(h1)); \
        hh[2*i] = h0; hh[2*i+1] = h1; ll[2*i] = l0; ll[2*i+1] = l1; \
    } \
    uint32_t base_ = sb + (uint32_t)(b) * BUFSTR; \
    STS128(base_ + OAH + soff,      hh[0], hh[1], hh[2], hh[3]); \
    STS128(base_ + OAH + soff + 16, hh[4], hh[5], hh[6], hh[7]); \
    STS128(base_ + OAL + soff,      ll[0], ll[1], ll[2], ll[3]); \
    STS128(base_ + OAL + soff + 16, ll[4], ll[5], ll[6], ll[7]); \
    STS128(base_ + OBH + soff,      pbh[0].x, pbh[0].y, pbh[0].z, pbh[0].w); \
    STS128(base_ + OBH + soff + 16, pbh[1].x, pbh[1].y, pbh[1].z, pbh[1].w); \
    STS128(base_ + OBL + soff,      pbl[0].x, pbl[0].y, pbl[0].z, pbl[0].w); \
    STS128(base_ + OBL + soff + 16, pbl[1].x, pbl[1].y, pbl[1].z, pbl[1].w); \
} while (0)

    const int nchunk = K / 32;
    LOADG(0);
    STOREBUF(0);
    __syncthreads();

    const uint32_t arow = (uint32_t)(wm * 64 + (lane & 15));
    const uint32_t acol = (uint32_t)((lane >> 4) * 8);
    const uint32_t brw  = (uint32_t)(wn * 32 + (lane & 7));
    const uint32_t bcl  = (uint32_t)(((lane >> 3) & 1) * 8);

    int buf = 0;
    for (int ck = 0; ck < nchunk; ck++) {
        if (ck + 1 < nchunk) LOADG((ck + 1) * 32);

        const uint32_t base = sb + (uint32_t)buf * BUFSTR;
#pragma unroll
        for (int ks = 0; ks < 2; ks++) {
            uint32_t ah[4][4], al[4][4];
#pragma unroll
            for (int mt = 0; mt < 4; mt++) {
                uint32_t aoff = ((arow + mt * 16) * ASTR + acol + ks * 16) * 2;
                LDSM_X4(ah[mt][0], ah[mt][1], ah[mt][2], ah[mt][3], base + OAH + aoff);
                LDSM_X4(al[mt][0], al[mt][1], al[mt][2], al[mt][3], base + OAL + aoff);
            }
#pragma unroll
            for (int nt = 0; nt < 4; nt++) {
                uint32_t boff = ((brw + nt * 8) * ASTR + bcl + ks * 16) * 2;
                uint32_t bh0, bh1, bl0, bl1;
                LDSM_X2(bh0, bh1, base + OBH + boff);
                LDSM_X2(bl0, bl1, base + OBL + boff);
#pragma unroll
                for (int mt = 0; mt < 4; mt++) {
                    MMA16816(acc[mt][nt], ah[mt][0], ah[mt][1], ah[mt][2], ah[mt][3], bh0, bh1);
                    MMA16816(acc[mt][nt], ah[mt][0], ah[mt][1], ah[mt][2], ah[mt][3], bl0, bl1);
                    MMA16816(acc[mt][nt], al[mt][0], al[mt][1], al[mt][2], al[mt][3], bh0, bh1);
                }
            }
        }
        if (ck + 1 < nchunk) STOREBUF(buf ^ 1);
        __syncthreads();
        buf ^= 1;
    }

#pragma unroll
    for (int mt = 0; mt < 4; mt++) {
        int r0 = brow + wm * 64 + mt * 16 + (lane >> 2);
#pragma unroll
        for (int nt = 0; nt < 4; nt++) {
            int c = bcol + wn * 32 + nt * 8 + (lane & 3) * 2;
            float bx = 0.f, by = 0.f;
            if (bias) { bx = bias[c]; by = bias[c + 1]; }
            float2 o0, o1;
            o0.x = acc[mt][nt][0] + bx; o0.y = acc[mt][nt][1] + by;
            o1.x = acc[mt][nt][2] + bx; o1.y = acc[mt][nt][3] + by;
            *(float2*)(C + (size_t)r0 * N + c)       = o0;
            *(float2*)(C + (size_t)(r0 + 8) * N + c) = o1;
        }
    }
#undef LOADG
#undef STOREBUF
}

// ================= fused flash attention (split HMMA) ======================
// Q/K/V tiles now use QSTR=72 (144 B) row stride: 64-elem rows fit WITHOUT
// the ASTR=40 aliasing race that corrupted R10 (and silently degraded R8).
#define QSTR   72
#define VSTR   72
#define PSTR   136
#define QKTILE (128*144)                 // 18432
#define FA_OQH 0
#define FA_OQL (QKTILE)                  // 18432
#define FA_OKH (2*QKTILE)                // 36864
#define FA_OKL (3*QKTILE)                // 55296
#define FA_OVH (4*QKTILE)                // 73728
#define FA_OVL (5*QKTILE)                // 92160
#define FA_OPH (6*QKTILE)                // 110592
#define FA_OPL (FA_OPH + 128*272)        // 145408
#define FA_M   (FA_OPL + 128*272)        // 180224
#define FA_L   (FA_M + 512)              // 180736
#define FA_R   (FA_L + 512)              // 181248
#define FA_PMX (FA_R + 512)              // 181760
#define FA_PSM (FA_PMX + 2048)           // 183808
#define FA_TAB (FA_PSM + 2048)           // 185856
#define DSMF   (FA_TAB + 1024)           // 186880

__global__ __launch_bounds__(256) void flash_k(
    const float* __restrict__ Q, const float* __restrict__ Kc,
    const float* __restrict__ V, float* __restrict__ O)
{
    extern __shared__ char smem[];
    const uint32_t sb = smem_to_u32(smem);
    float* mrow = (float*)(smem + FA_M);
    float* lrow = (float*)(smem + FA_L);
    float* rrow = (float*)(smem + FA_R);
    float* pmax = (float*)(smem + FA_PMX);
    float* psum = (float*)(smem + FA_PSM);
    float* tab  = (float*)(smem + FA_TAB);
    const int tid = threadIdx.x, lane = tid & 31, wid = tid >> 5;
    const int bh = blockIdx.y, b = bh >> 4, h = bh & 15;
    const int i0 = blockIdx.x * 128;
    const int wm = wid & 1, wn = wid >> 1;       // S-phase 2x4
    const int wmv = wid & 3, wnv = wid >> 2;     // AV-phase 4x2

    const int lr2 = tid >> 1, ls2 = tid & 1;

    // ---- load Q tile once (split hi/lo, A-operand layout, stride QSTR) ----
    {
        const float* qp = Q + (size_t)(b * SEQ + i0 + lr2) * DM + h * HDIM + ls2 * 32;
        const uint32_t off = (uint32_t)(lr2 * QSTR + ls2 * 32) * 2;
        uint32_t hh[16], ll[16];
#pragma unroll
        for (int i = 0; i < 8; i++) {
            float4 x = *(const float4*)(qp + i * 4);
            uint32_t h0 = bfpack(x.x, x.y), h1 = bfpack(x.z, x.w);
            hh[2*i] = h0; hh[2*i+1] = h1;
            ll[2*i]   = bfpack(x.x - bflo(h0), x.y - bfhi(h0));
            ll[2*i+1] = bfpack(x.z - bflo(h1), x.w - bfhi(h1));
        }
#pragma unroll
        for (int i = 0; i < 4; i++) {
            STS128(sb + FA_OQH + off + i * 16, hh[4*i], hh[4*i+1], hh[4*i+2], hh[4*i+3]);
            STS128(sb + FA_OQL + off + i * 16, ll[4*i], ll[4*i+1], ll[4*i+2], ll[4*i+3]);
        }
    }
    if (tid < 128) { mrow[tid] = -1e30f; lrow[tid] = 0.f; }

    float oacc[2][4][4];
#pragma unroll
    for (int i = 0; i < 2; i++)
#pragma unroll
        for (int j = 0; j < 4; j++)
#pragma unroll
            for (int e = 0; e < 4; e++) oacc[i][j][e] = 0.f;

    const float scale = 0.03125f;
    const uint32_t arow = (uint32_t)(wm * 64 + (lane & 15));
    const uint32_t acol = (uint32_t)((lane >> 4) * 8);
    const uint32_t brw  = (uint32_t)(wn * 32 + (lane & 7));
    const uint32_t bcl  = (uint32_t)(((lane >> 3) & 1) * 8);
    const uint32_t arv  = (uint32_t)(wmv * 32 + (lane & 15));
    const uint32_t klv  = (uint32_t)(lane & 15);
    const int lr4 = lane >> 2, lc4 = (lane & 3) * 2;

    for (int jt = 0; jt < 8; jt++) {
        const int j0 = jt * 128;
        __syncthreads();     // prior AV reads done; safe to overwrite K/V/tab
        tab[tid] = __expf(-0.01f * fabsf((float)(i0 - j0 + tid - 128)));

        // ---- load K (n-major) and V (k-major) tiles, split hi/lo ----
        {
            const float* kp = Kc + (size_t)(b * SEQ + j0 + lr2) * DM + h * HDIM + ls2 * 32;
            const float* vp = V  + (size_t)(b * SEQ + j0 + lr2) * DM + h * HDIM + ls2 * 32;
            const uint32_t offk = (uint32_t)(lr2 * QSTR + ls2 * 32) * 2;
            const uint32_t offv = (uint32_t)(lr2 * VSTR + ls2 * 32) * 2;
            uint32_t hh[16], ll[16];
#pragma unroll
            for (int i = 0; i < 8; i++) {
                float4 x = *(const float4*)(kp + i * 4);
                uint32_t h0 = bfpack(x.x, x.y), h1 = bfpack(x.z, x.w);
                hh[2*i] = h0; hh[2*i+1] = h1;
                ll[2*i]   = bfpack(x.x - bflo(h0), x.y - bfhi(h0));
                ll[2*i+1] = bfpack(x.z - bflo(h1), x.w - bfhi(h1));
            }
#pragma unroll
            for (int i = 0; i < 4; i++) {
                STS128(sb + FA_OKH + offk + i * 16, hh[4*i], hh[4*i+1], hh[4*i+2], hh[4*i+3]);
                STS128(sb + FA_OKL + offk + i * 16, ll[4*i], ll[4*i+1], ll[4*i+2], ll[4*i+3]);
            }
#pragma unroll
            for (int i = 0; i < 8; i++) {
                float4 x = *(const float4*)(vp + i * 4);
                uint32_t h0 = bfpack(x.x, x.y), h1 = bfpack(x.z, x.w);
                hh[2*i] = h0; hh[2*i+1] = h1;
                ll[2*i]   = bfpack(x.x - bflo(h0), x.y - bfhi(h0));
                ll[2*i+1] = bfpack(x.z - bflo(h1), x.w - bfhi(h1));
            }
#pragma unroll
            for (int i = 0; i < 4; i++) {
                STS128(sb + FA_OVH + offv + i * 16, hh[4*i], hh[4*i+1], hh[4*i+2], hh[4*i+3]);
                STS128(sb + FA_OVL + offv + i * 16, ll[4*i], ll[4*i+1], ll[4*i+2], ll[4*i+3]);
            }
        }
        __syncthreads();

        // ---- S = Q K^T (split) ----
        float sacc[4][4][4];
#pragma unroll
        for (int i = 0; i < 4; i++)
#pragma unroll
            for (int j = 0; j < 4; j++)
#pragma unroll
                for (int e = 0; e < 4; e++) sacc[i][j][e] = 0.f;
#pragma unroll
        for (int ks = 0; ks < 4; ks++) {
            uint32_t ah[4][4], al[4][4];
#pragma unroll
            for (int mt = 0; mt < 4; mt++) {
                uint32_t aoff = ((arow + mt * 16) * QSTR + acol + ks * 16) * 2;
                LDSM_X4(ah[mt][0], ah[mt][1], ah[mt][2], ah[mt][3], sb + FA_OQH + aoff);
                LDSM_X4(al[mt][0], al[mt][1], al[mt][2], al[mt][3], sb + FA_OQL + aoff);
            }
#pragma unroll
            for (int nt = 0; nt < 4; nt++) {
                uint32_t boff = ((brw + nt * 8) * QSTR + bcl + ks * 16) * 2;
                uint32_t bh0, bh1, bl0, bl1;
                LDSM_X2(bh0, bh1, sb + FA_OKH + boff);
                LDSM_X2(bl0, bl1, sb + FA_OKL + boff);
#pragma unroll
                for (int mt = 0; mt < 4; mt++) {
                    MMA16816(sacc[mt][nt], ah[mt][0], ah[mt][1], ah[mt][2], ah[mt][3], bh0, bh1);
                    MMA16816(sacc[mt][nt], ah[mt][0], ah[mt][1], ah[mt][2], ah[mt][3], bl0, bl1);
                    MMA16816(sacc[mt][nt], al[mt][0], al[mt][1], al[mt][2], al[mt][3], bh0, bh1);
                }
            }
        }

        // ---- scale + decay, per-warp row max ----
#pragma unroll
        for (int mt = 0; mt < 4; mt++) {
            int ri = wm * 64 + mt * 16 + lr4;
            float mx0 = -1e30f, mx1 = -1e30f;
#pragma unroll
            for (int nt = 0; nt < 4; nt++) {
                int cj = wn * 32 + nt * 8 + lc4;
                int d0 = ri - cj + 128;
                sacc[mt][nt][0] *= scale * tab[d0];
                sacc[mt][nt][1] *= scale * tab[d0 - 1];
                sacc[mt][nt][2] *= scale * tab[d0 + 8];
                sacc[mt][nt][3] *= scale * tab[d0 + 7];
                mx0 = fmaxf(mx0, fmaxf(sacc[mt][nt][0], sacc[mt][nt][1]));
                mx1 = fmaxf(mx1, fmaxf(sacc[mt][nt][2], sacc[mt][nt][3]));
            }
            mx0 = fmaxf(mx0, __shfl_xor_sync(0xffffffffu, mx0, 1));
            mx0 = fmaxf(mx0, __shfl_xor_sync(0xffffffffu, mx0, 2));
            mx1 = fmaxf(mx1, __shfl_xor_sync(0xffffffffu, mx1, 1));
            mx1 = fmaxf(mx1, __shfl_xor_sync(0xffffffffu, mx1, 2));
            if ((lane & 3) == 0) {
                pmax[wn * 128 + ri] = mx0;
                pmax[wn * 128 + ri + 8] = mx1;
            }
        }
        __syncthreads();
        if (tid < 128) {
            float mo = mrow[tid];
            float mn = fmaxf(fmaxf(pmax[tid], pmax[128 + tid]),
                             fmaxf(pmax[256 + tid], pmax[384 + tid]));
            mn = fmaxf(mo, mn);
            rrow[tid] = __expf(mo - mn);
            mrow[tid] = mn;
        }
        __syncthreads();

        // ---- exp, split-store P, partial sums ----
#pragma unroll
        for (int mt = 0; mt < 4; mt++) {
            int row0 = wm * 64 + mt * 16 + lr4;
            int row1 = row0 + 8;
            float m0 = mrow[row0], m1 = mrow[row1];
            float s0 = 0.f, s1 = 0.f;
#pragma unroll
            for (int nt = 0; nt < 4; nt++) {
                int col = wn * 32 + nt * 8 + lc4;
                float p0 = __expf(sacc[mt][nt][0] - m0);
                float p1 = __expf(sacc[mt][nt][1] - m0);
                float p2 = __expf(sacc[mt][nt][2] - m1);
                float p3 = __expf(sacc[mt][nt][3] - m1);
                s0 += p0 + p1; s1 += p2 + p3;
                uint32_t ph0 = bfpack(p0, p1);
                uint32_t pl0 = bfpack(p0 - bflo(ph0), p1 - bfhi(ph0));
                uint32_t ph1 = bfpack(p2, p3);
                uint32_t pl1 = bfpack(p2 - bflo(ph1), p3 - bfhi(ph1));
                uint32_t a0 = (uint32_t)(row0 * PSTR + col) * 2;
                uint32_t a1 = (uint32_t)(row1 * PSTR + col) * 2;
                STS32(sb + FA_OPH + a0, ph0);
                STS32(sb + FA_OPL + a0, pl0);
                STS32(sb + FA_OPH + a1, ph1);
                STS32(sb + FA_OPL + a1, pl1);
            }
            s0 += __shfl_xor_sync(0xffffffffu, s0, 1);
            s0 += __shfl_xor_sync(0xffffffffu, s0, 2);
            s1 += __shfl_xor_sync(0xffffffffu, s1, 1);
            s1 += __shfl_xor_sync(0xffffffffu, s1, 2);
            if ((lane & 3) == 0) {
                psum[wn * 128 + row0] = s0;
                psum[wn * 128 + row1] = s1;
            }
        }
        __syncthreads();
        if (tid < 128)
            lrow[tid] = lrow[tid] * rrow[tid]
                      + psum[tid] + psum[128 + tid] + psum[256 + tid] + psum[384 + tid];

        // ---- rescale O, then O += P @ V ----
#pragma unroll
        for (int mt = 0; mt < 2; mt++) {
            int r0 = wmv * 32 + mt * 16 + lr4;
            float f0 = rrow[r0], f1 = rrow[r0 + 8];
#pragma unroll
            for (int nt = 0; nt < 4; nt++) {
                oacc[mt][nt][0] *= f0; oacc[mt][nt][1] *= f0;
                oacc[mt][nt][2] *= f1; oacc[mt][nt][3] *= f1;
            }
        }
#pragma unroll
        for (int ks = 0; ks < 8; ks++) {
            uint32_t ah[2][4], al[2][4];
#pragma unroll
            for (int mt = 0; mt < 2; mt++) {
                uint32_t aoff = ((arv + mt * 16) * PSTR + (uint32_t)((lane >> 4) * 8) + ks * 16) * 2;
                LDSM_X4(ah[mt][0], ah[mt][1], ah[mt][2], ah[mt][3], sb + FA_OPH + aoff);
                LDSM_X4(al[mt][0], al[mt][1], al[mt][2], al[mt][3], sb + FA_OPL + aoff);
            }
#pragma unroll
            for (int nt = 0; nt < 4; nt++) {
                uint32_t boff = ((ks * 16 + klv) * VSTR + wnv * 32 + nt * 8) * 2;
                uint32_t bh0, bh1, bl0, bl1;
                LDSM_X2T(bh0, bh1, sb + FA_OVH + boff);
                LDSM_X2T(bl0, bl1, sb + FA_OVL + boff);
#pragma unroll
                for (int mt = 0; mt < 2; mt++) {
                    MMA16816(oacc[mt][nt], ah[mt][0], ah[mt][1], ah[mt][2], ah[mt][3], bh0, bh1);
                    MMA16816(oacc[mt][nt], ah[mt][0], ah[mt][1], ah[mt][2], ah[mt][3], bl0, bl1);
                    MMA16816(oacc[mt][nt], al[mt][0], al[mt][1], al[mt][2], al[mt][3], bh0, bh1);
                }
            }
        }
    }

    __syncthreads();
    // ---- normalize + write O ----
#pragma unroll
    for (int mt = 0; mt < 2; mt++) {
        int r0 = wmv * 32 + mt * 16 + lr4;
        float inv0 = 1.0f / lrow[r0];
        float inv1 = 1.0f / lrow[r0 + 8];
#pragma unroll
        for (int nt = 0; nt < 4; nt++) {
            int c = h * HDIM + wnv * 32 + nt * 8 + lc4;
            float2 o0, o1;
            o0.x = oacc[mt][nt][0] * inv0; o0.y = oacc[mt][nt][1] * inv0;
            o1.x = oacc[mt][nt][2] * inv1; o1.y = oacc[mt][nt][3] * inv1;
            *(float2*)(O + (size_t)(b * SEQ + i0 + r0) * DM + c)     = o0;
            *(float2*)(O + (size_t)(b * SEQ + i0 + r0 + 8) * DM + c) = o1;
        }
    }
}

// ---------------- FFMA2 SGEMM (kept for the K=50 embedding GEMM) -----------
__global__ __launch_bounds__(256) void sgemm2_k(
    int M, int N, int K,
    const float* __restrict__ A, const float* __restrict__ B,
    const float* __restrict__ bias, float* __restrict__ C)
{
    __shared__ __align__(16) float As[KT][128];
    __shared__ __align__(16) float Bs[KT][128];
    const int tid  = threadIdx.x;
    const int brow = blockIdx.y * 128;
    const int bcol = blockIdx.x * 128;
    const int ty = tid >> 4, tx = tid & 15;
    const int ar = tid >> 1, aks = (tid & 1) * 8;

    unsigned long long acc[8][4];
#pragma unroll
    for (int i = 0; i < 8; i++)
#pragma unroll
        for (int j = 0; j < 4; j++) acc[i][j] = 0ULL;

    for (int k0 = 0; k0 < K; k0 += KT) {
#pragma unroll
        for (int i = 0; i < 8; i++) {
            int kk = aks + i;
            As[kk][ar] = (k0 + kk < K) ? A[(size_t)(brow + ar) * K + k0 + kk] : 0.f;
        }
#pragma unroll
        for (int p = 0; p < 2; p++) {
            int id = p * 256 + tid;
            int kk = id >> 5, c4 = (id & 31) * 4;
            float4 bv = make_float4(0.f, 0.f, 0.f, 0.f);
            if (k0 + kk < K) bv = *(const float4*)(B + (size_t)(k0 + kk) * N + bcol + c4);
            *(float4*)&Bs[kk][c4] = bv;
        }
        __syncthreads();
#pragma unroll
        for (int kk = 0; kk < KT; kk++) {
            float4 a0 = *(const float4*)&As[kk][ty * 4];
            float4 a1 = *(const float4*)&As[kk][64 + ty * 4];
            float4 b0 = *(const float4*)&Bs[kk][tx * 4];
            float4 b1 = *(const float4*)&Bs[kk][64 + tx * 4];
            unsigned long long rb[4] = { pk2(b0.x, b0.y), pk2(b0.z, b0.w),
                                         pk2(b1.x, b1.y), pk2(b1.z, b1.w) };
            float ra[8] = { a0.x, a0.y, a0.z, a0.w, a1.x, a1.y, a1.z, a1.w };
#pragma unroll
            for (int i = 0; i < 8; i++) {
                unsigned long long ad = pk2(ra[i], ra[i]);
#pragma unroll
                for (int j = 0; j < 4; j++) acc[i][j] = ffma2(ad, rb[j], acc[i][j]);
            }
        }
        __syncthreads();
    }
#pragma unroll
    for (int ih = 0; ih < 2; ih++)
#pragma unroll
    for (int ii = 0; ii < 4; ii++) {
        int i = ih * 4 + ii;
        int r = brow + ih * 64 + ty * 4 + ii;
#pragma unroll
        for (int jh = 0; jh < 2; jh++) {
            int c = bcol + jh * 64 + tx * 4;
            float2 p0 = up2(acc[i][jh * 2]);
            float2 p1 = up2(acc[i][jh * 2 + 1]);
            float4 o; o.x = p0.x; o.y = p0.y; o.z = p1.x; o.w = p1.y;
            if (bias) { o.x += bias[c]; o.y += bias[c+1]; o.z += bias[c+2]; o.w += bias[c+3]; }
            *(float4*)(C + (size_t)r * N + c) = o;
        }
    }
}

// ---------------- Fourier token features -----------------------------------
__global__ void fourier_k(const int* __restrict__ src, const float* __restrict__ a_n,
                          const float* __restrict__ b_n, float* __restrict__ F)
{
    int idx = blockIdx.x * blockDim.x + threadIdx.x;
    if (idx >= ROWS * NFR) return;
    int bs = idx / NFR, n = idx % NFR;
    int tok = src[bs];
    float x   = (float)tok * (1.0f / (float)VOC);
    float ang = 6.28318530717958647692f * (float)(n + 1) * x;
    F[idx] = a_n[tok * NFR + n] * cosf(ang) + b_n[tok * NFR + n] * sinf(ang);
}

// ---------------- h += sinusoidal PE ---------------------------------------
__global__ void addpe_k(float* __restrict__ h)
{
    int idx = blockIdx.x * blockDim.x + threadIdx.x;
    if (idx >= ROWS * DM) return;
    int d = idx & (DM - 1);
    int s = (idx / DM) & (SEQ - 1);
    float div = expf(-(float)(d & ~1) * 8.99447301948846e-3f);
    float ang = (float)s * div;
    h[idx] += (d & 1) ? cosf(ang) : sinf(ang);
}

__global__ void add_k(const float* __restrict__ a, const float* __restrict__ b,
                      float* __restrict__ c, int n)
{
    int i = blockIdx.x * blockDim.x + threadIdx.x;
    if (i < n) c[i] = a[i] + b[i];
}

// ---------------------------------------------------------------------------
extern "C" void kernel_launch(void* const* d_in, const int* in_sizes, int n_in,
                              void* d_out, int out_size)
{
    const int*   src    = (const int*)  d_in[0];
    const float* a_n    = (const float*)d_in[2];
    const float* b_n    = (const float*)d_in[3];
    const float* proj_w = (const float*)d_in[4];
    const float* proj_b = (const float*)d_in[5];
    const float* rule   = (const float*)d_in[6];
    const float* Wq     = (const float*)d_in[7];
    const float* Wk     = (const float*)d_in[8];
    const float* Wv     = (const float*)d_in[9];
    const float* Wo     = (const float*)d_in[10];
    const float* Wdown  = (const float*)d_in[11];
    const float* Wup_k  = (const float*)d_in[12];
    const float* Wup_v  = (const float*)d_in[13];
    const float* Wout   = (const float*)d_in[14];
    const float* bout   = (const float*)d_in[15];
    float* out = (float*)d_out;

    float *h, *q, *k, *v, *kv, *kr, *vr, *lat, *four;
    __nv_bfloat16 *wbh, *wbl;
    cudaGetSymbolAddress((void**)&h,    g_h);
    cudaGetSymbolAddress((void**)&q,    g_q);
    cudaGetSymbolAddress((void**)&k,    g_k);
    cudaGetSymbolAddress((void**)&v,    g_v);
    cudaGetSymbolAddress((void**)&kv,   g_kv);
    cudaGetSymbolAddress((void**)&kr,   g_kr);
    cudaGetSymbolAddress((void**)&vr,   g_vr);
    cudaGetSymbolAddress((void**)&lat,  g_lat);
    cudaGetSymbolAddress((void**)&four, g_four);
    cudaGetSymbolAddress((void**)&wbh,  g_wbh);
    cudaGetSymbolAddress((void**)&wbl,  g_wbl);

    cudaFuncSetAttribute(gemm_mma, cudaFuncAttributeMaxDynamicSharedMemorySize, DSMG);
    cudaFuncSetAttribute(flash_k,  cudaFuncAttributeMaxDynamicSharedMemorySize, DSMF);

    // ---- transpose + split all weights into [N,K] bf16 hi/lo ----
    {
        const dim3 b(32, 8);
        wsplit_k<<<dim3(DM/32, DM/32), b>>>(rule, DM, DM, wbh + OFF_RULE, wbl + OFF_RULE);
        for (int l = 0; l < NL; l++) {
            size_t o = OFF_L(l);
            wsplit_k<<<dim3(DM/32, DM/32), b>>>(Wq + (size_t)l*DM*DM, DM, DM, wbh+o, wbl+o);
            wsplit_k<<<dim3(DM/32, DM/32), b>>>(Wk + (size_t)l*DM*DM, DM, DM, wbh+o+WSZ_DD, wbl+o+WSZ_DD);
            wsplit_k<<<dim3(DM/32, DM/32), b>>>(Wv + (size_t)l*DM*DM, DM, DM, wbh+o+2*WSZ_DD, wbl+o+2*WSZ_DD);
            wsplit_k<<<dim3(DM/32, DM/32), b>>>(Wo + (size_t)l*DM*DM, DM, DM, wbh+o+3*WSZ_DD, wbl+o+3*WSZ_DD);
            wsplit_k<<<dim3(DLAT/32, DM/32), b>>>(Wdown + (size_t)l*DM*DLAT, DM, DLAT,
                                                  wbh+o+4*WSZ_DD, wbl+o+4*WSZ_DD);
            wsplit_k<<<dim3(DM/32, DLAT/32), b>>>(Wup_k + (size_t)l*DLAT*DM, DLAT, DM,
                                                  wbh+o+4*WSZ_DD+WSZ_HALF, wbl+o+4*WSZ_DD+WSZ_HALF);
            wsplit_k<<<dim3(DM/32, DLAT/32), b>>>(Wup_v + (size_t)l*DLAT*DM, DLAT, DM,
                                                  wbh+o+4*WSZ_DD+2*WSZ_HALF, wbl+o+4*WSZ_DD+2*WSZ_HALF);
        }
        wsplit_k<<<dim3(VOC/32, DM/32), b>>>(Wout, DM, VOC, wbh + OFF_WOUT, wbl + OFF_WOUT);
    }

    const dim3 g_d  (DM   / 128, ROWS / 128);
    const dim3 g_dl (DLAT / 128, ROWS / 128);
    const dim3 g_voc(VOC  / 128, ROWS / 128);

    // ---- embedding ----
    fourier_k<<<(ROWS * NFR + 255) / 256, 256>>>(src, a_n, b_n, four);
    sgemm2_k<<<g_d, 256>>>(ROWS, DM, NFR, four, proj_w, proj_b, q);
    gemm_mma<<<g_d, 256, DSMG>>>(ROWS, DM, DM, q, wbh + OFF_RULE, wbl + OFF_RULE, nullptr, h);
    addpe_k<<<(ROWS * DM + 255) / 256, 256>>>(h);

    // ---- layers ----
    for (int l = 0; l < NL; l++) {
        size_t o = OFF_L(l);
        const __nv_bfloat16 *qh = wbh+o,             *ql = wbl+o;
        const __nv_bfloat16 *kh = wbh+o+WSZ_DD,      *kl = wbl+o+WSZ_DD;
        const __nv_bfloat16 *vh = wbh+o+2*WSZ_DD,    *vl = wbl+o+2*WSZ_DD;
        const __nv_bfloat16 *oh = wbh+o+3*WSZ_DD,    *ol = wbl+o+3*WSZ_DD;
        const __nv_bfloat16 *dh = wbh+o+4*WSZ_DD,    *dl = wbl+o+4*WSZ_DD;
        const __nv_bfloat16 *ukh= wbh+o+4*WSZ_DD+WSZ_HALF,   *ukl= wbl+o+4*WSZ_DD+WSZ_HALF;
        const __nv_bfloat16 *uvh= wbh+o+4*WSZ_DD+2*WSZ_HALF, *uvl= wbl+o+4*WSZ_DD+2*WSZ_HALF;

        gemm_mma<<<g_d, 256, DSMG>>>(ROWS, DM, DM, h, qh, ql, nullptr, q);
        gemm_mma<<<g_d, 256, DSMG>>>(ROWS, DM, DM, h, kh, kl, nullptr, k);
        gemm_mma<<<g_d, 256, DSMG>>>(ROWS, DM, DM, h, vh, vl, nullptr, v);
        add_k<<<(ROWS * DM + 255) / 256, 256>>>(k, v, kv, ROWS * DM);
        gemm_mma<<<g_dl, 256, DSMG>>>(ROWS, DLAT, DM, kv, dh, dl, nullptr, lat);
        gemm_mma<<<g_d, 256, DSMG>>>(ROWS, DM, DLAT, lat, ukh, ukl, nullptr, kr);
        gemm_mma<<<g_d, 256, DSMG>>>(ROWS, DM, DLAT, lat, uvh, uvl, nullptr, vr);

        flash_k<<<dim3(SEQ/128, BSZ*NH), 256, DSMF>>>(q, kr, vr, kv);

        gemm_mma<<<g_d, 256, DSMG>>>(ROWS, DM, DM, kv, oh, ol, nullptr, h);
    }

    // ---- vocab projection ----
    gemm_mma<<<g_voc, 256, DSMG>>>(ROWS, VOC, DM, h, wbh + OFF_WOUT, wbl + OFF_WOUT, bout, out);
}

// round 13
// speedup vs baseline: 1.1564x; 1.0189x over previous
#include <cuda_runtime.h>
#include <cuda_bf16.h>
#include <math.h>
#include <stdint.h>

#define BSZ  2
#define SEQ  1024
#define DM   1024
#define NH   16
#define HDIM 64
#define NL   4
#define VOC  32000
#define NFR  50
#define DLAT 512
#define ROWS (BSZ*SEQ)   // 2048
#define KT   16

// ---------------- scratch (device globals; no allocation allowed) ----------
__device__ float g_h [ROWS*DM];
__device__ float g_q [ROWS*DM];
__device__ float g_k [ROWS*DM];
__device__ float g_v [ROWS*DM];
__device__ float g_kv[ROWS*DM];
__device__ float g_kr[ROWS*DM];
__device__ float g_vr[ROWS*DM];
__device__ float g_lat[ROWS*DLAT];
__device__ float g_four[ROWS*NFR];
// pre-split activation (A operand) buffers
__device__ __align__(16) __nv_bfloat16 g_ah[ROWS*DM];
__device__ __align__(16) __nv_bfloat16 g_al[ROWS*DM];

// transposed + split weights: [N][K] bf16, hi and lo halves
#define WSZ_DD   (1024*1024)
#define WSZ_HALF (512*1024)
#define LSTRIDE  (4*WSZ_DD + 3*WSZ_HALF)
#define OFF_RULE 0
#define OFF_L(l) ((size_t)WSZ_DD + (size_t)(l)*LSTRIDE)
#define OFF_WOUT ((size_t)WSZ_DD + 4*(size_t)LSTRIDE)
#define WTOT     (OFF_WOUT + (size_t)VOC*DM)
__device__ __align__(16) __nv_bfloat16 g_wbh[WTOT];
__device__ __align__(16) __nv_bfloat16 g_wbl[WTOT];

// ---------------- f32x2 packed helpers (Blackwell FFMA2) -------------------
__device__ __forceinline__ unsigned long long pk2(float lo, float hi) {
    unsigned long long r;
    asm("mov.b64 %0, {%1, %2};" : "=l"(r) : "f"(lo), "f"(hi));
    return r;
}
__device__ __forceinline__ unsigned long long ffma2(
    unsigned long long a, unsigned long long b, unsigned long long c) {
    unsigned long long d;
    asm("fma.rn.f32x2 %0, %1, %2, %3;" : "=l"(d) : "l"(a), "l"(b), "l"(c));
    return d;
}
__device__ __forceinline__ float2 up2(unsigned long long v) {
    float2 f;
    asm("mov.b64 {%0, %1}, %2;" : "=f"(f.x), "=f"(f.y) : "l"(v));
    return f;
}

// ---------------- misc helpers ---------------------------------------------
__device__ __forceinline__ uint32_t smem_to_u32(const void* p) {
    uint32_t a;
    asm("{ .reg .u64 t; cvta.to.shared.u64 t, %1; cvt.u32.u64 %0, t; }" : "=r"(a) : "l"(p));
    return a;
}
__device__ __forceinline__ uint32_t bfpack(float lo, float hi) {
    uint32_t r;
    asm("cvt.rn.bf16x2.f32 %0, %1, %2;" : "=r"(r) : "f"(hi), "f"(lo));
    return r;
}
__device__ __forceinline__ float bflo(uint32_t p) { return __uint_as_float(p << 16); }
__device__ __forceinline__ float bfhi(uint32_t p) { return __uint_as_float(p & 0xffff0000u); }
#define STS128(addr, a, b, c, d) \
    asm volatile("st.shared.v4.b32 [%0], {%1, %2, %3, %4};" \
        :: "r"(addr), "r"(a), "r"(b), "r"(c), "r"(d) : "memory")
#define STS32(addr, v) \
    asm volatile("st.shared.b32 [%0], %1;" :: "r"(addr), "r"(v) : "memory")
#define LDSM_X4(r0, r1, r2, r3, addr) \
    asm volatile("ldmatrix.sync.aligned.m8n8.x4.shared.b16 {%0,%1,%2,%3}, [%4];" \
        : "=r"(r0), "=r"(r1), "=r"(r2), "=r"(r3) : "r"(addr))
#define LDSM_X2(r0, r1, addr) \
    asm volatile("ldmatrix.sync.aligned.m8n8.x2.shared.b16 {%0,%1}, [%2];" \
        : "=r"(r0), "=r"(r1) : "r"(addr))
#define LDSM_X2T(r0, r1, addr) \
    asm volatile("ldmatrix.sync.aligned.m8n8.x2.trans.shared.b16 {%0,%1}, [%2];" \
        : "=r"(r0), "=r"(r1) : "r"(addr))
#define MMA16816(d, a0, a1, a2, a3, b0, b1) \
    asm volatile("mma.sync.aligned.m16n8k16.row.col.f32.bf16.bf16.f32 " \
        "{%0,%1,%2,%3}, {%4,%5,%6,%7}, {%8,%9}, {%0,%1,%2,%3};" \
        : "+f"((d)[0]), "+f"((d)[1]), "+f"((d)[2]), "+f"((d)[3]) \
        : "r"(a0), "r"(a1), "r"(a2), "r"(a3), "r"(b0), "r"(b1))

// ===== weight transpose + bf16 split, vectorized stores ====================
__global__ __launch_bounds__(256) void wsplit_k(
    const float* __restrict__ W, int K, int N,
    __nv_bfloat16* __restrict__ Th, __nv_bfloat16* __restrict__ Tl)
{
    __shared__ float t[32][33];
    const int k0 = blockIdx.y * 32, n0 = blockIdx.x * 32;
    const int tx = threadIdx.x, ty = threadIdx.y;   // (32,8)
    const int tid = ty * 32 + tx;
#pragma unroll
    for (int i = 0; i < 4; i++)
        t[ty + 8 * i][tx] = W[(size_t)(k0 + ty + 8 * i) * N + n0 + tx];
    __syncthreads();
    const int half = tid >> 7;
    const int r = tid & 127;
    const int nl = r >> 2;
    const int kg = r & 3;
    uint32_t h[4], l[4];
#pragma unroll
    for (int i = 0; i < 4; i++) {
        float x0 = t[kg * 8 + 2 * i][nl];
        float x1 = t[kg * 8 + 2 * i + 1][nl];
        uint32_t hp = bfpack(x0, x1);
        uint32_t lp = bfpack(x0 - bflo(hp), x1 - bfhi(hp));
        h[i] = hp; l[i] = lp;
    }
    size_t o = (size_t)(n0 + nl) * K + k0 + kg * 8;
    if (half == 0) *(uint4*)(Th + o) = make_uint4(h[0], h[1], h[2], h[3]);
    else           *(uint4*)(Tl + o) = make_uint4(l[0], l[1], l[2], l[3]);
}

// ===== activation split: A (+A2) fp32 -> bf16 hi/lo (flat, vectorized) =====
__global__ __launch_bounds__(256) void asplit_k(
    const float* __restrict__ A, const float* __restrict__ A2, int total8,
    __nv_bfloat16* __restrict__ Ah, __nv_bfloat16* __restrict__ Al)
{
    int idx = blockIdx.x * 256 + threadIdx.x;
    if (idx >= total8) return;
    const float4* p = (const float4*)A + (size_t)idx * 2;
    float4 x0 = p[0], x1 = p[1];
    if (A2) {
        const float4* p2 = (const float4*)A2 + (size_t)idx * 2;
        float4 y0 = p2[0], y1 = p2[1];
        x0.x += y0.x; x0.y += y0.y; x0.z += y0.z; x0.w += y0.w;
        x1.x += y1.x; x1.y += y1.y; x1.z += y1.z; x1.w += y1.w;
    }
    uint32_t h0 = bfpack(x0.x, x0.y), h1 = bfpack(x0.z, x0.w);
    uint32_t h2 = bfpack(x1.x, x1.y), h3 = bfpack(x1.z, x1.w);
    uint32_t l0 = bfpack(x0.x - bflo(h0), x0.y - bfhi(h0));
    uint32_t l1 = bfpack(x0.z - bflo(h1), x0.w - bfhi(h1));
    uint32_t l2 = bfpack(x1.x - bflo(h2), x1.y - bfhi(h2));
    uint32_t l3 = bfpack(x1.z - bflo(h3), x1.w - bfhi(h3));
    *(uint4*)(Ah + (size_t)idx * 8) = make_uint4(h0, h1, h2, h3);
    *(uint4*)(Al + (size_t)idx * 8) = make_uint4(l0, l1, l2, l3);
}

// ================= HMMA bf16-split GEMM (pre-split A) ======================
#define ASTR   40                       // 32-elem rows + pad
#define TILEB  (128*80)
#define OAH    0
#define OAL    (TILEB)
#define OBH    (2*TILEB)
#define OBL    (3*TILEB)
#define BUFSTR (4*TILEB)
#define DSMG   (2*BUFSTR)               // 81920

__global__ __launch_bounds__(256) void gemm_mma(
    int M, int N, int K,
    const __nv_bfloat16* __restrict__ Ah, const __nv_bfloat16* __restrict__ Al,
    const __nv_bfloat16* __restrict__ Bh, const __nv_bfloat16* __restrict__ Bl,
    const float* __restrict__ bias, float* __restrict__ C)
{
    extern __shared__ char smem[];
    const uint32_t sb = smem_to_u32(smem);
    const int tid = threadIdx.x, lane = tid & 31, wid = tid >> 5;
    const int brow = blockIdx.y * 128, bcol = blockIdx.x * 128;
    const int wm = wid & 1, wn = wid >> 1;

    const int lrow = tid >> 1, lhalf = tid & 1;
    const __nv_bfloat16* Ahp = Ah + (size_t)(brow + lrow) * K + lhalf * 16;
    const __nv_bfloat16* Alp = Al + (size_t)(brow + lrow) * K + lhalf * 16;
    const __nv_bfloat16* Bhp = Bh + (size_t)(bcol + lrow) * K + lhalf * 16;
    const __nv_bfloat16* Blp = Bl + (size_t)(bcol + lrow) * K + lhalf * 16;
    const uint32_t soff = (uint32_t)(lrow * ASTR + lhalf * 16) * 2;

    float acc[4][4][4];
#pragma unroll
    for (int i = 0; i < 4; i++)
#pragma unroll
        for (int j = 0; j < 4; j++)
#pragma unroll
            for (int e = 0; e < 4; e++) acc[i][j][e] = 0.f;

    uint4 pah[2], pal[2], pbh[2], pbl[2];

#define LOADG(k0) do { \
    pah[0] = *(const uint4*)(Ahp + (k0)); pah[1] = *(const uint4*)(Ahp + (k0) + 8); \
    pal[0] = *(const uint4*)(Alp + (k0)); pal[1] = *(const uint4*)(Alp + (k0) + 8); \
    pbh[0] = *(const uint4*)(Bhp + (k0)); pbh[1] = *(const uint4*)(Bhp + (k0) + 8); \
    pbl[0] = *(const uint4*)(Blp + (k0)); pbl[1] = *(const uint4*)(Blp + (k0) + 8); \
} while (0)

#define STOREBUF(b) do { \
    uint32_t base_ = sb + (uint32_t)(b) * BUFSTR; \
    STS128(base_ + OAH + soff,      pah[0].x, pah[0].y, pah[0].z, pah[0].w); \
    STS128(base_ + OAH + soff + 16, pah[1].x, pah[1].y, pah[1].z, pah[1].w); \
    STS128(base_ + OAL + soff,      pal[0].x, pal[0].y, pal[0].z, pal[0].w); \
    STS128(base_ + OAL + soff + 16, pal[1].x, pal[1].y, pal[1].z, pal[1].w); \
    STS128(base_ + OBH + soff,      pbh[0].x, pbh[0].y, pbh[0].z, pbh[0].w); \
    STS128(base_ + OBH + soff + 16, pbh[1].x, pbh[1].y, pbh[1].z, pbh[1].w); \
    STS128(base_ + OBL + soff,      pbl[0].x, pbl[0].y, pbl[0].z, pbl[0].w); \
    STS128(base_ + OBL + soff + 16, pbl[1].x, pbl[1].y, pbl[1].z, pbl[1].w); \
} while (0)

    const int nchunk = K / 32;
    LOADG(0);
    STOREBUF(0);
    __syncthreads();

    const uint32_t arow = (uint32_t)(wm * 64 + (lane & 15));
    const uint32_t acol = (uint32_t)((lane >> 4) * 8);
    const uint32_t brw  = (uint32_t)(wn * 32 + (lane & 7));
    const uint32_t bcl  = (uint32_t)(((lane >> 3) & 1) * 8);

    int buf = 0;
    for (int ck = 0; ck < nchunk; ck++) {
        if (ck + 1 < nchunk) LOADG((ck + 1) * 32);

        const uint32_t base = sb + (uint32_t)buf * BUFSTR;
#pragma unroll
        for (int ks = 0; ks < 2; ks++) {
            uint32_t ah[4][4], al[4][4];
#pragma unroll
            for (int mt = 0; mt < 4; mt++) {
                uint32_t aoff = ((arow + mt * 16) * ASTR + acol + ks * 16) * 2;
                LDSM_X4(ah[mt][0], ah[mt][1], ah[mt][2], ah[mt][3], base + OAH + aoff);
                LDSM_X4(al[mt][0], al[mt][1], al[mt][2], al[mt][3], base + OAL + aoff);
            }
#pragma unroll
            for (int nt = 0; nt < 4; nt++) {
                uint32_t boff = ((brw + nt * 8) * ASTR + bcl + ks * 16) * 2;
                uint32_t bh0, bh1, bl0, bl1;
                LDSM_X2(bh0, bh1, base + OBH + boff);
                LDSM_X2(bl0, bl1, base + OBL + boff);
#pragma unroll
                for (int mt = 0; mt < 4; mt++) {
                    MMA16816(acc[mt][nt], ah[mt][0], ah[mt][1], ah[mt][2], ah[mt][3], bh0, bh1);
                    MMA16816(acc[mt][nt], ah[mt][0], ah[mt][1], ah[mt][2], ah[mt][3], bl0, bl1);
                    MMA16816(acc[mt][nt], al[mt][0], al[mt][1], al[mt][2], al[mt][3], bh0, bh1);
                }
            }
        }
        if (ck + 1 < nchunk) STOREBUF(buf ^ 1);
        __syncthreads();
        buf ^= 1;
    }

#pragma unroll
    for (int mt = 0; mt < 4; mt++) {
        int r0 = brow + wm * 64 + mt * 16 + (lane >> 2);
#pragma unroll
        for (int nt = 0; nt < 4; nt++) {
            int c = bcol + wn * 32 + nt * 8 + (lane & 3) * 2;
            float bx = 0.f, by = 0.f;
            if (bias) { bx = bias[c]; by = bias[c + 1]; }
            float2 o0, o1;
            o0.x = acc[mt][nt][0] + bx; o0.y = acc[mt][nt][1] + by;
            o1.x = acc[mt][nt][2] + bx; o1.y = acc[mt][nt][3] + by;
            *(float2*)(C + (size_t)r0 * N + c)       = o0;
            *(float2*)(C + (size_t)(r0 + 8) * N + c) = o1;
        }
    }
#undef LOADG
#undef STOREBUF
}

// ================= fused flash attention (split HMMA, R11-validated) =======
#define QSTR   72
#define VSTR   72
#define PSTR   136
#define QKTILE (128*144)
#define FA_OQH 0
#define FA_OQL (QKTILE)
#define FA_OKH (2*QKTILE)
#define FA_OKL (3*QKTILE)
#define FA_OVH (4*QKTILE)
#define FA_OVL (5*QKTILE)
#define FA_OPH (6*QKTILE)
#define FA_OPL (FA_OPH + 128*272)
#define FA_M   (FA_OPL + 128*272)
#define FA_L   (FA_M + 512)
#define FA_R   (FA_L + 512)
#define FA_PMX (FA_R + 512)
#define FA_PSM (FA_PMX + 2048)
#define FA_TAB (FA_PSM + 2048)
#define DSMF   (FA_TAB + 1024)

__global__ __launch_bounds__(256) void flash_k(
    const float* __restrict__ Q, const float* __restrict__ Kc,
    const float* __restrict__ V, float* __restrict__ O)
{
    extern __shared__ char smem[];
    const uint32_t sb = smem_to_u32(smem);
    float* mrow = (float*)(smem + FA_M);
    float* lrow = (float*)(smem + FA_L);
    float* rrow = (float*)(smem + FA_R);
    float* pmax = (float*)(smem + FA_PMX);
    float* psum = (float*)(smem + FA_PSM);
    float* tab  = (float*)(smem + FA_TAB);
    const int tid = threadIdx.x, lane = tid & 31, wid = tid >> 5;
    const int bh = blockIdx.y, b = bh >> 4, h = bh & 15;
    const int i0 = blockIdx.x * 128;
    const int wm = wid & 1, wn = wid >> 1;       // S-phase 2x4
    const int wmv = wid & 3, wnv = wid >> 2;     // AV-phase 4x2

    const int lr2 = tid >> 1, ls2 = tid & 1;

    // ---- load Q tile once (split hi/lo, A-operand layout, stride QSTR) ----
    {
        const float* qp = Q + (size_t)(b * SEQ + i0 + lr2) * DM + h * HDIM + ls2 * 32;
        const uint32_t off = (uint32_t)(lr2 * QSTR + ls2 * 32) * 2;
        uint32_t hh[16], ll[16];
#pragma unroll
        for (int i = 0; i < 8; i++) {
            float4 x = *(const float4*)(qp + i * 4);
            uint32_t h0 = bfpack(x.x, x.y), h1 = bfpack(x.z, x.w);
            hh[2*i] = h0; hh[2*i+1] = h1;
            ll[2*i]   = bfpack(x.x - bflo(h0), x.y - bfhi(h0));
            ll[2*i+1] = bfpack(x.z - bflo(h1), x.w - bfhi(h1));
        }
#pragma unroll
        for (int i = 0; i < 4; i++) {
            STS128(sb + FA_OQH + off + i * 16, hh[4*i], hh[4*i+1], hh[4*i+2], hh[4*i+3]);
            STS128(sb + FA_OQL + off + i * 16, ll[4*i], ll[4*i+1], ll[4*i+2], ll[4*i+3]);
        }
    }
    if (tid < 128) { mrow[tid] = -1e30f; lrow[tid] = 0.f; }

    float oacc[2][4][4];
#pragma unroll
    for (int i = 0; i < 2; i++)
#pragma unroll
        for (int j = 0; j < 4; j++)
#pragma unroll
            for (int e = 0; e < 4; e++) oacc[i][j][e] = 0.f;

    const float scale = 0.03125f;
    const uint32_t arow = (uint32_t)(wm * 64 + (lane & 15));
    const uint32_t acol = (uint32_t)((lane >> 4) * 8);
    const uint32_t brw  = (uint32_t)(wn * 32 + (lane & 7));
    const uint32_t bcl  = (uint32_t)(((lane >> 3) & 1) * 8);
    const uint32_t arv  = (uint32_t)(wmv * 32 + (lane & 15));
    const uint32_t klv  = (uint32_t)(lane & 15);
    const int lr4 = lane >> 2, lc4 = (lane & 3) * 2;

    for (int jt = 0; jt < 8; jt++) {
        const int j0 = jt * 128;
        __syncthreads();
        tab[tid] = __expf(-0.01f * fabsf((float)(i0 - j0 + tid - 128)));

        // ---- load K (n-major) and V (k-major) tiles, split hi/lo ----
        {
            const float* kp = Kc + (size_t)(b * SEQ + j0 + lr2) * DM + h * HDIM + ls2 * 32;
            const float* vp = V  + (size_t)(b * SEQ + j0 + lr2) * DM + h * HDIM + ls2 * 32;
            const uint32_t offk = (uint32_t)(lr2 * QSTR + ls2 * 32) * 2;
            const uint32_t offv = (uint32_t)(lr2 * VSTR + ls2 * 32) * 2;
            uint32_t hh[16], ll[16];
#pragma unroll
            for (int i = 0; i < 8; i++) {
                float4 x = *(const float4*)(kp + i * 4);
                uint32_t h0 = bfpack(x.x, x.y), h1 = bfpack(x.z, x.w);
                hh[2*i] = h0; hh[2*i+1] = h1;
                ll[2*i]   = bfpack(x.x - bflo(h0), x.y - bfhi(h0));
                ll[2*i+1] = bfpack(x.z - bflo(h1), x.w - bfhi(h1));
            }
#pragma unroll
            for (int i = 0; i < 4; i++) {
                STS128(sb + FA_OKH + offk + i * 16, hh[4*i], hh[4*i+1], hh[4*i+2], hh[4*i+3]);
                STS128(sb + FA_OKL + offk + i * 16, ll[4*i], ll[4*i+1], ll[4*i+2], ll[4*i+3]);
            }
#pragma unroll
            for (int i = 0; i < 8; i++) {
                float4 x = *(const float4*)(vp + i * 4);
                uint32_t h0 = bfpack(x.x, x.y), h1 = bfpack(x.z, x.w);
                hh[2*i] = h0; hh[2*i+1] = h1;
                ll[2*i]   = bfpack(x.x - bflo(h0), x.y - bfhi(h0));
                ll[2*i+1] = bfpack(x.z - bflo(h1), x.w - bfhi(h1));
            }
#pragma unroll
            for (int i = 0; i < 4; i++) {
                STS128(sb + FA_OVH + offv + i * 16, hh[4*i], hh[4*i+1], hh[4*i+2], hh[4*i+3]);
                STS128(sb + FA_OVL + offv + i * 16, ll[4*i], ll[4*i+1], ll[4*i+2], ll[4*i+3]);
            }
        }
        __syncthreads();

        // ---- S = Q K^T (split) ----
        float sacc[4][4][4];
#pragma unroll
        for (int i = 0; i < 4; i++)
#pragma unroll
            for (int j = 0; j < 4; j++)
#pragma unroll
                for (int e = 0; e < 4; e++) sacc[i][j][e] = 0.f;
#pragma unroll
        for (int ks = 0; ks < 4; ks++) {
            uint32_t ah[4][4], al[4][4];
#pragma unroll
            for (int mt = 0; mt < 4; mt++) {
                uint32_t aoff = ((arow + mt * 16) * QSTR + acol + ks * 16) * 2;
                LDSM_X4(ah[mt][0], ah[mt][1], ah[mt][2], ah[mt][3], sb + FA_OQH + aoff);
                LDSM_X4(al[mt][0], al[mt][1], al[mt][2], al[mt][3], sb + FA_OQL + aoff);
            }
#pragma unroll
            for (int nt = 0; nt < 4; nt++) {
                uint32_t boff = ((brw + nt * 8) * QSTR + bcl + ks * 16) * 2;
                uint32_t bh0, bh1, bl0, bl1;
                LDSM_X2(bh0, bh1, sb + FA_OKH + boff);
                LDSM_X2(bl0, bl1, sb + FA_OKL + boff);
#pragma unroll
                for (int mt = 0; mt < 4; mt++) {
                    MMA16816(sacc[mt][nt], ah[mt][0], ah[mt][1], ah[mt][2], ah[mt][3], bh0, bh1);
                    MMA16816(sacc[mt][nt], ah[mt][0], ah[mt][1], ah[mt][2], ah[mt][3], bl0, bl1);
                    MMA16816(sacc[mt][nt], al[mt][0], al[mt][1], al[mt][2], al[mt][3], bh0, bh1);
                }
            }
        }

        // ---- scale + decay, per-warp row max ----
#pragma unroll
        for (int mt = 0; mt < 4; mt++) {
            int ri = wm * 64 + mt * 16 + lr4;
            float mx0 = -1e30f, mx1 = -1e30f;
#pragma unroll
            for (int nt = 0; nt < 4; nt++) {
                int cj = wn * 32 + nt * 8 + lc4;
                int d0 = ri - cj + 128;
                sacc[mt][nt][0] *= scale * tab[d0];
                sacc[mt][nt][1] *= scale * tab[d0 - 1];
                sacc[mt][nt][2] *= scale * tab[d0 + 8];
                sacc[mt][nt][3] *= scale * tab[d0 + 7];
                mx0 = fmaxf(mx0, fmaxf(sacc[mt][nt][0], sacc[mt][nt][1]));
                mx1 = fmaxf(mx1, fmaxf(sacc[mt][nt][2], sacc[mt][nt][3]));
            }
            mx0 = fmaxf(mx0, __shfl_xor_sync(0xffffffffu, mx0, 1));
            mx0 = fmaxf(mx0, __shfl_xor_sync(0xffffffffu, mx0, 2));
            mx1 = fmaxf(mx1, __shfl_xor_sync(0xffffffffu, mx1, 1));
            mx1 = fmaxf(mx1, __shfl_xor_sync(0xffffffffu, mx1, 2));
            if ((lane & 3) == 0) {
                pmax[wn * 128 + ri] = mx0;
                pmax[wn * 128 + ri + 8] = mx1;
            }
        }
        __syncthreads();
        if (tid < 128) {
            float mo = mrow[tid];
            float mn = fmaxf(fmaxf(pmax[tid], pmax[128 + tid]),
                             fmaxf(pmax[256 + tid], pmax[384 + tid]));
            mn = fmaxf(mo, mn);
            rrow[tid] = __expf(mo - mn);
            mrow[tid] = mn;
        }
        __syncthreads();

        // ---- exp, split-store P, partial sums ----
#pragma unroll
        for (int mt = 0; mt < 4; mt++) {
            int row0 = wm * 64 + mt * 16 + lr4;
            int row1 = row0 + 8;
            float m0 = mrow[row0], m1 = mrow[row1];
            float s0 = 0.f, s1 = 0.f;
#pragma unroll
            for (int nt = 0; nt < 4; nt++) {
                int col = wn * 32 + nt * 8 + lc4;
                float p0 = __expf(sacc[mt][nt][0] - m0);
                float p1 = __expf(sacc[mt][nt][1] - m0);
                float p2 = __expf(sacc[mt][nt][2] - m1);
                float p3 = __expf(sacc[mt][nt][3] - m1);
                s0 += p0 + p1; s1 += p2 + p3;
                uint32_t ph0 = bfpack(p0, p1);
                uint32_t pl0 = bfpack(p0 - bflo(ph0), p1 - bfhi(ph0));
                uint32_t ph1 = bfpack(p2, p3);
                uint32_t pl1 = bfpack(p2 - bflo(ph1), p3 - bfhi(ph1));
                uint32_t a0 = (uint32_t)(row0 * PSTR + col) * 2;
                uint32_t a1 = (uint32_t)(row1 * PSTR + col) * 2;
                STS32(sb + FA_OPH + a0, ph0);
                STS32(sb + FA_OPL + a0, pl0);
                STS32(sb + FA_OPH + a1, ph1);
                STS32(sb + FA_OPL + a1, pl1);
            }
            s0 += __shfl_xor_sync(0xffffffffu, s0, 1);
            s0 += __shfl_xor_sync(0xffffffffu, s0, 2);
            s1 += __shfl_xor_sync(0xffffffffu, s1, 1);
            s1 += __shfl_xor_sync(0xffffffffu, s1, 2);
            if ((lane & 3) == 0) {
                psum[wn * 128 + row0] = s0;
                psum[wn * 128 + row1] = s1;
            }
        }
        __syncthreads();
        if (tid < 128)
            lrow[tid] = lrow[tid] * rrow[tid]
                      + psum[tid] + psum[128 + tid] + psum[256 + tid] + psum[384 + tid];

        // ---- rescale O, then O += P @ V ----
#pragma unroll
        for (int mt = 0; mt < 2; mt++) {
            int r0 = wmv * 32 + mt * 16 + lr4;
            float f0 = rrow[r0], f1 = rrow[r0 + 8];
#pragma unroll
            for (int nt = 0; nt < 4; nt++) {
                oacc[mt][nt][0] *= f0; oacc[mt][nt][1] *= f0;
                oacc[mt][nt][2] *= f1; oacc[mt][nt][3] *= f1;
            }
        }
#pragma unroll
        for (int ks = 0; ks < 8; ks++) {
            uint32_t ah[2][4], al[2][4];
#pragma unroll
            for (int mt = 0; mt < 2; mt++) {
                uint32_t aoff = ((arv + mt * 16) * PSTR + (uint32_t)((lane >> 4) * 8) + ks * 16) * 2;
                LDSM_X4(ah[mt][0], ah[mt][1], ah[mt][2], ah[mt][3], sb + FA_OPH + aoff);
                LDSM_X4(al[mt][0], al[mt][1], al[mt][2], al[mt][3], sb + FA_OPL + aoff);
            }
#pragma unroll
            for (int nt = 0; nt < 4; nt++) {
                uint32_t boff = ((ks * 16 + klv) * VSTR + wnv * 32 + nt * 8) * 2;
                uint32_t bh0, bh1, bl0, bl1;
                LDSM_X2T(bh0, bh1, sb + FA_OVH + boff);
                LDSM_X2T(bl0, bl1, sb + FA_OVL + boff);
#pragma unroll
                for (int mt = 0; mt < 2; mt++) {
                    MMA16816(oacc[mt][nt], ah[mt][0], ah[mt][1], ah[mt][2], ah[mt][3], bh0, bh1);
                    MMA16816(oacc[mt][nt], ah[mt][0], ah[mt][1], ah[mt][2], ah[mt][3], bl0, bl1);
                    MMA16816(oacc[mt][nt], al[mt][0], al[mt][1], al[mt][2], al[mt][3], bh0, bh1);
                }
            }
        }
    }

    __syncthreads();
    // ---- normalize + write O ----
#pragma unroll
    for (int mt = 0; mt < 2; mt++) {
        int r0 = wmv * 32 + mt * 16 + lr4;
        float inv0 = 1.0f / lrow[r0];
        float inv1 = 1.0f / lrow[r0 + 8];
#pragma unroll
        for (int nt = 0; nt < 4; nt++) {
            int c = h * HDIM + wnv * 32 + nt * 8 + lc4;
            float2 o0, o1;
            o0.x = oacc[mt][nt][0] * inv0; o0.y = oacc[mt][nt][1] * inv0;
            o1.x = oacc[mt][nt][2] * inv1; o1.y = oacc[mt][nt][3] * inv1;
            *(float2*)(O + (size_t)(b * SEQ + i0 + r0) * DM + c)     = o0;
            *(float2*)(O + (size_t)(b * SEQ + i0 + r0 + 8) * DM + c) = o1;
        }
    }
}

// ---------------- FFMA2 SGEMM (kept for the K=50 embedding GEMM) -----------
__global__ __launch_bounds__(256) void sgemm2_k(
    int M, int N, int K,
    const float* __restrict__ A, const float* __restrict__ B,
    const float* __restrict__ bias, float* __restrict__ C)
{
    __shared__ __align__(16) float As[KT][128];
    __shared__ __align__(16) float Bs[KT][128];
    const int tid  = threadIdx.x;
    const int brow = blockIdx.y * 128;
    const int bcol = blockIdx.x * 128;
    const int ty = tid >> 4, tx = tid & 15;
    const int ar = tid >> 1, aks = (tid & 1) * 8;

    unsigned long long acc[8][4];
#pragma unroll
    for (int i = 0; i < 8; i++)
#pragma unroll
        for (int j = 0; j < 4; j++) acc[i][j] = 0ULL;

    for (int k0 = 0; k0 < K; k0 += KT) {
#pragma unroll
        for (int i = 0; i < 8; i++) {
            int kk = aks + i;
            As[kk][ar] = (k0 + kk < K) ? A[(size_t)(brow + ar) * K + k0 + kk] : 0.f;
        }
#pragma unroll
        for (int p = 0; p < 2; p++) {
            int id = p * 256 + tid;
            int kk = id >> 5, c4 = (id & 31) * 4;
            float4 bv = make_float4(0.f, 0.f, 0.f, 0.f);
            if (k0 + kk < K) bv = *(const float4*)(B + (size_t)(k0 + kk) * N + bcol + c4);
            *(float4*)&Bs[kk][c4] = bv;
        }
        __syncthreads();
#pragma unroll
        for (int kk = 0; kk < KT; kk++) {
            float4 a0 = *(const float4*)&As[kk][ty * 4];
            float4 a1 = *(const float4*)&As[kk][64 + ty * 4];
            float4 b0 = *(const float4*)&Bs[kk][tx * 4];
            float4 b1 = *(const float4*)&Bs[kk][64 + tx * 4];
            unsigned long long rb[4] = { pk2(b0.x, b0.y), pk2(b0.z, b0.w),
                                         pk2(b1.x, b1.y), pk2(b1.z, b1.w) };
            float ra[8] = { a0.x, a0.y, a0.z, a0.w, a1.x, a1.y, a1.z, a1.w };
#pragma unroll
            for (int i = 0; i < 8; i++) {
                unsigned long long ad = pk2(ra[i], ra[i]);
#pragma unroll
                for (int j = 0; j < 4; j++) acc[i][j] = ffma2(ad, rb[j], acc[i][j]);
            }
        }
        __syncthreads();
    }
#pragma unroll
    for (int ih = 0; ih < 2; ih++)
#pragma unroll
    for (int ii = 0; ii < 4; ii++) {
        int i = ih * 4 + ii;
        int r = brow + ih * 64 + ty * 4 + ii;
#pragma unroll
        for (int jh = 0; jh < 2; jh++) {
            int c = bcol + jh * 64 + tx * 4;
            float2 p0 = up2(acc[i][jh * 2]);
            float2 p1 = up2(acc[i][jh * 2 + 1]);
            float4 o; o.x = p0.x; o.y = p0.y; o.z = p1.x; o.w = p1.y;
            if (bias) { o.x += bias[c]; o.y += bias[c+1]; o.z += bias[c+2]; o.w += bias[c+3]; }
            *(float4*)(C + (size_t)r * N + c) = o;
        }
    }
}

// ---------------- Fourier token features -----------------------------------
__global__ void fourier_k(const int* __restrict__ src, const float* __restrict__ a_n,
                          const float* __restrict__ b_n, float* __restrict__ F)
{
    int idx = blockIdx.x * blockDim.x + threadIdx.x;
    if (idx >= ROWS * NFR) return;
    int bs = idx / NFR, n = idx % NFR;
    int tok = src[bs];
    float x   = (float)tok * (1.0f / (float)VOC);
    float ang = 6.28318530717958647692f * (float)(n + 1) * x;
    F[idx] = a_n[tok * NFR + n] * cosf(ang) + b_n[tok * NFR + n] * sinf(ang);
}

// ---------------- h += sinusoidal PE ---------------------------------------
__global__ void addpe_k(float* __restrict__ h)
{
    int idx = blockIdx.x * blockDim.x + threadIdx.x;
    if (idx >= ROWS * DM) return;
    int d = idx & (DM - 1);
    int s = (idx / DM) & (SEQ - 1);
    float div = expf(-(float)(d & ~1) * 8.99447301948846e-3f);
    float ang = (float)s * div;
    h[idx] += (d & 1) ? cosf(ang) : sinf(ang);
}

// ---------------------------------------------------------------------------
extern "C" void kernel_launch(void* const* d_in, const int* in_sizes, int n_in,
                              void* d_out, int out_size)
{
    const int*   src    = (const int*)  d_in[0];
    const float* a_n    = (const float*)d_in[2];
    const float* b_n    = (const float*)d_in[3];
    const float* proj_w = (const float*)d_in[4];
    const float* proj_b = (const float*)d_in[5];
    const float* rule   = (const float*)d_in[6];
    const float* Wq     = (const float*)d_in[7];
    const float* Wk     = (const float*)d_in[8];
    const float* Wv     = (const float*)d_in[9];
    const float* Wo     = (const float*)d_in[10];
    const float* Wdown  = (const float*)d_in[11];
    const float* Wup_k  = (const float*)d_in[12];
    const float* Wup_v  = (const float*)d_in[13];
    const float* Wout   = (const float*)d_in[14];
    const float* bout   = (const float*)d_in[15];
    float* out = (float*)d_out;

    float *h, *q, *k, *v, *kv, *kr, *vr, *lat, *four;
    __nv_bfloat16 *wbh, *wbl, *ah, *al;
    cudaGetSymbolAddress((void**)&h,    g_h);
    cudaGetSymbolAddress((void**)&q,    g_q);
    cudaGetSymbolAddress((void**)&k,    g_k);
    cudaGetSymbolAddress((void**)&v,    g_v);
    cudaGetSymbolAddress((void**)&kv,   g_kv);
    cudaGetSymbolAddress((void**)&kr,   g_kr);
    cudaGetSymbolAddress((void**)&vr,   g_vr);
    cudaGetSymbolAddress((void**)&lat,  g_lat);
    cudaGetSymbolAddress((void**)&four, g_four);
    cudaGetSymbolAddress((void**)&wbh,  g_wbh);
    cudaGetSymbolAddress((void**)&wbl,  g_wbl);
    cudaGetSymbolAddress((void**)&ah,   g_ah);
    cudaGetSymbolAddress((void**)&al,   g_al);

    cudaFuncSetAttribute(gemm_mma, cudaFuncAttributeMaxDynamicSharedMemorySize, DSMG);
    cudaFuncSetAttribute(flash_k,  cudaFuncAttributeMaxDynamicSharedMemorySize, DSMF);

    // ---- transpose + split all weights into [N,K] bf16 hi/lo ----
    {
        const dim3 b(32, 8);
        wsplit_k<<<dim3(DM/32, DM/32), b>>>(rule, DM, DM, wbh + OFF_RULE, wbl + OFF_RULE);
        for (int l = 0; l < NL; l++) {
            size_t o = OFF_L(l);
            wsplit_k<<<dim3(DM/32, DM/32), b>>>(Wq + (size_t)l*DM*DM, DM, DM, wbh+o, wbl+o);
            wsplit_k<<<dim3(DM/32, DM/32), b>>>(Wk + (size_t)l*DM*DM, DM, DM, wbh+o+WSZ_DD, wbl+o+WSZ_DD);
            wsplit_k<<<dim3(DM/32, DM/32), b>>>(Wv + (size_t)l*DM*DM, DM, DM, wbh+o+2*WSZ_DD, wbl+o+2*WSZ_DD);
            wsplit_k<<<dim3(DM/32, DM/32), b>>>(Wo + (size_t)l*DM*DM, DM, DM, wbh+o+3*WSZ_DD, wbl+o+3*WSZ_DD);
            wsplit_k<<<dim3(DLAT/32, DM/32), b>>>(Wdown + (size_t)l*DM*DLAT, DM, DLAT,
                                                  wbh+o+4*WSZ_DD, wbl+o+4*WSZ_DD);
            wsplit_k<<<dim3(DM/32, DLAT/32), b>>>(Wup_k + (size_t)l*DLAT*DM, DLAT, DM,
                                                  wbh+o+4*WSZ_DD+WSZ_HALF, wbl+o+4*WSZ_DD+WSZ_HALF);
            wsplit_k<<<dim3(DM/32, DLAT/32), b>>>(Wup_v + (size_t)l*DLAT*DM, DLAT, DM,
                                                  wbh+o+4*WSZ_DD+2*WSZ_HALF, wbl+o+4*WSZ_DD+2*WSZ_HALF);
        }
        wsplit_k<<<dim3(VOC/32, DM/32), b>>>(Wout, DM, VOC, wbh + OFF_WOUT, wbl + OFF_WOUT);
    }

    const dim3 g_d  (DM   / 128, ROWS / 128);
    const dim3 g_dl (DLAT / 128, ROWS / 128);
    const dim3 g_voc(VOC  / 128, ROWS / 128);
    const int T8_DD = ROWS * DM / 8;      // 262144 -> 1024 blocks
    const int T8_DL = ROWS * DLAT / 8;    // 131072 -> 512 blocks

    // ---- embedding ----
    fourier_k<<<(ROWS * NFR + 255) / 256, 256>>>(src, a_n, b_n, four);
    sgemm2_k<<<g_d, 256>>>(ROWS, DM, NFR, four, proj_w, proj_b, q);
    asplit_k<<<T8_DD / 256, 256>>>(q, nullptr, T8_DD, ah, al);
    gemm_mma<<<g_d, 256, DSMG>>>(ROWS, DM, DM, ah, al, wbh + OFF_RULE, wbl + OFF_RULE, nullptr, h);
    addpe_k<<<(ROWS * DM + 255) / 256, 256>>>(h);

    // ---- layers ----
    for (int l = 0; l < NL; l++) {
        size_t o = OFF_L(l);
        const __nv_bfloat16 *qh = wbh+o,             *ql = wbl+o;
        const __nv_bfloat16 *kh = wbh+o+WSZ_DD,      *kl = wbl+o+WSZ_DD;
        const __nv_bfloat16 *vh = wbh+o+2*WSZ_DD,    *vl = wbl+o+2*WSZ_DD;
        const __nv_bfloat16 *oh = wbh+o+3*WSZ_DD,    *ol = wbl+o+3*WSZ_DD;
        const __nv_bfloat16 *dh = wbh+o+4*WSZ_DD,    *dl = wbl+o+4*WSZ_DD;
        const __nv_bfloat16 *ukh= wbh+o+4*WSZ_DD+WSZ_HALF,   *ukl= wbl+o+4*WSZ_DD+WSZ_HALF;
        const __nv_bfloat16 *uvh= wbh+o+4*WSZ_DD+2*WSZ_HALF, *uvl= wbl+o+4*WSZ_DD+2*WSZ_HALF;

        asplit_k<<<T8_DD / 256, 256>>>(h, nullptr, T8_DD, ah, al);
        gemm_mma<<<g_d, 256, DSMG>>>(ROWS, DM, DM, ah, al, qh, ql, nullptr, q);
        gemm_mma<<<g_d, 256, DSMG>>>(ROWS, DM, DM, ah, al, kh, kl, nullptr, k);
        gemm_mma<<<g_d, 256, DSMG>>>(ROWS, DM, DM, ah, al, vh, vl, nullptr, v);
        asplit_k<<<T8_DD / 256, 256>>>(k, v, T8_DD, ah, al);   // k+v fused
        gemm_mma<<<g_dl, 256, DSMG>>>(ROWS, DLAT, DM, ah, al, dh, dl, nullptr, lat);
        asplit_k<<<T8_DL / 256, 256>>>(lat, nullptr, T8_DL, ah, al);
        gemm_mma<<<g_d, 256, DSMG>>>(ROWS, DM, DLAT, ah, al, ukh, ukl, nullptr, kr);
        gemm_mma<<<g_d, 256, DSMG>>>(ROWS, DM, DLAT, ah, al, uvh, uvl, nullptr, vr);

        flash_k<<<dim3(SEQ/128, BSZ*NH), 256, DSMF>>>(q, kr, vr, kv);

        asplit_k<<<T8_DD / 256, 256>>>(kv, nullptr, T8_DD, ah, al);
        gemm_mma<<<g_d, 256, DSMG>>>(ROWS, DM, DM, ah, al, oh, ol, nullptr, h);
    }

    // ---- vocab projection ----
    asplit_k<<<T8_DD / 256, 256>>>(h, nullptr, T8_DD, ah, al);
    gemm_mma<<<g_voc, 256, DSMG>>>(ROWS, VOC, DM, ah, al, wbh + OFF_WOUT, wbl + OFF_WOUT, bout, out);
}

// round 14
// speedup vs baseline: 1.1660x; 1.0083x over previous
#include <cuda_runtime.h>
#include <cuda_bf16.h>
#include <math.h>
#include <stdint.h>

#define BSZ  2
#define SEQ  1024
#define DM   1024
#define NH   16
#define HDIM 64
#define NL   4
#define VOC  32000
#define NFR  50
#define DLAT 512
#define ROWS (BSZ*SEQ)   // 2048
#define KT   16

// ---------------- scratch (device globals; no allocation allowed) ----------
__device__ float g_h  [ROWS*DM];          // embed h (fp32, addpe target)
__device__ float g_t  [ROWS*DM];          // embed temp
__device__ float g_kv [ROWS*DM];          // attention output
__device__ float g_qkv [ROWS*3*DM];       // fused q|k|v
__device__ float g_krvr[ROWS*2*DM];       // fused kr|vr
__device__ float g_four[ROWS*NFR];
// split activation buffers
__device__ __align__(16) __nv_bfloat16 g_ah[ROWS*DM];
__device__ __align__(16) __nv_bfloat16 g_al[ROWS*DM];
__device__ __align__(16) __nv_bfloat16 g_hh[ROWS*DM];
__device__ __align__(16) __nv_bfloat16 g_hl[ROWS*DM];
__device__ __align__(16) __nv_bfloat16 g_lh[ROWS*DLAT];
__device__ __align__(16) __nv_bfloat16 g_ll[ROWS*DLAT];

// transposed + split weights: [N][K] bf16, hi and lo halves
#define WSZ_DD   (1024*1024)
#define WSZ_HALF (512*1024)
#define LSTRIDE  (4*WSZ_DD + 3*WSZ_HALF)
#define OFF_RULE 0
#define OFF_L(l) ((size_t)WSZ_DD + (size_t)(l)*LSTRIDE)
#define OFF_WOUT ((size_t)WSZ_DD + 4*(size_t)LSTRIDE)
#define WTOT     (OFF_WOUT + (size_t)VOC*DM)
__device__ __align__(16) __nv_bfloat16 g_wbh[WTOT];
__device__ __align__(16) __nv_bfloat16 g_wbl[WTOT];

// ---------------- f32x2 packed helpers (Blackwell FFMA2) -------------------
__device__ __forceinline__ unsigned long long pk2(float lo, float hi) {
    unsigned long long r;
    asm("mov.b64 %0, {%1, %2};" : "=l"(r) : "f"(lo), "f"(hi));
    return r;
}
__device__ __forceinline__ unsigned long long ffma2(
    unsigned long long a, unsigned long long b, unsigned long long c) {
    unsigned long long d;
    asm("fma.rn.f32x2 %0, %1, %2, %3;" : "=l"(d) : "l"(a), "l"(b), "l"(c));
    return d;
}
__device__ __forceinline__ float2 up2(unsigned long long v) {
    float2 f;
    asm("mov.b64 {%0, %1}, %2;" : "=f"(f.x), "=f"(f.y) : "l"(v));
    return f;
}

// ---------------- misc helpers ---------------------------------------------
__device__ __forceinline__ uint32_t smem_to_u32(const void* p) {
    uint32_t a;
    asm("{ .reg .u64 t; cvta.to.shared.u64 t, %1; cvt.u32.u64 %0, t; }" : "=r"(a) : "l"(p));
    return a;
}
__device__ __forceinline__ uint32_t bfpack(float lo, float hi) {
    uint32_t r;
    asm("cvt.rn.bf16x2.f32 %0, %1, %2;" : "=r"(r) : "f"(hi), "f"(lo));
    return r;
}
__device__ __forceinline__ float bflo(uint32_t p) { return __uint_as_float(p << 16); }
__device__ __forceinline__ float bfhi(uint32_t p) { return __uint_as_float(p & 0xffff0000u); }
#define STS128(addr, a, b, c, d) \
    asm volatile("st.shared.v4.b32 [%0], {%1, %2, %3, %4};" \
        :: "r"(addr), "r"(a), "r"(b), "r"(c), "r"(d) : "memory")
#define STS32(addr, v) \
    asm volatile("st.shared.b32 [%0], %1;" :: "r"(addr), "r"(v) : "memory")
#define LDSM_X4(r0, r1, r2, r3, addr) \
    asm volatile("ldmatrix.sync.aligned.m8n8.x4.shared.b16 {%0,%1,%2,%3}, [%4];" \
        : "=r"(r0), "=r"(r1), "=r"(r2), "=r"(r3) : "r"(addr))
#define LDSM_X2(r0, r1, addr) \
    asm volatile("ldmatrix.sync.aligned.m8n8.x2.shared.b16 {%0,%1}, [%2];" \
        : "=r"(r0), "=r"(r1) : "r"(addr))
#define LDSM_X2T(r0, r1, addr) \
    asm volatile("ldmatrix.sync.aligned.m8n8.x2.trans.shared.b16 {%0,%1}, [%2];" \
        : "=r"(r0), "=r"(r1) : "r"(addr))
#define MMA16816(d, a0, a1, a2, a3, b0, b1) \
    asm volatile("mma.sync.aligned.m16n8k16.row.col.f32.bf16.bf16.f32 " \
        "{%0,%1,%2,%3}, {%4,%5,%6,%7}, {%8,%9}, {%0,%1,%2,%3};" \
        : "+f"((d)[0]), "+f"((d)[1]), "+f"((d)[2]), "+f"((d)[3]) \
        : "r"(a0), "r"(a1), "r"(a2), "r"(a3), "r"(b0), "r"(b1))

// ===== weight transpose + bf16 split, vectorized stores ====================
__global__ __launch_bounds__(256) void wsplit_k(
    const float* __restrict__ W, int K, int N,
    __nv_bfloat16* __restrict__ Th, __nv_bfloat16* __restrict__ Tl)
{
    __shared__ float t[32][33];
    const int k0 = blockIdx.y * 32, n0 = blockIdx.x * 32;
    const int tx = threadIdx.x, ty = threadIdx.y;   // (32,8)
    const int tid = ty * 32 + tx;
#pragma unroll
    for (int i = 0; i < 4; i++)
        t[ty + 8 * i][tx] = W[(size_t)(k0 + ty + 8 * i) * N + n0 + tx];
    __syncthreads();
    const int half = tid >> 7;
    const int r = tid & 127;
    const int nl = r >> 2;
    const int kg = r & 3;
    uint32_t h[4], l[4];
#pragma unroll
    for (int i = 0; i < 4; i++) {
        float x0 = t[kg * 8 + 2 * i][nl];
        float x1 = t[kg * 8 + 2 * i + 1][nl];
        uint32_t hp = bfpack(x0, x1);
        uint32_t lp = bfpack(x0 - bflo(hp), x1 - bfhi(hp));
        h[i] = hp; l[i] = lp;
    }
    size_t o = (size_t)(n0 + nl) * K + k0 + kg * 8;
    if (half == 0) *(uint4*)(Th + o) = make_uint4(h[0], h[1], h[2], h[3]);
    else           *(uint4*)(Tl + o) = make_uint4(l[0], l[1], l[2], l[3]);
}

// ===== activation split: A (+A2) fp32 (strided) -> bf16 hi/lo ==============
__global__ __launch_bounds__(256) void asplit_k(
    const float* __restrict__ A, const float* __restrict__ A2,
    int rows, int cols8, int lda,
    __nv_bfloat16* __restrict__ Ah, __nv_bfloat16* __restrict__ Al)
{
    int idx = blockIdx.x * 256 + threadIdx.x;
    if (idx >= rows * cols8) return;
    int r = idx / cols8, c8 = idx - r * cols8;
    const float* base = A + (size_t)r * lda + c8 * 8;
    float4 x0 = *(const float4*)base, x1 = *(const float4*)(base + 4);
    if (A2) {
        const float* b2 = A2 + (size_t)r * lda + c8 * 8;
        float4 y0 = *(const float4*)b2, y1 = *(const float4*)(b2 + 4);
        x0.x += y0.x; x0.y += y0.y; x0.z += y0.z; x0.w += y0.w;
        x1.x += y1.x; x1.y += y1.y; x1.z += y1.z; x1.w += y1.w;
    }
    uint32_t h0 = bfpack(x0.x, x0.y), h1 = bfpack(x0.z, x0.w);
    uint32_t h2 = bfpack(x1.x, x1.y), h3 = bfpack(x1.z, x1.w);
    uint32_t l0 = bfpack(x0.x - bflo(h0), x0.y - bfhi(h0));
    uint32_t l1 = bfpack(x0.z - bflo(h1), x0.w - bfhi(h1));
    uint32_t l2 = bfpack(x1.x - bflo(h2), x1.y - bfhi(h2));
    uint32_t l3 = bfpack(x1.z - bflo(h3), x1.w - bfhi(h3));
    size_t o = (size_t)r * (cols8 * 8) + c8 * 8;
    *(uint4*)(Ah + o) = make_uint4(h0, h1, h2, h3);
    *(uint4*)(Al + o) = make_uint4(l0, l1, l2, l3);
}

// ================= HMMA bf16-split GEMM (pre-split A, optional split out) ==
#define ASTR   40
#define TILEB  (128*80)
#define OAH    0
#define OAL    (TILEB)
#define OBH    (2*TILEB)
#define OBL    (3*TILEB)
#define BUFSTR (4*TILEB)
#define DSMG   (2*BUFSTR)               // 81920

__global__ __launch_bounds__(256) void gemm_mma(
    int M, int N, int K,
    const __nv_bfloat16* __restrict__ Ah, const __nv_bfloat16* __restrict__ Al,
    const __nv_bfloat16* __restrict__ Bh, const __nv_bfloat16* __restrict__ Bl,
    const float* __restrict__ bias, float* __restrict__ C,
    __nv_bfloat16* __restrict__ Oh, __nv_bfloat16* __restrict__ Ol)
{
    extern __shared__ char smem[];
    const uint32_t sb = smem_to_u32(smem);
    const int tid = threadIdx.x, lane = tid & 31, wid = tid >> 5;
    const int brow = blockIdx.y * 128, bcol = blockIdx.x * 128;
    const int wm = wid & 1, wn = wid >> 1;

    const int lrow = tid >> 1, lhalf = tid & 1;
    const __nv_bfloat16* Ahp = Ah + (size_t)(brow + lrow) * K + lhalf * 16;
    const __nv_bfloat16* Alp = Al + (size_t)(brow + lrow) * K + lhalf * 16;
    const __nv_bfloat16* Bhp = Bh + (size_t)(bcol + lrow) * K + lhalf * 16;
    const __nv_bfloat16* Blp = Bl + (size_t)(bcol + lrow) * K + lhalf * 16;
    const uint32_t soff = (uint32_t)(lrow * ASTR + lhalf * 16) * 2;

    float acc[4][4][4];
#pragma unroll
    for (int i = 0; i < 4; i++)
#pragma unroll
        for (int j = 0; j < 4; j++)
#pragma unroll
            for (int e = 0; e < 4; e++) acc[i][j][e] = 0.f;

    uint4 pah[2], pal[2], pbh[2], pbl[2];

#define LOADG(k0) do { \
    pah[0] = *(const uint4*)(Ahp + (k0)); pah[1] = *(const uint4*)(Ahp + (k0) + 8); \
    pal[0] = *(const uint4*)(Alp + (k0)); pal[1] = *(const uint4*)(Alp + (k0) + 8); \
    pbh[0] = *(const uint4*)(Bhp + (k0)); pbh[1] = *(const uint4*)(Bhp + (k0) + 8); \
    pbl[0] = *(const uint4*)(Blp + (k0)); pbl[1] = *(const uint4*)(Blp + (k0) + 8); \
} while (0)

#define STOREBUF(b) do { \
    uint32_t base_ = sb + (uint32_t)(b) * BUFSTR; \
    STS128(base_ + OAH + soff,      pah[0].x, pah[0].y, pah[0].z, pah[0].w); \
    STS128(base_ + OAH + soff + 16, pah[1].x, pah[1].y, pah[1].z, pah[1].w); \
    STS128(base_ + OAL + soff,      pal[0].x, pal[0].y, pal[0].z, pal[0].w); \
    STS128(base_ + OAL + soff + 16, pal[1].x, pal[1].y, pal[1].z, pal[1].w); \
    STS128(base_ + OBH + soff,      pbh[0].x, pbh[0].y, pbh[0].z, pbh[0].w); \
    STS128(base_ + OBH + soff + 16, pbh[1].x, pbh[1].y, pbh[1].z, pbh[1].w); \
    STS128(base_ + OBL + soff,      pbl[0].x, pbl[0].y, pbl[0].z, pbl[0].w); \
    STS128(base_ + OBL + soff + 16, pbl[1].x, pbl[1].y, pbl[1].z, pbl[1].w); \
} while (0)

    const int nchunk = K / 32;
    LOADG(0);
    STOREBUF(0);
    __syncthreads();

    const uint32_t arow = (uint32_t)(wm * 64 + (lane & 15));
    const uint32_t acol = (uint32_t)((lane >> 4) * 8);
    const uint32_t brw  = (uint32_t)(wn * 32 + (lane & 7));
    const uint32_t bcl  = (uint32_t)(((lane >> 3) & 1) * 8);

    int buf = 0;
    for (int ck = 0; ck < nchunk; ck++) {
        if (ck + 1 < nchunk) LOADG((ck + 1) * 32);

        const uint32_t base = sb + (uint32_t)buf * BUFSTR;
#pragma unroll
        for (int ks = 0; ks < 2; ks++) {
            uint32_t ah[4][4], al[4][4];
#pragma unroll
            for (int mt = 0; mt < 4; mt++) {
                uint32_t aoff = ((arow + mt * 16) * ASTR + acol + ks * 16) * 2;
                LDSM_X4(ah[mt][0], ah[mt][1], ah[mt][2], ah[mt][3], base + OAH + aoff);
                LDSM_X4(al[mt][0], al[mt][1], al[mt][2], al[mt][3], base + OAL + aoff);
            }
#pragma unroll
            for (int nt = 0; nt < 4; nt++) {
                uint32_t boff = ((brw + nt * 8) * ASTR + bcl + ks * 16) * 2;
                uint32_t bh0, bh1, bl0, bl1;
                LDSM_X2(bh0, bh1, base + OBH + boff);
                LDSM_X2(bl0, bl1, base + OBL + boff);
#pragma unroll
                for (int mt = 0; mt < 4; mt++) {
                    MMA16816(acc[mt][nt], ah[mt][0], ah[mt][1], ah[mt][2], ah[mt][3], bh0, bh1);
                    MMA16816(acc[mt][nt], ah[mt][0], ah[mt][1], ah[mt][2], ah[mt][3], bl0, bl1);
                    MMA16816(acc[mt][nt], al[mt][0], al[mt][1], al[mt][2], al[mt][3], bh0, bh1);
                }
            }
        }
        if (ck + 1 < nchunk) STOREBUF(buf ^ 1);
        __syncthreads();
        buf ^= 1;
    }

#pragma unroll
    for (int mt = 0; mt < 4; mt++) {
        int r0 = brow + wm * 64 + mt * 16 + (lane >> 2);
#pragma unroll
        for (int nt = 0; nt < 4; nt++) {
            int c = bcol + wn * 32 + nt * 8 + (lane & 3) * 2;
            float bx = 0.f, by = 0.f;
            if (bias) { bx = bias[c]; by = bias[c + 1]; }
            float2 o0, o1;
            o0.x = acc[mt][nt][0] + bx; o0.y = acc[mt][nt][1] + by;
            o1.x = acc[mt][nt][2] + bx; o1.y = acc[mt][nt][3] + by;
            if (C) {
                *(float2*)(C + (size_t)r0 * N + c)       = o0;
                *(float2*)(C + (size_t)(r0 + 8) * N + c) = o1;
            }
            if (Oh) {
                uint32_t h0 = bfpack(o0.x, o0.y);
                uint32_t l0 = bfpack(o0.x - bflo(h0), o0.y - bfhi(h0));
                uint32_t h1 = bfpack(o1.x, o1.y);
                uint32_t l1 = bfpack(o1.x - bflo(h1), o1.y - bfhi(h1));
                *(uint32_t*)(Oh + (size_t)r0 * N + c)       = h0;
                *(uint32_t*)(Ol + (size_t)r0 * N + c)       = l0;
                *(uint32_t*)(Oh + (size_t)(r0 + 8) * N + c) = h1;
                *(uint32_t*)(Ol + (size_t)(r0 + 8) * N + c) = l1;
            }
        }
    }
#undef LOADG
#undef STOREBUF
}

// ================= fused flash attention (split HMMA, strided inputs) ======
#define QSTR   72
#define VSTR   72
#define PSTR   136
#define QKTILE (128*144)
#define FA_OQH 0
#define FA_OQL (QKTILE)
#define FA_OKH (2*QKTILE)
#define FA_OKL (3*QKTILE)
#define FA_OVH (4*QKTILE)
#define FA_OVL (5*QKTILE)
#define FA_OPH (6*QKTILE)
#define FA_OPL (FA_OPH + 128*272)
#define FA_M   (FA_OPL + 128*272)
#define FA_L   (FA_M + 512)
#define FA_R   (FA_L + 512)
#define FA_PMX (FA_R + 512)
#define FA_PSM (FA_PMX + 2048)
#define FA_TAB (FA_PSM + 2048)
#define DSMF   (FA_TAB + 1024)

__global__ __launch_bounds__(256) void flash_k(
    const float* __restrict__ Q, int ldq,
    const float* __restrict__ Kc, int ldk,
    const float* __restrict__ V, int ldv,
    float* __restrict__ O)
{
    extern __shared__ char smem[];
    const uint32_t sb = smem_to_u32(smem);
    float* mrow = (float*)(smem + FA_M);
    float* lrow = (float*)(smem + FA_L);
    float* rrow = (float*)(smem + FA_R);
    float* pmax = (float*)(smem + FA_PMX);
    float* psum = (float*)(smem + FA_PSM);
    float* tab  = (float*)(smem + FA_TAB);
    const int tid = threadIdx.x, lane = tid & 31, wid = tid >> 5;
    const int bh = blockIdx.y, b = bh >> 4, h = bh & 15;
    const int i0 = blockIdx.x * 128;
    const int wm = wid & 1, wn = wid >> 1;
    const int wmv = wid & 3, wnv = wid >> 2;

    const int lr2 = tid >> 1, ls2 = tid & 1;

    {
        const float* qp = Q + (size_t)(b * SEQ + i0 + lr2) * ldq + h * HDIM + ls2 * 32;
        const uint32_t off = (uint32_t)(lr2 * QSTR + ls2 * 32) * 2;
        uint32_t hh[16], ll[16];
#pragma unroll
        for (int i = 0; i < 8; i++) {
            float4 x = *(const float4*)(qp + i * 4);
            uint32_t h0 = bfpack(x.x, x.y), h1 = bfpack(x.z, x.w);
            hh[2*i] = h0; hh[2*i+1] = h1;
            ll[2*i]   = bfpack(x.x - bflo(h0), x.y - bfhi(h0));
            ll[2*i+1] = bfpack(x.z - bflo(h1), x.w - bfhi(h1));
        }
#pragma unroll
        for (int i = 0; i < 4; i++) {
            STS128(sb + FA_OQH + off + i * 16, hh[4*i], hh[4*i+1], hh[4*i+2], hh[4*i+3]);
            STS128(sb + FA_OQL + off + i * 16, ll[4*i], ll[4*i+1], ll[4*i+2], ll[4*i+3]);
        }
    }
    if (tid < 128) { mrow[tid] = -1e30f; lrow[tid] = 0.f; }

    float oacc[2][4][4];
#pragma unroll
    for (int i = 0; i < 2; i++)
#pragma unroll
        for (int j = 0; j < 4; j++)
#pragma unroll
            for (int e = 0; e < 4; e++) oacc[i][j][e] = 0.f;

    const float scale = 0.03125f;
    const uint32_t arow = (uint32_t)(wm * 64 + (lane & 15));
    const uint32_t acol = (uint32_t)((lane >> 4) * 8);
    const uint32_t brw  = (uint32_t)(wn * 32 + (lane & 7));
    const uint32_t bcl  = (uint32_t)(((lane >> 3) & 1) * 8);
    const uint32_t arv  = (uint32_t)(wmv * 32 + (lane & 15));
    const uint32_t klv  = (uint32_t)(lane & 15);
    const int lr4 = lane >> 2, lc4 = (lane & 3) * 2;

    for (int jt = 0; jt < 8; jt++) {
        const int j0 = jt * 128;
        __syncthreads();
        tab[tid] = __expf(-0.01f * fabsf((float)(i0 - j0 + tid - 128)));

        {
            const float* kp = Kc + (size_t)(b * SEQ + j0 + lr2) * ldk + h * HDIM + ls2 * 32;
            const float* vp = V  + (size_t)(b * SEQ + j0 + lr2) * ldv + h * HDIM + ls2 * 32;
            const uint32_t offk = (uint32_t)(lr2 * QSTR + ls2 * 32) * 2;
            const uint32_t offv = (uint32_t)(lr2 * VSTR + ls2 * 32) * 2;
            uint32_t hh[16], ll[16];
#pragma unroll
            for (int i = 0; i < 8; i++) {
                float4 x = *(const float4*)(kp + i * 4);
                uint32_t h0 = bfpack(x.x, x.y), h1 = bfpack(x.z, x.w);
                hh[2*i] = h0; hh[2*i+1] = h1;
                ll[2*i]   = bfpack(x.x - bflo(h0), x.y - bfhi(h0));
                ll[2*i+1] = bfpack(x.z - bflo(h1), x.w - bfhi(h1));
            }
#pragma unroll
            for (int i = 0; i < 4; i++) {
                STS128(sb + FA_OKH + offk + i * 16, hh[4*i], hh[4*i+1], hh[4*i+2], hh[4*i+3]);
                STS128(sb + FA_OKL + offk + i * 16, ll[4*i], ll[4*i+1], ll[4*i+2], ll[4*i+3]);
            }
#pragma unroll
            for (int i = 0; i < 8; i++) {
                float4 x = *(const float4*)(vp + i * 4);
                uint32_t h0 = bfpack(x.x, x.y), h1 = bfpack(x.z, x.w);
                hh[2*i] = h0; hh[2*i+1] = h1;
                ll[2*i]   = bfpack(x.x - bflo(h0), x.y - bfhi(h0));
                ll[2*i+1] = bfpack(x.z - bflo(h1), x.w - bfhi(h1));
            }
#pragma unroll
            for (int i = 0; i < 4; i++) {
                STS128(sb + FA_OVH + offv + i * 16, hh[4*i], hh[4*i+1], hh[4*i+2], hh[4*i+3]);
                STS128(sb + FA_OVL + offv + i * 16, ll[4*i], ll[4*i+1], ll[4*i+2], ll[4*i+3]);
            }
        }
        __syncthreads();

        float sacc[4][4][4];
#pragma unroll
        for (int i = 0; i < 4; i++)
#pragma unroll
            for (int j = 0; j < 4; j++)
#pragma unroll
                for (int e = 0; e < 4; e++) sacc[i][j][e] = 0.f;
#pragma unroll
        for (int ks = 0; ks < 4; ks++) {
            uint32_t ah[4][4], al[4][4];
#pragma unroll
            for (int mt = 0; mt < 4; mt++) {
                uint32_t aoff = ((arow + mt * 16) * QSTR + acol + ks * 16) * 2;
                LDSM_X4(ah[mt][0], ah[mt][1], ah[mt][2], ah[mt][3], sb + FA_OQH + aoff);
                LDSM_X4(al[mt][0], al[mt][1], al[mt][2], al[mt][3], sb + FA_OQL + aoff);
            }
#pragma unroll
            for (int nt = 0; nt < 4; nt++) {
                uint32_t boff = ((brw + nt * 8) * QSTR + bcl + ks * 16) * 2;
                uint32_t bh0, bh1, bl0, bl1;
                LDSM_X2(bh0, bh1, sb + FA_OKH + boff);
                LDSM_X2(bl0, bl1, sb + FA_OKL + boff);
#pragma unroll
                for (int mt = 0; mt < 4; mt++) {
                    MMA16816(sacc[mt][nt], ah[mt][0], ah[mt][1], ah[mt][2], ah[mt][3], bh0, bh1);
                    MMA16816(sacc[mt][nt], ah[mt][0], ah[mt][1], ah[mt][2], ah[mt][3], bl0, bl1);
                    MMA16816(sacc[mt][nt], al[mt][0], al[mt][1], al[mt][2], al[mt][3], bh0, bh1);
                }
            }
        }

#pragma unroll
        for (int mt = 0; mt < 4; mt++) {
            int ri = wm * 64 + mt * 16 + lr4;
            float mx0 = -1e30f, mx1 = -1e30f;
#pragma unroll
            for (int nt = 0; nt < 4; nt++) {
                int cj = wn * 32 + nt * 8 + lc4;
                int d0 = ri - cj + 128;
                sacc[mt][nt][0] *= scale * tab[d0];
                sacc[mt][nt][1] *= scale * tab[d0 - 1];
                sacc[mt][nt][2] *= scale * tab[d0 + 8];
                sacc[mt][nt][3] *= scale * tab[d0 + 7];
                mx0 = fmaxf(mx0, fmaxf(sacc[mt][nt][0], sacc[mt][nt][1]));
                mx1 = fmaxf(mx1, fmaxf(sacc[mt][nt][2], sacc[mt][nt][3]));
            }
            mx0 = fmaxf(mx0, __shfl_xor_sync(0xffffffffu, mx0, 1));
            mx0 = fmaxf(mx0, __shfl_xor_sync(0xffffffffu, mx0, 2));
            mx1 = fmaxf(mx1, __shfl_xor_sync(0xffffffffu, mx1, 1));
            mx1 = fmaxf(mx1, __shfl_xor_sync(0xffffffffu, mx1, 2));
            if ((lane & 3) == 0) {
                pmax[wn * 128 + ri] = mx0;
                pmax[wn * 128 + ri + 8] = mx1;
            }
        }
        __syncthreads();
        if (tid < 128) {
            float mo = mrow[tid];
            float mn = fmaxf(fmaxf(pmax[tid], pmax[128 + tid]),
                             fmaxf(pmax[256 + tid], pmax[384 + tid]));
            mn = fmaxf(mo, mn);
            rrow[tid] = __expf(mo - mn);
            mrow[tid] = mn;
        }
        __syncthreads();

#pragma unroll
        for (int mt = 0; mt < 4; mt++) {
            int row0 = wm * 64 + mt * 16 + lr4;
            int row1 = row0 + 8;
            float m0 = mrow[row0], m1 = mrow[row1];
            float s0 = 0.f, s1 = 0.f;
#pragma unroll
            for (int nt = 0; nt < 4; nt++) {
                int col = wn * 32 + nt * 8 + lc4;
                float p0 = __expf(sacc[mt][nt][0] - m0);
                float p1 = __expf(sacc[mt][nt][1] - m0);
                float p2 = __expf(sacc[mt][nt][2] - m1);
                float p3 = __expf(sacc[mt][nt][3] - m1);
                s0 += p0 + p1; s1 += p2 + p3;
                uint32_t ph0 = bfpack(p0, p1);
                uint32_t pl0 = bfpack(p0 - bflo(ph0), p1 - bfhi(ph0));
                uint32_t ph1 = bfpack(p2, p3);
                uint32_t pl1 = bfpack(p2 - bflo(ph1), p3 - bfhi(ph1));
                uint32_t a0 = (uint32_t)(row0 * PSTR + col) * 2;
                uint32_t a1 = (uint32_t)(row1 * PSTR + col) * 2;
                STS32(sb + FA_OPH + a0, ph0);
                STS32(sb + FA_OPL + a0, pl0);
                STS32(sb + FA_OPH + a1, ph1);
                STS32(sb + FA_OPL + a1, pl1);
            }
            s0 += __shfl_xor_sync(0xffffffffu, s0, 1);
            s0 += __shfl_xor_sync(0xffffffffu, s0, 2);
            s1 += __shfl_xor_sync(0xffffffffu, s1, 1);
            s1 += __shfl_xor_sync(0xffffffffu, s1, 2);
            if ((lane & 3) == 0) {
                psum[wn * 128 + row0] = s0;
                psum[wn * 128 + row1] = s1;
            }
        }
        __syncthreads();
        if (tid < 128)
            lrow[tid] = lrow[tid] * rrow[tid]
                      + psum[tid] + psum[128 + tid] + psum[256 + tid] + psum[384 + tid];

#pragma unroll
        for (int mt = 0; mt < 2; mt++) {
            int r0 = wmv * 32 + mt * 16 + lr4;
            float f0 = rrow[r0], f1 = rrow[r0 + 8];
#pragma unroll
            for (int nt = 0; nt < 4; nt++) {
                oacc[mt][nt][0] *= f0; oacc[mt][nt][1] *= f0;
                oacc[mt][nt][2] *= f1; oacc[mt][nt][3] *= f1;
            }
        }
#pragma unroll
        for (int ks = 0; ks < 8; ks++) {
            uint32_t ah[2][4], al[2][4];
#pragma unroll
            for (int mt = 0; mt < 2; mt++) {
                uint32_t aoff = ((arv + mt * 16) * PSTR + (uint32_t)((lane >> 4) * 8) + ks * 16) * 2;
                LDSM_X4(ah[mt][0], ah[mt][1], ah[mt][2], ah[mt][3], sb + FA_OPH + aoff);
                LDSM_X4(al[mt][0], al[mt][1], al[mt][2], al[mt][3], sb + FA_OPL + aoff);
            }
#pragma unroll
            for (int nt = 0; nt < 4; nt++) {
                uint32_t boff = ((ks * 16 + klv) * VSTR + wnv * 32 + nt * 8) * 2;
                uint32_t bh0, bh1, bl0, bl1;
                LDSM_X2T(bh0, bh1, sb + FA_OVH + boff);
                LDSM_X2T(bl0, bl1, sb + FA_OVL + boff);
#pragma unroll
                for (int mt = 0; mt < 2; mt++) {
                    MMA16816(oacc[mt][nt], ah[mt][0], ah[mt][1], ah[mt][2], ah[mt][3], bh0, bh1);
                    MMA16816(oacc[mt][nt], ah[mt][0], ah[mt][1], ah[mt][2], ah[mt][3], bl0, bl1);
                    MMA16816(oacc[mt][nt], al[mt][0], al[mt][1], al[mt][2], al[mt][3], bh0, bh1);
                }
            }
        }
    }

    __syncthreads();
#pragma unroll
    for (int mt = 0; mt < 2; mt++) {
        int r0 = wmv * 32 + mt * 16 + lr4;
        float inv0 = 1.0f / lrow[r0];
        float inv1 = 1.0f / lrow[r0 + 8];
#pragma unroll
        for (int nt = 0; nt < 4; nt++) {
            int c = h * HDIM + wnv * 32 + nt * 8 + lc4;
            float2 o0, o1;
            o0.x = oacc[mt][nt][0] * inv0; o0.y = oacc[mt][nt][1] * inv0;
            o1.x = oacc[mt][nt][2] * inv1; o1.y = oacc[mt][nt][3] * inv1;
            *(float2*)(O + (size_t)(b * SEQ + i0 + r0) * DM + c)     = o0;
            *(float2*)(O + (size_t)(b * SEQ + i0 + r0 + 8) * DM + c) = o1;
        }
    }
}

// ---------------- FFMA2 SGEMM (kept for the K=50 embedding GEMM) -----------
__global__ __launch_bounds__(256) void sgemm2_k(
    int M, int N, int K,
    const float* __restrict__ A, const float* __restrict__ B,
    const float* __restrict__ bias, float* __restrict__ C)
{
    __shared__ __align__(16) float As[KT][128];
    __shared__ __align__(16) float Bs[KT][128];
    const int tid  = threadIdx.x;
    const int brow = blockIdx.y * 128;
    const int bcol = blockIdx.x * 128;
    const int ty = tid >> 4, tx = tid & 15;
    const int ar = tid >> 1, aks = (tid & 1) * 8;

    unsigned long long acc[8][4];
#pragma unroll
    for (int i = 0; i < 8; i++)
#pragma unroll
        for (int j = 0; j < 4; j++) acc[i][j] = 0ULL;

    for (int k0 = 0; k0 < K; k0 += KT) {
#pragma unroll
        for (int i = 0; i < 8; i++) {
            int kk = aks + i;
            As[kk][ar] = (k0 + kk < K) ? A[(size_t)(brow + ar) * K + k0 + kk] : 0.f;
        }
#pragma unroll
        for (int p = 0; p < 2; p++) {
            int id = p * 256 + tid;
            int kk = id >> 5, c4 = (id & 31) * 4;
            float4 bv = make_float4(0.f, 0.f, 0.f, 0.f);
            if (k0 + kk < K) bv = *(const float4*)(B + (size_t)(k0 + kk) * N + bcol + c4);
            *(float4*)&Bs[kk][c4] = bv;
        }
        __syncthreads();
#pragma unroll
        for (int kk = 0; kk < KT; kk++) {
            float4 a0 = *(const float4*)&As[kk][ty * 4];
            float4 a1 = *(const float4*)&As[kk][64 + ty * 4];
            float4 b0 = *(const float4*)&Bs[kk][tx * 4];
            float4 b1 = *(const float4*)&Bs[kk][64 + tx * 4];
            unsigned long long rb[4] = { pk2(b0.x, b0.y), pk2(b0.z, b0.w),
                                         pk2(b1.x, b1.y), pk2(b1.z, b1.w) };
            float ra[8] = { a0.x, a0.y, a0.z, a0.w, a1.x, a1.y, a1.z, a1.w };
#pragma unroll
            for (int i = 0; i < 8; i++) {
                unsigned long long ad = pk2(ra[i], ra[i]);
#pragma unroll
                for (int j = 0; j < 4; j++) acc[i][j] = ffma2(ad, rb[j], acc[i][j]);
            }
        }
        __syncthreads();
    }
#pragma unroll
    for (int ih = 0; ih < 2; ih++)
#pragma unroll
    for (int ii = 0; ii < 4; ii++) {
        int i = ih * 4 + ii;
        int r = brow + ih * 64 + ty * 4 + ii;
#pragma unroll
        for (int jh = 0; jh < 2; jh++) {
            int c = bcol + jh * 64 + tx * 4;
            float2 p0 = up2(acc[i][jh * 2]);
            float2 p1 = up2(acc[i][jh * 2 + 1]);
            float4 o; o.x = p0.x; o.y = p0.y; o.z = p1.x; o.w = p1.y;
            if (bias) { o.x += bias[c]; o.y += bias[c+1]; o.z += bias[c+2]; o.w += bias[c+3]; }
            *(float4*)(C + (size_t)r * N + c) = o;
        }
    }
}

// ---------------- Fourier token features -----------------------------------
__global__ void fourier_k(const int* __restrict__ src, const float* __restrict__ a_n,
                          const float* __restrict__ b_n, float* __restrict__ F)
{
    int idx = blockIdx.x * blockDim.x + threadIdx.x;
    if (idx >= ROWS * NFR) return;
    int bs = idx / NFR, n = idx % NFR;
    int tok = src[bs];
    float x   = (float)tok * (1.0f / (float)VOC);
    float ang = 6.28318530717958647692f * (float)(n + 1) * x;
    F[idx] = a_n[tok * NFR + n] * cosf(ang) + b_n[tok * NFR + n] * sinf(ang);
}

// ---------------- h += sinusoidal PE ---------------------------------------
__global__ void addpe_k(float* __restrict__ h)
{
    int idx = blockIdx.x * blockDim.x + threadIdx.x;
    if (idx >= ROWS * DM) return;
    int d = idx & (DM - 1);
    int s = (idx / DM) & (SEQ - 1);
    float div = expf(-(float)(d & ~1) * 8.99447301948846e-3f);
    float ang = (float)s * div;
    h[idx] += (d & 1) ? cosf(ang) : sinf(ang);
}

// ---------------------------------------------------------------------------
extern "C" void kernel_launch(void* const* d_in, const int* in_sizes, int n_in,
                              void* d_out, int out_size)
{
    const int*   src    = (const int*)  d_in[0];
    const float* a_n    = (const float*)d_in[2];
    const float* b_n    = (const float*)d_in[3];
    const float* proj_w = (const float*)d_in[4];
    const float* proj_b = (const float*)d_in[5];
    const float* rule   = (const float*)d_in[6];
    const float* Wq     = (const float*)d_in[7];
    const float* Wk     = (const float*)d_in[8];
    const float* Wv     = (const float*)d_in[9];
    const float* Wo     = (const float*)d_in[10];
    const float* Wdown  = (const float*)d_in[11];
    const float* Wup_k  = (const float*)d_in[12];
    const float* Wup_v  = (const float*)d_in[13];
    const float* Wout   = (const float*)d_in[14];
    const float* bout   = (const float*)d_in[15];
    float* out = (float*)d_out;

    float *h, *t, *kv, *qkv, *krvr, *four;
    __nv_bfloat16 *wbh, *wbl, *ah, *al, *hh, *hl, *lh, *ll;
    cudaGetSymbolAddress((void**)&h,    g_h);
    cudaGetSymbolAddress((void**)&t,    g_t);
    cudaGetSymbolAddress((void**)&kv,   g_kv);
    cudaGetSymbolAddress((void**)&qkv,  g_qkv);
    cudaGetSymbolAddress((void**)&krvr, g_krvr);
    cudaGetSymbolAddress((void**)&four, g_four);
    cudaGetSymbolAddress((void**)&wbh,  g_wbh);
    cudaGetSymbolAddress((void**)&wbl,  g_wbl);
    cudaGetSymbolAddress((void**)&ah,   g_ah);
    cudaGetSymbolAddress((void**)&al,   g_al);
    cudaGetSymbolAddress((void**)&hh,   g_hh);
    cudaGetSymbolAddress((void**)&hl,   g_hl);
    cudaGetSymbolAddress((void**)&lh,   g_lh);
    cudaGetSymbolAddress((void**)&ll,   g_ll);

    cudaFuncSetAttribute(gemm_mma, cudaFuncAttributeMaxDynamicSharedMemorySize, DSMG);
    cudaFuncSetAttribute(flash_k,  cudaFuncAttributeMaxDynamicSharedMemorySize, DSMF);

    // ---- transpose + split all weights into [N,K] bf16 hi/lo ----
    {
        const dim3 b(32, 8);
        wsplit_k<<<dim3(DM/32, DM/32), b>>>(rule, DM, DM, wbh + OFF_RULE, wbl + OFF_RULE);
        for (int l = 0; l < NL; l++) {
            size_t o = OFF_L(l);
            wsplit_k<<<dim3(DM/32, DM/32), b>>>(Wq + (size_t)l*DM*DM, DM, DM, wbh+o, wbl+o);
            wsplit_k<<<dim3(DM/32, DM/32), b>>>(Wk + (size_t)l*DM*DM, DM, DM, wbh+o+WSZ_DD, wbl+o+WSZ_DD);
            wsplit_k<<<dim3(DM/32, DM/32), b>>>(Wv + (size_t)l*DM*DM, DM, DM, wbh+o+2*WSZ_DD, wbl+o+2*WSZ_DD);
            wsplit_k<<<dim3(DM/32, DM/32), b>>>(Wo + (size_t)l*DM*DM, DM, DM, wbh+o+3*WSZ_DD, wbl+o+3*WSZ_DD);
            wsplit_k<<<dim3(DLAT/32, DM/32), b>>>(Wdown + (size_t)l*DM*DLAT, DM, DLAT,
                                                  wbh+o+4*WSZ_DD, wbl+o+4*WSZ_DD);
            wsplit_k<<<dim3(DM/32, DLAT/32), b>>>(Wup_k + (size_t)l*DLAT*DM, DLAT, DM,
                                                  wbh+o+4*WSZ_DD+WSZ_HALF, wbl+o+4*WSZ_DD+WSZ_HALF);
            wsplit_k<<<dim3(DM/32, DLAT/32), b>>>(Wup_v + (size_t)l*DLAT*DM, DLAT, DM,
                                                  wbh+o+4*WSZ_DD+2*WSZ_HALF, wbl+o+4*WSZ_DD+2*WSZ_HALF);
        }
        wsplit_k<<<dim3(VOC/32, DM/32), b>>>(Wout, DM, VOC, wbh + OFF_WOUT, wbl + OFF_WOUT);
    }

    const dim3 g_qkv3(3*DM/128, ROWS/128);   // 384 CTAs
    const dim3 g_up  (2*DM/128, ROWS/128);   // 256 CTAs
    const dim3 g_d   (DM  /128, ROWS/128);   // 128 CTAs
    const dim3 g_dl  (DLAT/128, ROWS/128);   //  64 CTAs
    const dim3 g_voc (VOC /128, ROWS/128);   // 4000 CTAs
    const int N8_DD = ROWS * (DM/8);

    // ---- embedding ----
    fourier_k<<<(ROWS * NFR + 255) / 256, 256>>>(src, a_n, b_n, four);
    sgemm2_k<<<g_d, 256>>>(ROWS, DM, NFR, four, proj_w, proj_b, t);
    asplit_k<<<(N8_DD + 255)/256, 256>>>(t, nullptr, ROWS, DM/8, DM, ah, al);
    gemm_mma<<<g_d, 256, DSMG>>>(ROWS, DM, DM, ah, al, wbh + OFF_RULE, wbl + OFF_RULE,
                                 nullptr, h, nullptr, nullptr);
    addpe_k<<<(ROWS * DM + 255) / 256, 256>>>(h);
    asplit_k<<<(N8_DD + 255)/256, 256>>>(h, nullptr, ROWS, DM/8, DM, hh, hl);

    // ---- layers ----
    for (int l = 0; l < NL; l++) {
        size_t o = OFF_L(l);
        const __nv_bfloat16 *qkh= wbh+o,                   *qkl= wbl+o;              // q|k|v rows 0..3071
        const __nv_bfloat16 *dh = wbh+o+4*WSZ_DD,          *dl = wbl+o+4*WSZ_DD;
        const __nv_bfloat16 *uh = wbh+o+4*WSZ_DD+WSZ_HALF, *ul = wbl+o+4*WSZ_DD+WSZ_HALF;  // up_k|up_v rows 0..2047
        const __nv_bfloat16 *oh = wbh+o+3*WSZ_DD,          *ol = wbl+o+3*WSZ_DD;

        // fused QKV -> qkv [ROWS, 3*DM]
        gemm_mma<<<g_qkv3, 256, DSMG>>>(ROWS, 3*DM, DM, hh, hl, qkh, qkl,
                                        nullptr, qkv, nullptr, nullptr);
        // k+v split (strided views into qkv)
        asplit_k<<<(N8_DD + 255)/256, 256>>>(qkv + DM, qkv + 2*DM, ROWS, DM/8, 3*DM, ah, al);
        // down -> lat split-only
        gemm_mma<<<g_dl, 256, DSMG>>>(ROWS, DLAT, DM, ah, al, dh, dl,
                                      nullptr, nullptr, lh, ll);
        // fused up -> krvr [ROWS, 2*DM]
        gemm_mma<<<g_up, 256, DSMG>>>(ROWS, 2*DM, DLAT, lh, ll, uh, ul,
                                      nullptr, krvr, nullptr, nullptr);

        flash_k<<<dim3(SEQ/128, BSZ*NH), 256, DSMF>>>(qkv, 3*DM, krvr, 2*DM,
                                                      krvr + DM, 2*DM, kv);

        asplit_k<<<(N8_DD + 255)/256, 256>>>(kv, nullptr, ROWS, DM/8, DM, ah, al);
        // Wo -> h split-only (feeds next layer / vocab)
        gemm_mma<<<g_d, 256, DSMG>>>(ROWS, DM, DM, ah, al, oh, ol,
                                     nullptr, nullptr, hh, hl);
    }

    // ---- vocab projection ----
    gemm_mma<<<g_voc, 256, DSMG>>>(ROWS, VOC, DM, hh, hl, wbh + OFF_WOUT, wbl + OFF_WOUT,
                                   bout, out, nullptr, nullptr);
}

// round 16
// speedup vs baseline: 1.1872x; 1.0181x over previous
#include <cuda_runtime.h>
#include <cuda_bf16.h>
#include <math.h>
#include <stdint.h>

#define BSZ  2
#define SEQ  1024
#define DM   1024
#define NH   16
#define HDIM 64
#define NL   4
#define VOC  32000
#define NFR  50
#define DLAT 512
#define ROWS (BSZ*SEQ)   // 2048
#define KT   16

// ---------------- scratch (device globals; no allocation allowed) ----------
__device__ float g_h  [ROWS*DM];
__device__ float g_t  [ROWS*DM];
__device__ float g_kv [ROWS*DM];
__device__ float g_qkv [ROWS*3*DM];
__device__ float g_krvr[ROWS*2*DM];
__device__ float g_four[ROWS*NFR];
__device__ __align__(16) __nv_bfloat16 g_ah[ROWS*DM];
__device__ __align__(16) __nv_bfloat16 g_al[ROWS*DM];
__device__ __align__(16) __nv_bfloat16 g_hh[ROWS*DM];
__device__ __align__(16) __nv_bfloat16 g_hl[ROWS*DM];
__device__ __align__(16) __nv_bfloat16 g_lh[ROWS*DLAT];
__device__ __align__(16) __nv_bfloat16 g_ll[ROWS*DLAT];

// transposed + split weights: [N][K] bf16, hi and lo halves
#define WSZ_DD   (1024*1024)
#define WSZ_HALF (512*1024)
#define LSTRIDE  (4*WSZ_DD + 3*WSZ_HALF)
#define OFF_RULE 0
#define OFF_L(l) ((size_t)WSZ_DD + (size_t)(l)*LSTRIDE)
#define OFF_WOUT ((size_t)WSZ_DD + 4*(size_t)LSTRIDE)
#define WTOT     (OFF_WOUT + (size_t)VOC*DM)
__device__ __align__(16) __nv_bfloat16 g_wbh[WTOT];
__device__ __align__(16) __nv_bfloat16 g_wbl[WTOT];

// ---------------- f32x2 packed helpers -------------------------------------
__device__ __forceinline__ unsigned long long pk2(float lo, float hi) {
    unsigned long long r;
    asm("mov.b64 %0, {%1, %2};" : "=l"(r) : "f"(lo), "f"(hi));
    return r;
}
__device__ __forceinline__ unsigned long long ffma2(
    unsigned long long a, unsigned long long b, unsigned long long c) {
    unsigned long long d;
    asm("fma.rn.f32x2 %0, %1, %2, %3;" : "=l"(d) : "l"(a), "l"(b), "l"(c));
    return d;
}
__device__ __forceinline__ float2 up2(unsigned long long v) {
    float2 f;
    asm("mov.b64 {%0, %1}, %2;" : "=f"(f.x), "=f"(f.y) : "l"(v));
    return f;
}

// ---------------- misc helpers ---------------------------------------------
__device__ __forceinline__ uint32_t smem_to_u32(const void* p) {
    uint32_t a;
    asm("{ .reg .u64 t; cvta.to.shared.u64 t, %1; cvt.u32.u64 %0, t; }" : "=r"(a) : "l"(p));
    return a;
}
__device__ __forceinline__ uint32_t bfpack(float lo, float hi) {
    uint32_t r;
    asm("cvt.rn.bf16x2.f32 %0, %1, %2;" : "=r"(r) : "f"(hi), "f"(lo));
    return r;
}
__device__ __forceinline__ float bflo(uint32_t p) { return __uint_as_float(p << 16); }
__device__ __forceinline__ float bfhi(uint32_t p) { return __uint_as_float(p & 0xffff0000u); }
#define STS128(addr, a, b, c, d) \
    asm volatile("st.shared.v4.b32 [%0], {%1, %2, %3, %4};" \
        :: "r"(addr), "r"(a), "r"(b), "r"(c), "r"(d) : "memory")
#define STS32(addr, v) \
    asm volatile("st.shared.b32 [%0], %1;" :: "r"(addr), "r"(v) : "memory")
#define LDSM_X4(r0, r1, r2, r3, addr) \
    asm volatile("ldmatrix.sync.aligned.m8n8.x4.shared.b16 {%0,%1,%2,%3}, [%4];" \
        : "=r"(r0), "=r"(r1), "=r"(r2), "=r"(r3) : "r"(addr))
#define LDSM_X2(r0, r1, addr) \
    asm volatile("ldmatrix.sync.aligned.m8n8.x2.shared.b16 {%0,%1}, [%2];" \
        : "=r"(r0), "=r"(r1) : "r"(addr))
#define LDSM_X2T(r0, r1, addr) \
    asm volatile("ldmatrix.sync.aligned.m8n8.x2.trans.shared.b16 {%0,%1}, [%2];" \
        : "=r"(r0), "=r"(r1) : "r"(addr))
#define MMA16816(d, a0, a1, a2, a3, b0, b1) \
    asm volatile("mma.sync.aligned.m16n8k16.row.col.f32.bf16.bf16.f32 " \
        "{%0,%1,%2,%3}, {%4,%5,%6,%7}, {%8,%9}, {%0,%1,%2,%3};" \
        : "+f"((d)[0]), "+f"((d)[1]), "+f"((d)[2]), "+f"((d)[3]) \
        : "r"(a0), "r"(a1), "r"(a2), "r"(a3), "r"(b0), "r"(b1))

// ===== weight transpose + bf16 split: 64x64 tiles, layer-batched ===========
__global__ __launch_bounds__(256) void wsplit_k(
    const float* __restrict__ W, int K, int N,
    size_t inStrideZ, size_t outStrideZ,
    __nv_bfloat16* __restrict__ Th, __nv_bfloat16* __restrict__ Tl)
{
    __shared__ float t[64][65];
    const int k0 = blockIdx.y * 64, n0 = blockIdx.x * 64;
    const int tid = threadIdx.x;
    const float* Wz = W + (size_t)blockIdx.z * inStrideZ;
    __nv_bfloat16* Thz = Th + (size_t)blockIdx.z * outStrideZ;
    __nv_bfloat16* Tlz = Tl + (size_t)blockIdx.z * outStrideZ;

    const int lr = tid >> 4, lc = (tid & 15) * 4;
#pragma unroll
    for (int p = 0; p < 4; p++) {
        int k = lr + p * 16;
        float4 x = *(const float4*)(Wz + (size_t)(k0 + k) * N + n0 + lc);
        t[k][lc] = x.x; t[k][lc + 1] = x.y; t[k][lc + 2] = x.z; t[k][lc + 3] = x.w;
    }
    __syncthreads();

    const int n = tid >> 2;
    const int kgb = tid & 3;
#pragma unroll
    for (int i = 0; i < 2; i++) {
        int kg = kgb + 4 * i;
        uint32_t h[4], l[4];
#pragma unroll
        for (int j = 0; j < 4; j++) {
            float x0 = t[kg * 8 + 2 * j][n];
            float x1 = t[kg * 8 + 2 * j + 1][n];
            uint32_t hp = bfpack(x0, x1);
            uint32_t lp = bfpack(x0 - bflo(hp), x1 - bfhi(hp));
            h[j] = hp; l[j] = lp;
        }
        size_t o = (size_t)(n0 + n) * K + k0 + kg * 8;
        *(uint4*)(Thz + o) = make_uint4(h[0], h[1], h[2], h[3]);
        *(uint4*)(Tlz + o) = make_uint4(l[0], l[1], l[2], l[3]);
    }
}

// ===== activation split: A (+A2) fp32 (strided) -> bf16 hi/lo ==============
__global__ __launch_bounds__(256) void asplit_k(
    const float* __restrict__ A, const float* __restrict__ A2,
    int rows, int cols8, int lda,
    __nv_bfloat16* __restrict__ Ah, __nv_bfloat16* __restrict__ Al)
{
    int idx = blockIdx.x * 256 + threadIdx.x;
    if (idx >= rows * cols8) return;
    int r = idx / cols8, c8 = idx - r * cols8;
    const float* base = A + (size_t)r * lda + c8 * 8;
    float4 x0 = *(const float4*)base, x1 = *(const float4*)(base + 4);
    if (A2) {
        const float* b2 = A2 + (size_t)r * lda + c8 * 8;
        float4 y0 = *(const float4*)b2, y1 = *(const float4*)(b2 + 4);
        x0.x += y0.x; x0.y += y0.y; x0.z += y0.z; x0.w += y0.w;
        x1.x += y1.x; x1.y += y1.y; x1.z += y1.z; x1.w += y1.w;
    }
    uint32_t h0 = bfpack(x0.x, x0.y), h1 = bfpack(x0.z, x0.w);
    uint32_t h2 = bfpack(x1.x, x1.y), h3 = bfpack(x1.z, x1.w);
    uint32_t l0 = bfpack(x0.x - bflo(h0), x0.y - bfhi(h0));
    uint32_t l1 = bfpack(x0.z - bflo(h1), x0.w - bfhi(h1));
    uint32_t l2 = bfpack(x1.x - bflo(h2), x1.y - bfhi(h2));
    uint32_t l3 = bfpack(x1.z - bflo(h3), x1.w - bfhi(h3));
    size_t o = (size_t)r * (cols8 * 8) + c8 * 8;
    *(uint4*)(Ah + o) = make_uint4(h0, h1, h2, h3);
    *(uint4*)(Al + o) = make_uint4(l0, l1, l2, l3);
}

// ================= HMMA bf16-split GEMM (pre-split A, optional split out) ==
#define ASTR   40
#define TILEB  (128*80)
#define OAH    0
#define OAL    (TILEB)
#define OBH    (2*TILEB)
#define OBL    (3*TILEB)
#define BUFSTR (4*TILEB)
#define DSMG   (2*BUFSTR)               // 81920

__global__ __launch_bounds__(256) void gemm_mma(
    int M, int N, int K,
    const __nv_bfloat16* __restrict__ Ah, const __nv_bfloat16* __restrict__ Al,
    const __nv_bfloat16* __restrict__ Bh, const __nv_bfloat16* __restrict__ Bl,
    const float* __restrict__ bias, float* __restrict__ C,
    __nv_bfloat16* __restrict__ Oh, __nv_bfloat16* __restrict__ Ol)
{
    extern __shared__ char smem[];
    const uint32_t sb = smem_to_u32(smem);
    const int tid = threadIdx.x, lane = tid & 31, wid = tid >> 5;
    const int brow = blockIdx.y * 128, bcol = blockIdx.x * 128;
    const int wm = wid & 1, wn = wid >> 1;

    const int lrow = tid >> 1, lhalf = tid & 1;
    const __nv_bfloat16* Ahp = Ah + (size_t)(brow + lrow) * K + lhalf * 16;
    const __nv_bfloat16* Alp = Al + (size_t)(brow + lrow) * K + lhalf * 16;
    const __nv_bfloat16* Bhp = Bh + (size_t)(bcol + lrow) * K + lhalf * 16;
    const __nv_bfloat16* Blp = Bl + (size_t)(bcol + lrow) * K + lhalf * 16;
    const uint32_t soff = (uint32_t)(lrow * ASTR + lhalf * 16) * 2;

    float acc[4][4][4];
#pragma unroll
    for (int i = 0; i < 4; i++)
#pragma unroll
        for (int j = 0; j < 4; j++)
#pragma unroll
            for (int e = 0; e < 4; e++) acc[i][j][e] = 0.f;

    uint4 pah[2], pal[2], pbh[2], pbl[2];

#define LOADG(k0) do { \
    pah[0] = *(const uint4*)(Ahp + (k0)); pah[1] = *(const uint4*)(Ahp + (k0) + 8); \
    pal[0] = *(const uint4*)(Alp + (k0)); pal[1] = *(const uint4*)(Alp + (k0) + 8); \
    pbh[0] = *(const uint4*)(Bhp + (k0)); pbh[1] = *(const uint4*)(Bhp + (k0) + 8); \
    pbl[0] = *(const uint4*)(Blp + (k0)); pbl[1] = *(const uint4*)(Blp + (k0) + 8); \
} while (0)

#define STOREBUF(b) do { \
    uint32_t base_ = sb + (uint32_t)(b) * BUFSTR; \
    STS128(base_ + OAH + soff,      pah[0].x, pah[0].y, pah[0].z, pah[0].w); \
    STS128(base_ + OAH + soff + 16, pah[1].x, pah[1].y, pah[1].z, pah[1].w); \
    STS128(base_ + OAL + soff,      pal[0].x, pal[0].y, pal[0].z, pal[0].w); \
    STS128(base_ + OAL + soff + 16, pal[1].x, pal[1].y, pal[1].z, pal[1].w); \
    STS128(base_ + OBH + soff,      pbh[0].x, pbh[0].y, pbh[0].z, pbh[0].w); \
    STS128(base_ + OBH + soff + 16, pbh[1].x, pbh[1].y, pbh[1].z, pbh[1].w); \
    STS128(base_ + OBL + soff,      pbl[0].x, pbl[0].y, pbl[0].z, pbl[0].w); \
    STS128(base_ + OBL + soff + 16, pbl[1].x, pbl[1].y, pbl[1].z, pbl[1].w); \
} while (0)

    const int nchunk = K / 32;
    LOADG(0);
    STOREBUF(0);
    __syncthreads();

    const uint32_t arow = (uint32_t)(wm * 64 + (lane & 15));
    const uint32_t acol = (uint32_t)((lane >> 4) * 8);
    const uint32_t brw  = (uint32_t)(wn * 32 + (lane & 7));
    const uint32_t bcl  = (uint32_t)(((lane >> 3) & 1) * 8);

    int buf = 0;
    for (int ck = 0; ck < nchunk; ck++) {
        if (ck + 1 < nchunk) LOADG((ck + 1) * 32);

        const uint32_t base = sb + (uint32_t)buf * BUFSTR;
#pragma unroll
        for (int ks = 0; ks < 2; ks++) {
            uint32_t ah[4][4], al[4][4];
#pragma unroll
            for (int mt = 0; mt < 4; mt++) {
                uint32_t aoff = ((arow + mt * 16) * ASTR + acol + ks * 16) * 2;
                LDSM_X4(ah[mt][0], ah[mt][1], ah[mt][2], ah[mt][3], base + OAH + aoff);
                LDSM_X4(al[mt][0], al[mt][1], al[mt][2], al[mt][3], base + OAL + aoff);
            }
#pragma unroll
            for (int nt = 0; nt < 4; nt++) {
                uint32_t boff = ((brw + nt * 8) * ASTR + bcl + ks * 16) * 2;
                uint32_t bh0, bh1, bl0, bl1;
                LDSM_X2(bh0, bh1, base + OBH + boff);
                LDSM_X2(bl0, bl1, base + OBL + boff);
#pragma unroll
                for (int mt = 0; mt < 4; mt++) {
                    MMA16816(acc[mt][nt], ah[mt][0], ah[mt][1], ah[mt][2], ah[mt][3], bh0, bh1);
                    MMA16816(acc[mt][nt], ah[mt][0], ah[mt][1], ah[mt][2], ah[mt][3], bl0, bl1);
                    MMA16816(acc[mt][nt], al[mt][0], al[mt][1], al[mt][2], al[mt][3], bh0, bh1);
                }
            }
        }
        if (ck + 1 < nchunk) STOREBUF(buf ^ 1);
        __syncthreads();
        buf ^= 1;
    }

#pragma unroll
    for (int mt = 0; mt < 4; mt++) {
        int r0 = brow + wm * 64 + mt * 16 + (lane >> 2);
#pragma unroll
        for (int nt = 0; nt < 4; nt++) {
            int c = bcol + wn * 32 + nt * 8 + (lane & 3) * 2;
            float bx = 0.f, by = 0.f;
            if (bias) { bx = bias[c]; by = bias[c + 1]; }
            float2 o0, o1;
            o0.x = acc[mt][nt][0] + bx; o0.y = acc[mt][nt][1] + by;
            o1.x = acc[mt][nt][2] + bx; o1.y = acc[mt][nt][3] + by;
            if (C) {
                *(float2*)(C + (size_t)r0 * N + c)       = o0;
                *(float2*)(C + (size_t)(r0 + 8) * N + c) = o1;
            }
            if (Oh) {
                uint32_t h0 = bfpack(o0.x, o0.y);
                uint32_t l0 = bfpack(o0.x - bflo(h0), o0.y - bfhi(h0));
                uint32_t h1 = bfpack(o1.x, o1.y);
                uint32_t l1 = bfpack(o1.x - bflo(h1), o1.y - bfhi(h1));
                *(uint32_t*)(Oh + (size_t)r0 * N + c)       = h0;
                *(uint32_t*)(Ol + (size_t)r0 * N + c)       = l0;
                *(uint32_t*)(Oh + (size_t)(r0 + 8) * N + c) = h1;
                *(uint32_t*)(Ol + (size_t)(r0 + 8) * N + c) = l1;
            }
        }
    }
#undef LOADG
#undef STOREBUF
}

// ================= fused flash attention (split HMMA, strided inputs) ======
#define QSTR   72
#define VSTR   72
#define PSTR   136
#define QKTILE (128*144)
#define FA_OQH 0
#define FA_OQL (QKTILE)
#define FA_OKH (2*QKTILE)
#define FA_OKL (3*QKTILE)
#define FA_OVH (4*QKTILE)
#define FA_OVL (5*QKTILE)
#define FA_OPH (6*QKTILE)
#define FA_OPL (FA_OPH + 128*272)
#define FA_M   (FA_OPL + 128*272)
#define FA_L   (FA_M + 512)
#define FA_R   (FA_L + 512)
#define FA_PMX (FA_R + 512)
#define FA_PSM (FA_PMX + 2048)
#define FA_TAB (FA_PSM + 2048)
#define DSMF   (FA_TAB + 1024)

__global__ __launch_bounds__(256) void flash_k(
    const float* __restrict__ Q, int ldq,
    const float* __restrict__ Kc, int ldk,
    const float* __restrict__ V, int ldv,
    float* __restrict__ O)
{
    extern __shared__ char smem[];
    const uint32_t sb = smem_to_u32(smem);
    float* mrow = (float*)(smem + FA_M);
    float* lrow = (float*)(smem + FA_L);
    float* rrow = (float*)(smem + FA_R);
    float* pmax = (float*)(smem + FA_PMX);
    float* psum = (float*)(smem + FA_PSM);
    float* tab  = (float*)(smem + FA_TAB);
    const int tid = threadIdx.x, lane = tid & 31, wid = tid >> 5;
    const int bh = blockIdx.y, b = bh >> 4, h = bh & 15;
    const int i0 = blockIdx.x * 128;
    const int wm = wid & 1, wn = wid >> 1;
    const int wmv = wid & 3, wnv = wid >> 2;

    const int lr2 = tid >> 1, ls2 = tid & 1;

    {
        const float* qp = Q + (size_t)(b * SEQ + i0 + lr2) * ldq + h * HDIM + ls2 * 32;
        const uint32_t off = (uint32_t)(lr2 * QSTR + ls2 * 32) * 2;
        uint32_t hh[16], ll[16];
#pragma unroll
        for (int i = 0; i < 8; i++) {
            float4 x = *(const float4*)(qp + i * 4);
            uint32_t h0 = bfpack(x.x, x.y), h1 = bfpack(x.z, x.w);
            hh[2*i] = h0; hh[2*i+1] = h1;
            ll[2*i]   = bfpack(x.x - bflo(h0), x.y - bfhi(h0));
            ll[2*i+1] = bfpack(x.z - bflo(h1), x.w - bfhi(h1));
        }
#pragma unroll
        for (int i = 0; i < 4; i++) {
            STS128(sb + FA_OQH + off + i * 16, hh[4*i], hh[4*i+1], hh[4*i+2], hh[4*i+3]);
            STS128(sb + FA_OQL + off + i * 16, ll[4*i], ll[4*i+1], ll[4*i+2], ll[4*i+3]);
        }
    }
    if (tid < 128) { mrow[tid] = -1e30f; lrow[tid] = 0.f; }

    float oacc[2][4][4];
#pragma unroll
    for (int i = 0; i < 2; i++)
#pragma unroll
        for (int j = 0; j < 4; j++)
#pragma unroll
            for (int e = 0; e < 4; e++) oacc[i][j][e] = 0.f;

    const float scale = 0.03125f;
    const uint32_t arow = (uint32_t)(wm * 64 + (lane & 15));
    const uint32_t acol = (uint32_t)((lane >> 4) * 8);
    const uint32_t brw  = (uint32_t)(wn * 32 + (lane & 7));
    const uint32_t bcl  = (uint32_t)(((lane >> 3) & 1) * 8);
    const uint32_t arv  = (uint32_t)(wmv * 32 + (lane & 15));
    const uint32_t klv  = (uint32_t)(lane & 15);
    const int lr4 = lane >> 2, lc4 = (lane & 3) * 2;

    for (int jt = 0; jt < 8; jt++) {
        const int j0 = jt * 128;
        __syncthreads();
        tab[tid] = __expf(-0.01f * fabsf((float)(i0 - j0 + tid - 128)));

        {
            const float* kp = Kc + (size_t)(b * SEQ + j0 + lr2) * ldk + h * HDIM + ls2 * 32;
            const float* vp = V  + (size_t)(b * SEQ + j0 + lr2) * ldv + h * HDIM + ls2 * 32;
            const uint32_t offk = (uint32_t)(lr2 * QSTR + ls2 * 32) * 2;
            const uint32_t offv = (uint32_t)(lr2 * VSTR + ls2 * 32) * 2;
            uint32_t hh[16], ll[16];
#pragma unroll
            for (int i = 0; i < 8; i++) {
                float4 x = *(const float4*)(kp + i * 4);
                uint32_t h0 = bfpack(x.x, x.y), h1 = bfpack(x.z, x.w);
                hh[2*i] = h0; hh[2*i+1] = h1;
                ll[2*i]   = bfpack(x.x - bflo(h0), x.y - bfhi(h0));
                ll[2*i+1] = bfpack(x.z - bflo(h1), x.w - bfhi(h1));
            }
#pragma unroll
            for (int i = 0; i < 4; i++) {
                STS128(sb + FA_OKH + offk + i * 16, hh[4*i], hh[4*i+1], hh[4*i+2], hh[4*i+3]);
                STS128(sb + FA_OKL + offk + i * 16, ll[4*i], ll[4*i+1], ll[4*i+2], ll[4*i+3]);
            }
#pragma unroll
            for (int i = 0; i < 8; i++) {
                float4 x = *(const float4*)(vp + i * 4);
                uint32_t h0 = bfpack(x.x, x.y), h1 = bfpack(x.z, x.w);
                hh[2*i] = h0; hh[2*i+1] = h1;
                ll[2*i]   = bfpack(x.x - bflo(h0), x.y - bfhi(h0));
                ll[2*i+1] = bfpack(x.z - bflo(h1), x.w - bfhi(h1));
            }
#pragma unroll
            for (int i = 0; i < 4; i++) {
                STS128(sb + FA_OVH + offv + i * 16, hh[4*i], hh[4*i+1], hh[4*i+2], hh[4*i+3]);
                STS128(sb + FA_OVL + offv + i * 16, ll[4*i], ll[4*i+1], ll[4*i+2], ll[4*i+3]);
            }
        }
        __syncthreads();

        float sacc[4][4][4];
#pragma unroll
        for (int i = 0; i < 4; i++)
#pragma unroll
            for (int j = 0; j < 4; j++)
#pragma unroll
                for (int e = 0; e < 4; e++) sacc[i][j][e] = 0.f;
#pragma unroll
        for (int ks = 0; ks < 4; ks++) {
            uint32_t ah[4][4], al[4][4];
#pragma unroll
            for (int mt = 0; mt < 4; mt++) {
                uint32_t aoff = ((arow + mt * 16) * QSTR + acol + ks * 16) * 2;
                LDSM_X4(ah[mt][0], ah[mt][1], ah[mt][2], ah[mt][3], sb + FA_OQH + aoff);
                LDSM_X4(al[mt][0], al[mt][1], al[mt][2], al[mt][3], sb + FA_OQL + aoff);
            }
#pragma unroll
            for (int nt = 0; nt < 4; nt++) {
                uint32_t boff = ((brw + nt * 8) * QSTR + bcl + ks * 16) * 2;
                uint32_t bh0, bh1, bl0, bl1;
                LDSM_X2(bh0, bh1, sb + FA_OKH + boff);
                LDSM_X2(bl0, bl1, sb + FA_OKL + boff);
#pragma unroll
                for (int mt = 0; mt < 4; mt++) {
                    MMA16816(sacc[mt][nt], ah[mt][0], ah[mt][1], ah[mt][2], ah[mt][3], bh0, bh1);
                    MMA16816(sacc[mt][nt], ah[mt][0], ah[mt][1], ah[mt][2], ah[mt][3], bl0, bl1);
                    MMA16816(sacc[mt][nt], al[mt][0], al[mt][1], al[mt][2], al[mt][3], bh0, bh1);
                }
            }
        }

#pragma unroll
        for (int mt = 0; mt < 4; mt++) {
            int ri = wm * 64 + mt * 16 + lr4;
            float mx0 = -1e30f, mx1 = -1e30f;
#pragma unroll
            for (int nt = 0; nt < 4; nt++) {
                int cj = wn * 32 + nt * 8 + lc4;
                int d0 = ri - cj + 128;
                sacc[mt][nt][0] *= scale * tab[d0];
                sacc[mt][nt][1] *= scale * tab[d0 - 1];
                sacc[mt][nt][2] *= scale * tab[d0 + 8];
                sacc[mt][nt][3] *= scale * tab[d0 + 7];
                mx0 = fmaxf(mx0, fmaxf(sacc[mt][nt][0], sacc[mt][nt][1]));
                mx1 = fmaxf(mx1, fmaxf(sacc[mt][nt][2], sacc[mt][nt][3]));
            }
            mx0 = fmaxf(mx0, __shfl_xor_sync(0xffffffffu, mx0, 1));
            mx0 = fmaxf(mx0, __shfl_xor_sync(0xffffffffu, mx0, 2));
            mx1 = fmaxf(mx1, __shfl_xor_sync(0xffffffffu, mx1, 1));
            mx1 = fmaxf(mx1, __shfl_xor_sync(0xffffffffu, mx1, 2));
            if ((lane & 3) == 0) {
                pmax[wn * 128 + ri] = mx0;
                pmax[wn * 128 + ri + 8] = mx1;
            }
        }
        __syncthreads();
        if (tid < 128) {
            float mo = mrow[tid];
            float mn = fmaxf(fmaxf(pmax[tid], pmax[128 + tid]),
                             fmaxf(pmax[256 + tid], pmax[384 + tid]));
            mn = fmaxf(mo, mn);
            rrow[tid] = __expf(mo - mn);
            mrow[tid] = mn;
        }
        __syncthreads();

#pragma unroll
        for (int mt = 0; mt < 4; mt++) {
            int row0 = wm * 64 + mt * 16 + lr4;
            int row1 = row0 + 8;
            float m0 = mrow[row0], m1 = mrow[row1];
            float s0 = 0.f, s1 = 0.f;
#pragma unroll
            for (int nt = 0; nt < 4; nt++) {
                int col = wn * 32 + nt * 8 + lc4;
                float p0 = __expf(sacc[mt][nt][0] - m0);
                float p1 = __expf(sacc[mt][nt][1] - m0);
                float p2 = __expf(sacc[mt][nt][2] - m1);
                float p3 = __expf(sacc[mt][nt][3] - m1);
                s0 += p0 + p1; s1 += p2 + p3;
                uint32_t ph0 = bfpack(p0, p1);
                uint32_t pl0 = bfpack(p0 - bflo(ph0), p1 - bfhi(ph0));
                uint32_t ph1 = bfpack(p2, p3);
                uint32_t pl1 = bfpack(p2 - bflo(ph1), p3 - bfhi(ph1));
                uint32_t a0 = (uint32_t)(row0 * PSTR + col) * 2;
                uint32_t a1 = (uint32_t)(row1 * PSTR + col) * 2;
                STS32(sb + FA_OPH + a0, ph0);
                STS32(sb + FA_OPL + a0, pl0);
                STS32(sb + FA_OPH + a1, ph1);
                STS32(sb + FA_OPL + a1, pl1);
            }
            s0 += __shfl_xor_sync(0xffffffffu, s0, 1);
            s0 += __shfl_xor_sync(0xffffffffu, s0, 2);
            s1 += __shfl_xor_sync(0xffffffffu, s1, 1);
            s1 += __shfl_xor_sync(0xffffffffu, s1, 2);
            if ((lane & 3) == 0) {
                psum[wn * 128 + row0] = s0;
                psum[wn * 128 + row1] = s1;
            }
        }
        __syncthreads();
        if (tid < 128)
            lrow[tid] = lrow[tid] * rrow[tid]
                      + psum[tid] + psum[128 + tid] + psum[256 + tid] + psum[384 + tid];

#pragma unroll
        for (int mt = 0; mt < 2; mt++) {
            int r0 = wmv * 32 + mt * 16 + lr4;
            float f0 = rrow[r0], f1 = rrow[r0 + 8];
#pragma unroll
            for (int nt = 0; nt < 4; nt++) {
                oacc[mt][nt][0] *= f0; oacc[mt][nt][1] *= f0;
                oacc[mt][nt][2] *= f1; oacc[mt][nt][3] *= f1;
            }
        }
#pragma unroll
        for (int ks = 0; ks < 8; ks++) {
            uint32_t ah[2][4], al[2][4];
#pragma unroll
            for (int mt = 0; mt < 2; mt++) {
                uint32_t aoff = ((arv + mt * 16) * PSTR + (uint32_t)((lane >> 4) * 8) + ks * 16) * 2;
                LDSM_X4(ah[mt][0], ah[mt][1], ah[mt][2], ah[mt][3], sb + FA_OPH + aoff);
                LDSM_X4(al[mt][0], al[mt][1], al[mt][2], al[mt][3], sb + FA_OPL + aoff);
            }
#pragma unroll
            for (int nt = 0; nt < 4; nt++) {
                uint32_t boff = ((ks * 16 + klv) * VSTR + wnv * 32 + nt * 8) * 2;
                uint32_t bh0, bh1, bl0, bl1;
                LDSM_X2T(bh0, bh1, sb + FA_OVH + boff);
                LDSM_X2T(bl0, bl1, sb + FA_OVL + boff);
#pragma unroll
                for (int mt = 0; mt < 2; mt++) {
                    MMA16816(oacc[mt][nt], ah[mt][0], ah[mt][1], ah[mt][2], ah[mt][3], bh0, bh1);
                    MMA16816(oacc[mt][nt], ah[mt][0], ah[mt][1], ah[mt][2], ah[mt][3], bl0, bl1);
                    MMA16816(oacc[mt][nt], al[mt][0], al[mt][1], al[mt][2], al[mt][3], bh0, bh1);
                }
            }
        }
    }

    __syncthreads();
#pragma unroll
    for (int mt = 0; mt < 2; mt++) {
        int r0 = wmv * 32 + mt * 16 + lr4;
        float inv0 = 1.0f / lrow[r0];
        float inv1 = 1.0f / lrow[r0 + 8];
#pragma unroll
        for (int nt = 0; nt < 4; nt++) {
            int c = h * HDIM + wnv * 32 + nt * 8 + lc4;
            float2 o0, o1;
            o0.x = oacc[mt][nt][0] * inv0; o0.y = oacc[mt][nt][1] * inv0;
            o1.x = oacc[mt][nt][2] * inv1; o1.y = oacc[mt][nt][3] * inv1;
            *(float2*)(O + (size_t)(b * SEQ + i0 + r0) * DM + c)     = o0;
            *(float2*)(O + (size_t)(b * SEQ + i0 + r0 + 8) * DM + c) = o1;
        }
    }
}

// ---------------- FFMA2 SGEMM (kept for the K=50 embedding GEMM) -----------
__global__ __launch_bounds__(256) void sgemm2_k(
    int M, int N, int K,
    const float* __restrict__ A, const float* __restrict__ B,
    const float* __restrict__ bias, float* __restrict__ C)
{
    __shared__ __align__(16) float As[KT][128];
    __shared__ __align__(16) float Bs[KT][128];
    const int tid  = threadIdx.x;
    const int brow = blockIdx.y * 128;
    const int bcol = blockIdx.x * 128;
    const int ty = tid >> 4, tx = tid & 15;
    const int ar = tid >> 1, aks = (tid & 1) * 8;

    unsigned long long acc[8][4];
#pragma unroll
    for (int i = 0; i < 8; i++)
#pragma unroll
        for (int j = 0; j < 4; j++) acc[i][j] = 0ULL;

    for (int k0 = 0; k0 < K; k0 += KT) {
#pragma unroll
        for (int i = 0; i < 8; i++) {
            int kk = aks + i;
            As[kk][ar] = (k0 + kk < K) ? A[(size_t)(brow + ar) * K + k0 + kk] : 0.f;
        }
#pragma unroll
        for (int p = 0; p < 2; p++) {
            int id = p * 256 + tid;
            int kk = id >> 5, c4 = (id & 31) * 4;
            float4 bv = make_float4(0.f, 0.f, 0.f, 0.f);
            if (k0 + kk < K) bv = *(const float4*)(B + (size_t)(k0 + kk) * N + bcol + c4);
            *(float4*)&Bs[kk][c4] = bv;
        }
        __syncthreads();
#pragma unroll
        for (int kk = 0; kk < KT; kk++) {
            float4 a0 = *(const float4*)&As[kk][ty * 4];
            float4 a1 = *(const float4*)&As[kk][64 + ty * 4];
            float4 b0 = *(const float4*)&Bs[kk][tx * 4];
            float4 b1 = *(const float4*)&Bs[kk][64 + tx * 4];
            unsigned long long rb[4] = { pk2(b0.x, b0.y), pk2(b0.z, b0.w),
                                         pk2(b1.x, b1.y), pk2(b1.z, b1.w) };
            float ra[8] = { a0.x, a0.y, a0.z, a0.w, a1.x, a1.y, a1.z, a1.w };
#pragma unroll
            for (int i = 0; i < 8; i++) {
                unsigned long long ad = pk2(ra[i], ra[i]);
#pragma unroll
                for (int j = 0; j < 4; j++) acc[i][j] = ffma2(ad, rb[j], acc[i][j]);
            }
        }
        __syncthreads();
    }
#pragma unroll
    for (int ih = 0; ih < 2; ih++)
#pragma unroll
    for (int ii = 0; ii < 4; ii++) {
        int i = ih * 4 + ii;
        int r = brow + ih * 64 + ty * 4 + ii;
#pragma unroll
        for (int jh = 0; jh < 2; jh++) {
            int c = bcol + jh * 64 + tx * 4;
            float2 p0 = up2(acc[i][jh * 2]);
            float2 p1 = up2(acc[i][jh * 2 + 1]);
            float4 o; o.x = p0.x; o.y = p0.y; o.z = p1.x; o.w = p1.y;
            if (bias) { o.x += bias[c]; o.y += bias[c+1]; o.z += bias[c+2]; o.w += bias[c+3]; }
            *(float4*)(C + (size_t)r * N + c) = o;
        }
    }
}

// ---------------- Fourier token features -----------------------------------
__global__ void fourier_k(const int* __restrict__ src, const float* __restrict__ a_n,
                          const float* __restrict__ b_n, float* __restrict__ F)
{
    int idx = blockIdx.x * blockDim.x + threadIdx.x;
    if (idx >= ROWS * NFR) return;
    int bs = idx / NFR, n = idx % NFR;
    int tok = src[bs];
    float x   = (float)tok * (1.0f / (float)VOC);
    float ang = 6.28318530717958647692f * (float)(n + 1) * x;
    F[idx] = a_n[tok * NFR + n] * cosf(ang) + b_n[tok * NFR + n] * sinf(ang);
}

// ---------------- h += sinusoidal PE ---------------------------------------
__global__ void addpe_k(float* __restrict__ h)
{
    int idx = blockIdx.x * blockDim.x + threadIdx.x;
    if (idx >= ROWS * DM) return;
    int d = idx & (DM - 1);
    int s = (idx / DM) & (SEQ - 1);
    float div = expf(-(float)(d & ~1) * 8.99447301948846e-3f);
    float ang = (float)s * div;
    h[idx] += (d & 1) ? cosf(ang) : sinf(ang);
}

// ---------------------------------------------------------------------------
extern "C" void kernel_launch(void* const* d_in, const int* in_sizes, int n_in,
                              void* d_out, int out_size)
{
    const int*   src    = (const int*)  d_in[0];
    const float* a_n    = (const float*)d_in[2];
    const float* b_n    = (const float*)d_in[3];
    const float* proj_w = (const float*)d_in[4];
    const float* proj_b = (const float*)d_in[5];
    const float* rule   = (const float*)d_in[6];
    const float* Wq     = (const float*)d_in[7];
    const float* Wk     = (const float*)d_in[8];
    const float* Wv     = (const float*)d_in[9];
    const float* Wo     = (const float*)d_in[10];
    const float* Wdown  = (const float*)d_in[11];
    const float* Wup_k  = (const float*)d_in[12];
    const float* Wup_v  = (const float*)d_in[13];
    const float* Wout   = (const float*)d_in[14];
    const float* bout   = (const float*)d_in[15];
    float* out = (float*)d_out;

    float *h, *t, *kv, *qkv, *krvr, *four;
    __nv_bfloat16 *wbh, *wbl, *ah, *al, *hh, *hl, *lh, *ll;
    cudaGetSymbolAddress((void**)&h,    g_h);
    cudaGetSymbolAddress((void**)&t,    g_t);
    cudaGetSymbolAddress((void**)&kv,   g_kv);
    cudaGetSymbolAddress((void**)&qkv,  g_qkv);
    cudaGetSymbolAddress((void**)&krvr, g_krvr);
    cudaGetSymbolAddress((void**)&four, g_four);
    cudaGetSymbolAddress((void**)&wbh,  g_wbh);
    cudaGetSymbolAddress((void**)&wbl,  g_wbl);
    cudaGetSymbolAddress((void**)&ah,   g_ah);
    cudaGetSymbolAddress((void**)&al,   g_al);
    cudaGetSymbolAddress((void**)&hh,   g_hh);
    cudaGetSymbolAddress((void**)&hl,   g_hl);
    cudaGetSymbolAddress((void**)&lh,   g_lh);
    cudaGetSymbolAddress((void**)&ll,   g_ll);

    cudaFuncSetAttribute(gemm_mma, cudaFuncAttributeMaxDynamicSharedMemorySize, DSMG);
    cudaFuncSetAttribute(flash_k,  cudaFuncAttributeMaxDynamicSharedMemorySize, DSMF);

    // ---- transpose + split all weights (batched over layers, 9 launches) ----
    {
        const size_t SDD = (size_t)DM * DM, SDH = (size_t)DM * DLAT;
        wsplit_k<<<dim3(DM/64, DM/64, 1), 256>>>(rule, DM, DM, 0, 0,
                                                 wbh + OFF_RULE, wbl + OFF_RULE);
        wsplit_k<<<dim3(DM/64, DM/64, NL), 256>>>(Wq, DM, DM, SDD, LSTRIDE,
                                                  wbh + OFF_L(0), wbl + OFF_L(0));
        wsplit_k<<<dim3(DM/64, DM/64, NL), 256>>>(Wk, DM, DM, SDD, LSTRIDE,
                                                  wbh + OFF_L(0) + WSZ_DD, wbl + OFF_L(0) + WSZ_DD);
        wsplit_k<<<dim3(DM/64, DM/64, NL), 256>>>(Wv, DM, DM, SDD, LSTRIDE,
                                                  wbh + OFF_L(0) + 2*WSZ_DD, wbl + OFF_L(0) + 2*WSZ_DD);
        wsplit_k<<<dim3(DM/64, DM/64, NL), 256>>>(Wo, DM, DM, SDD, LSTRIDE,
                                                  wbh + OFF_L(0) + 3*WSZ_DD, wbl + OFF_L(0) + 3*WSZ_DD);
        wsplit_k<<<dim3(DLAT/64, DM/64, NL), 256>>>(Wdown, DM, DLAT, SDH, LSTRIDE,
                                                    wbh + OFF_L(0) + 4*WSZ_DD, wbl + OFF_L(0) + 4*WSZ_DD);
        wsplit_k<<<dim3(DM/64, DLAT/64, NL), 256>>>(Wup_k, DLAT, DM, SDH, LSTRIDE,
                                                    wbh + OFF_L(0) + 4*WSZ_DD + WSZ_HALF,
                                                    wbl + OFF_L(0) + 4*WSZ_DD + WSZ_HALF);
        wsplit_k<<<dim3(DM/64, DLAT/64, NL), 256>>>(Wup_v, DLAT, DM, SDH, LSTRIDE,
                                                    wbh + OFF_L(0) + 4*WSZ_DD + 2*WSZ_HALF,
                                                    wbl + OFF_L(0) + 4*WSZ_DD + 2*WSZ_HALF);
        wsplit_k<<<dim3(VOC/64, DM/64, 1), 256>>>(Wout, DM, VOC, 0, 0,
                                                  wbh + OFF_WOUT, wbl + OFF_WOUT);
    }

    const dim3 g_qkv3(3*DM/128, ROWS/128);   // 384 CTAs
    const dim3 g_up  (2*DM/128, ROWS/128);   // 256 CTAs
    const dim3 g_d   (DM  /128, ROWS/128);   // 128 CTAs
    const dim3 g_dl  (DLAT/128, ROWS/128);   //  64 CTAs
    const dim3 g_voc (VOC /128, ROWS/128);   // 4000 CTAs
    const int N8_DD = ROWS * (DM/8);

    // ---- embedding ----
    fourier_k<<<(ROWS * NFR + 255) / 256, 256>>>(src, a_n, b_n, four);
    sgemm2_k<<<g_d, 256>>>(ROWS, DM, NFR, four, proj_w, proj_b, t);
    asplit_k<<<(N8_DD + 255)/256, 256>>>(t, nullptr, ROWS, DM/8, DM, ah, al);
    gemm_mma<<<g_d, 256, DSMG>>>(ROWS, DM, DM, ah, al, wbh + OFF_RULE, wbl + OFF_RULE,
                                 nullptr, h, nullptr, nullptr);
    addpe_k<<<(ROWS * DM + 255) / 256, 256>>>(h);
    asplit_k<<<(N8_DD + 255)/256, 256>>>(h, nullptr, ROWS, DM/8, DM, hh, hl);

    // ---- layers ----
    for (int l = 0; l < NL; l++) {
        size_t o = OFF_L(l);
        const __nv_bfloat16 *qkh= wbh+o,                   *qkl= wbl+o;
        const __nv_bfloat16 *dh = wbh+o+4*WSZ_DD,          *dl = wbl+o+4*WSZ_DD;
        const __nv_bfloat16 *uh = wbh+o+4*WSZ_DD+WSZ_HALF, *ul = wbl+o+4*WSZ_DD+WSZ_HALF;
        const __nv_bfloat16 *oh = wbh+o+3*WSZ_DD,          *ol = wbl+o+3*WSZ_DD;

        gemm_mma<<<g_qkv3, 256, DSMG>>>(ROWS, 3*DM, DM, hh, hl, qkh, qkl,
                                        nullptr, qkv, nullptr, nullptr);
        asplit_k<<<(N8_DD + 255)/256, 256>>>(qkv + DM, qkv + 2*DM, ROWS, DM/8, 3*DM, ah, al);
        gemm_mma<<<g_dl, 256, DSMG>>>(ROWS, DLAT, DM, ah, al, dh, dl,
                                      nullptr, nullptr, lh, ll);
        gemm_mma<<<g_up, 256, DSMG>>>(ROWS, 2*DM, DLAT, lh, ll, uh, ul,
                                      nullptr, krvr, nullptr, nullptr);

        flash_k<<<dim3(SEQ/128, BSZ*NH), 256, DSMF>>>(qkv, 3*DM, krvr, 2*DM,
                                                      krvr + DM, 2*DM, kv);

        asplit_k<<<(N8_DD + 255)/256, 256>>>(kv, nullptr, ROWS, DM/8, DM, ah, al);
        gemm_mma<<<g_d, 256, DSMG>>>(ROWS, DM, DM, ah, al, oh, ol,
                                     nullptr, nullptr, hh, hl);
    }

    // ---- vocab projection ----
    gemm_mma<<<g_voc, 256, DSMG>>>(ROWS, VOC, DM, hh, hl, wbh + OFF_WOUT, wbl + OFF_WOUT,
                                   bout, out, nullptr, nullptr);
}

// round 17
// speedup vs baseline: 1.2690x; 1.0689x over previous
#include <cuda_runtime.h>
#include <cuda_bf16.h>
#include <math.h>
#include <stdint.h>

#define BSZ  2
#define SEQ  1024
#define DM   1024
#define NH   16
#define HDIM 64
#define NL   4
#define VOC  32000
#define NFR  50
#define DLAT 512
#define ROWS (BSZ*SEQ)   // 2048
#define KT   16

// ---------------- scratch (device globals; no allocation allowed) ----------
__device__ float g_h  [ROWS*DM];
__device__ float g_t  [ROWS*DM];          // embed temp / per-layer q buffer
__device__ float g_krvr[ROWS*2*DM];
__device__ float g_four[ROWS*NFR];
__device__ __align__(16) __nv_bfloat16 g_ah[ROWS*DM];
__device__ __align__(16) __nv_bfloat16 g_al[ROWS*DM];
__device__ __align__(16) __nv_bfloat16 g_hh[ROWS*DM];
__device__ __align__(16) __nv_bfloat16 g_hl[ROWS*DM];
__device__ __align__(16) __nv_bfloat16 g_lh[ROWS*DLAT];
__device__ __align__(16) __nv_bfloat16 g_ll[ROWS*DLAT];

// transposed + split weights: [N][K] bf16, hi and lo halves
// per layer: q (DD) | kvsum (DD) | wo (DD) | down (DD/2) | up (DD)  = 4.5 DD
#define WSZ_DD   (1024*1024)
#define WSZ_HALF (512*1024)
#define LOFF_Q    0
#define LOFF_KV   ((size_t)WSZ_DD)
#define LOFF_WO   (2*(size_t)WSZ_DD)
#define LOFF_DOWN (3*(size_t)WSZ_DD)
#define LOFF_UP   (3*(size_t)WSZ_DD + WSZ_HALF)
#define LSTRIDE   (4*(size_t)WSZ_DD + 3*(size_t)WSZ_HALF)
#define OFF_RULE 0
#define OFF_L(l) ((size_t)WSZ_DD + (size_t)(l)*LSTRIDE)
#define OFF_WOUT ((size_t)WSZ_DD + 4*LSTRIDE)
#define WTOT     (OFF_WOUT + (size_t)VOC*DM)
__device__ __align__(16) __nv_bfloat16 g_wbh[WTOT];
__device__ __align__(16) __nv_bfloat16 g_wbl[WTOT];

// ---------------- f32x2 packed helpers -------------------------------------
__device__ __forceinline__ unsigned long long pk2(float lo, float hi) {
    unsigned long long r;
    asm("mov.b64 %0, {%1, %2};" : "=l"(r) : "f"(lo), "f"(hi));
    return r;
}
__device__ __forceinline__ unsigned long long ffma2(
    unsigned long long a, unsigned long long b, unsigned long long c) {
    unsigned long long d;
    asm("fma.rn.f32x2 %0, %1, %2, %3;" : "=l"(d) : "l"(a), "l"(b), "l"(c));
    return d;
}
__device__ __forceinline__ float2 up2(unsigned long long v) {
    float2 f;
    asm("mov.b64 {%0, %1}, %2;" : "=f"(f.x), "=f"(f.y) : "l"(v));
    return f;
}

// ---------------- misc helpers ---------------------------------------------
__device__ __forceinline__ uint32_t smem_to_u32(const void* p) {
    uint32_t a;
    asm("{ .reg .u64 t; cvta.to.shared.u64 t, %1; cvt.u32.u64 %0, t; }" : "=r"(a) : "l"(p));
    return a;
}
__device__ __forceinline__ uint32_t bfpack(float lo, float hi) {
    uint32_t r;
    asm("cvt.rn.bf16x2.f32 %0, %1, %2;" : "=r"(r) : "f"(hi), "f"(lo));
    return r;
}
__device__ __forceinline__ float bflo(uint32_t p) { return __uint_as_float(p << 16); }
__device__ __forceinline__ float bfhi(uint32_t p) { return __uint_as_float(p & 0xffff0000u); }
#define STS128(addr, a, b, c, d) \
    asm volatile("st.shared.v4.b32 [%0], {%1, %2, %3, %4};" \
        :: "r"(addr), "r"(a), "r"(b), "r"(c), "r"(d) : "memory")
#define STS32(addr, v) \
    asm volatile("st.shared.b32 [%0], %1;" :: "r"(addr), "r"(v) : "memory")
#define LDSM_X4(r0, r1, r2, r3, addr) \
    asm volatile("ldmatrix.sync.aligned.m8n8.x4.shared.b16 {%0,%1,%2,%3}, [%4];" \
        : "=r"(r0), "=r"(r1), "=r"(r2), "=r"(r3) : "r"(addr))
#define LDSM_X2(r0, r1, addr) \
    asm volatile("ldmatrix.sync.aligned.m8n8.x2.shared.b16 {%0,%1}, [%2];" \
        : "=r"(r0), "=r"(r1) : "r"(addr))
#define LDSM_X2T(r0, r1, addr) \
    asm volatile("ldmatrix.sync.aligned.m8n8.x2.trans.shared.b16 {%0,%1}, [%2];" \
        : "=r"(r0), "=r"(r1) : "r"(addr))
#define MMA16816(d, a0, a1, a2, a3, b0, b1) \
    asm volatile("mma.sync.aligned.m16n8k16.row.col.f32.bf16.bf16.f32 " \
        "{%0,%1,%2,%3}, {%4,%5,%6,%7}, {%8,%9}, {%0,%1,%2,%3};" \
        : "+f"((d)[0]), "+f"((d)[1]), "+f"((d)[2]), "+f"((d)[3]) \
        : "r"(a0), "r"(a1), "r"(a2), "r"(a3), "r"(b0), "r"(b1))

// ===== weight transpose + bf16 split: 64x64 tiles, layer-batched ===========
// Optional second source W2 (element-wise sum before split) for Wk+Wv.
__global__ __launch_bounds__(256) void wsplit_k(
    const float* __restrict__ W, const float* __restrict__ W2, int K, int N,
    size_t inStrideZ, size_t outStrideZ,
    __nv_bfloat16* __restrict__ Th, __nv_bfloat16* __restrict__ Tl)
{
    __shared__ float t[64][65];
    const int k0 = blockIdx.y * 64, n0 = blockIdx.x * 64;
    const int tid = threadIdx.x;
    const float* Wz  = W  + (size_t)blockIdx.z * inStrideZ;
    const float* W2z = W2 ? W2 + (size_t)blockIdx.z * inStrideZ : (const float*)0;
    __nv_bfloat16* Thz = Th + (size_t)blockIdx.z * outStrideZ;
    __nv_bfloat16* Tlz = Tl + (size_t)blockIdx.z * outStrideZ;

    const int lr = tid >> 4, lc = (tid & 15) * 4;
#pragma unroll
    for (int p = 0; p < 4; p++) {
        int k = lr + p * 16;
        float4 x = *(const float4*)(Wz + (size_t)(k0 + k) * N + n0 + lc);
        if (W2z) {
            float4 y = *(const float4*)(W2z + (size_t)(k0 + k) * N + n0 + lc);
            x.x += y.x; x.y += y.y; x.z += y.z; x.w += y.w;
        }
        t[k][lc] = x.x; t[k][lc + 1] = x.y; t[k][lc + 2] = x.z; t[k][lc + 3] = x.w;
    }
    __syncthreads();

    const int n = tid >> 2;
    const int kgb = tid & 3;
#pragma unroll
    for (int i = 0; i < 2; i++) {
        int kg = kgb + 4 * i;
        uint32_t h[4], l[4];
#pragma unroll
        for (int j = 0; j < 4; j++) {
            float x0 = t[kg * 8 + 2 * j][n];
            float x1 = t[kg * 8 + 2 * j + 1][n];
            uint32_t hp = bfpack(x0, x1);
            uint32_t lp = bfpack(x0 - bflo(hp), x1 - bfhi(hp));
            h[j] = hp; l[j] = lp;
        }
        size_t o = (size_t)(n0 + n) * K + k0 + kg * 8;
        *(uint4*)(Thz + o) = make_uint4(h[0], h[1], h[2], h[3]);
        *(uint4*)(Tlz + o) = make_uint4(l[0], l[1], l[2], l[3]);
    }
}

// ===== activation split: A fp32 -> bf16 hi/lo (embed path only) ============
__global__ __launch_bounds__(256) void asplit_k(
    const float* __restrict__ A, int total8,
    __nv_bfloat16* __restrict__ Ah, __nv_bfloat16* __restrict__ Al)
{
    int idx = blockIdx.x * 256 + threadIdx.x;
    if (idx >= total8) return;
    const float* base = A + (size_t)idx * 8;
    float4 x0 = *(const float4*)base, x1 = *(const float4*)(base + 4);
    uint32_t h0 = bfpack(x0.x, x0.y), h1 = bfpack(x0.z, x0.w);
    uint32_t h2 = bfpack(x1.x, x1.y), h3 = bfpack(x1.z, x1.w);
    uint32_t l0 = bfpack(x0.x - bflo(h0), x0.y - bfhi(h0));
    uint32_t l1 = bfpack(x0.z - bflo(h1), x0.w - bfhi(h1));
    uint32_t l2 = bfpack(x1.x - bflo(h2), x1.y - bfhi(h2));
    uint32_t l3 = bfpack(x1.z - bflo(h3), x1.w - bfhi(h3));
    *(uint4*)(Ah + (size_t)idx * 8) = make_uint4(h0, h1, h2, h3);
    *(uint4*)(Al + (size_t)idx * 8) = make_uint4(l0, l1, l2, l3);
}

// ================= HMMA bf16-split GEMM (pre-split A, optional split out) ==
#define ASTR   40
#define TILEB  (128*80)
#define OAH    0
#define OAL    (TILEB)
#define OBH    (2*TILEB)
#define OBL    (3*TILEB)
#define BUFSTR (4*TILEB)
#define DSMG   (2*BUFSTR)               // 81920

__global__ __launch_bounds__(256) void gemm_mma(
    int M, int N, int K,
    const __nv_bfloat16* __restrict__ Ah, const __nv_bfloat16* __restrict__ Al,
    const __nv_bfloat16* __restrict__ Bh, const __nv_bfloat16* __restrict__ Bl,
    const float* __restrict__ bias, float* __restrict__ C,
    __nv_bfloat16* __restrict__ Oh, __nv_bfloat16* __restrict__ Ol)
{
    extern __shared__ char smem[];
    const uint32_t sb = smem_to_u32(smem);
    const int tid = threadIdx.x, lane = tid & 31, wid = tid >> 5;
    const int brow = blockIdx.y * 128, bcol = blockIdx.x * 128;
    const int wm = wid & 1, wn = wid >> 1;

    const int lrow = tid >> 1, lhalf = tid & 1;
    const __nv_bfloat16* Ahp = Ah + (size_t)(brow + lrow) * K + lhalf * 16;
    const __nv_bfloat16* Alp = Al + (size_t)(brow + lrow) * K + lhalf * 16;
    const __nv_bfloat16* Bhp = Bh + (size_t)(bcol + lrow) * K + lhalf * 16;
    const __nv_bfloat16* Blp = Bl + (size_t)(bcol + lrow) * K + lhalf * 16;
    const uint32_t soff = (uint32_t)(lrow * ASTR + lhalf * 16) * 2;

    float acc[4][4][4];
#pragma unroll
    for (int i = 0; i < 4; i++)
#pragma unroll
        for (int j = 0; j < 4; j++)
#pragma unroll
            for (int e = 0; e < 4; e++) acc[i][j][e] = 0.f;

    uint4 pah[2], pal[2], pbh[2], pbl[2];

#define LOADG(k0) do { \
    pah[0] = *(const uint4*)(Ahp + (k0)); pah[1] = *(const uint4*)(Ahp + (k0) + 8); \
    pal[0] = *(const uint4*)(Alp + (k0)); pal[1] = *(const uint4*)(Alp + (k0) + 8); \
    pbh[0] = *(const uint4*)(Bhp + (k0)); pbh[1] = *(const uint4*)(Bhp + (k0) + 8); \
    pbl[0] = *(const uint4*)(Blp + (k0)); pbl[1] = *(const uint4*)(Blp + (k0) + 8); \
} while (0)

#define STOREBUF(b) do { \
    uint32_t base_ = sb + (uint32_t)(b) * BUFSTR; \
    STS128(base_ + OAH + soff,      pah[0].x, pah[0].y, pah[0].z, pah[0].w); \
    STS128(base_ + OAH + soff + 16, pah[1].x, pah[1].y, pah[1].z, pah[1].w); \
    STS128(base_ + OAL + soff,      pal[0].x, pal[0].y, pal[0].z, pal[0].w); \
    STS128(base_ + OAL + soff + 16, pal[1].x, pal[1].y, pal[1].z, pal[1].w); \
    STS128(base_ + OBH + soff,      pbh[0].x, pbh[0].y, pbh[0].z, pbh[0].w); \
    STS128(base_ + OBH + soff + 16, pbh[1].x, pbh[1].y, pbh[1].z, pbh[1].w); \
    STS128(base_ + OBL + soff,      pbl[0].x, pbl[0].y, pbl[0].z, pbl[0].w); \
    STS128(base_ + OBL + soff + 16, pbl[1].x, pbl[1].y, pbl[1].z, pbl[1].w); \
} while (0)

    const int nchunk = K / 32;
    LOADG(0);
    STOREBUF(0);
    __syncthreads();

    const uint32_t arow = (uint32_t)(wm * 64 + (lane & 15));
    const uint32_t acol = (uint32_t)((lane >> 4) * 8);
    const uint32_t brw  = (uint32_t)(wn * 32 + (lane & 7));
    const uint32_t bcl  = (uint32_t)(((lane >> 3) & 1) * 8);

    int buf = 0;
    for (int ck = 0; ck < nchunk; ck++) {
        if (ck + 1 < nchunk) LOADG((ck + 1) * 32);

        const uint32_t base = sb + (uint32_t)buf * BUFSTR;
#pragma unroll
        for (int ks = 0; ks < 2; ks++) {
            uint32_t ah[4][4], al[4][4];
#pragma unroll
            for (int mt = 0; mt < 4; mt++) {
                uint32_t aoff = ((arow + mt * 16) * ASTR + acol + ks * 16) * 2;
                LDSM_X4(ah[mt][0], ah[mt][1], ah[mt][2], ah[mt][3], base + OAH + aoff);
                LDSM_X4(al[mt][0], al[mt][1], al[mt][2], al[mt][3], base + OAL + aoff);
            }
#pragma unroll
            for (int nt = 0; nt < 4; nt++) {
                uint32_t boff = ((brw + nt * 8) * ASTR + bcl + ks * 16) * 2;
                uint32_t bh0, bh1, bl0, bl1;
                LDSM_X2(bh0, bh1, base + OBH + boff);
                LDSM_X2(bl0, bl1, base + OBL + boff);
#pragma unroll
                for (int mt = 0; mt < 4; mt++) {
                    MMA16816(acc[mt][nt], ah[mt][0], ah[mt][1], ah[mt][2], ah[mt][3], bh0, bh1);
                    MMA16816(acc[mt][nt], ah[mt][0], ah[mt][1], ah[mt][2], ah[mt][3], bl0, bl1);
                    MMA16816(acc[mt][nt], al[mt][0], al[mt][1], al[mt][2], al[mt][3], bh0, bh1);
                }
            }
        }
        if (ck + 1 < nchunk) STOREBUF(buf ^ 1);
        __syncthreads();
        buf ^= 1;
    }

#pragma unroll
    for (int mt = 0; mt < 4; mt++) {
        int r0 = brow + wm * 64 + mt * 16 + (lane >> 2);
#pragma unroll
        for (int nt = 0; nt < 4; nt++) {
            int c = bcol + wn * 32 + nt * 8 + (lane & 3) * 2;
            float bx = 0.f, by = 0.f;
            if (bias) { bx = bias[c]; by = bias[c + 1]; }
            float2 o0, o1;
            o0.x = acc[mt][nt][0] + bx; o0.y = acc[mt][nt][1] + by;
            o1.x = acc[mt][nt][2] + bx; o1.y = acc[mt][nt][3] + by;
            if (C) {
                *(float2*)(C + (size_t)r0 * N + c)       = o0;
                *(float2*)(C + (size_t)(r0 + 8) * N + c) = o1;
            }
            if (Oh) {
                uint32_t h0 = bfpack(o0.x, o0.y);
                uint32_t l0 = bfpack(o0.x - bflo(h0), o0.y - bfhi(h0));
                uint32_t h1 = bfpack(o1.x, o1.y);
                uint32_t l1 = bfpack(o1.x - bflo(h1), o1.y - bfhi(h1));
                *(uint32_t*)(Oh + (size_t)r0 * N + c)       = h0;
                *(uint32_t*)(Ol + (size_t)r0 * N + c)       = l0;
                *(uint32_t*)(Oh + (size_t)(r0 + 8) * N + c) = h1;
                *(uint32_t*)(Ol + (size_t)(r0 + 8) * N + c) = l1;
            }
        }
    }
#undef LOADG
#undef STOREBUF
}

// ================= fused flash attention (split HMMA, split output) ========
#define QSTR   72
#define VSTR   72
#define PSTR   136
#define QKTILE (128*144)
#define FA_OQH 0
#define FA_OQL (QKTILE)
#define FA_OKH (2*QKTILE)
#define FA_OKL (3*QKTILE)
#define FA_OVH (4*QKTILE)
#define FA_OVL (5*QKTILE)
#define FA_OPH (6*QKTILE)
#define FA_OPL (FA_OPH + 128*272)
#define FA_M   (FA_OPL + 128*272)
#define FA_L   (FA_M + 512)
#define FA_R   (FA_L + 512)
#define FA_PMX (FA_R + 512)
#define FA_PSM (FA_PMX + 2048)
#define FA_TAB (FA_PSM + 2048)
#define DSMF   (FA_TAB + 1024)

__global__ __launch_bounds__(256) void flash_k(
    const float* __restrict__ Q, int ldq,
    const float* __restrict__ Kc, int ldk,
    const float* __restrict__ V, int ldv,
    __nv_bfloat16* __restrict__ Oh, __nv_bfloat16* __restrict__ Ol)
{
    extern __shared__ char smem[];
    const uint32_t sb = smem_to_u32(smem);
    float* mrow = (float*)(smem + FA_M);
    float* lrow = (float*)(smem + FA_L);
    float* rrow = (float*)(smem + FA_R);
    float* pmax = (float*)(smem + FA_PMX);
    float* psum = (float*)(smem + FA_PSM);
    float* tab  = (float*)(smem + FA_TAB);
    const int tid = threadIdx.x, lane = tid & 31, wid = tid >> 5;
    const int bh = blockIdx.y, b = bh >> 4, h = bh & 15;
    const int i0 = blockIdx.x * 128;
    const int wm = wid & 1, wn = wid >> 1;
    const int wmv = wid & 3, wnv = wid >> 2;

    const int lr2 = tid >> 1, ls2 = tid & 1;

    {
        const float* qp = Q + (size_t)(b * SEQ + i0 + lr2) * ldq + h * HDIM + ls2 * 32;
        const uint32_t off = (uint32_t)(lr2 * QSTR + ls2 * 32) * 2;
        uint32_t hh[16], ll[16];
#pragma unroll
        for (int i = 0; i < 8; i++) {
            float4 x = *(const float4*)(qp + i * 4);
            uint32_t h0 = bfpack(x.x, x.y), h1 = bfpack(x.z, x.w);
            hh[2*i] = h0; hh[2*i+1] = h1;
            ll[2*i]   = bfpack(x.x - bflo(h0), x.y - bfhi(h0));
            ll[2*i+1] = bfpack(x.z - bflo(h1), x.w - bfhi(h1));
        }
#pragma unroll
        for (int i = 0; i < 4; i++) {
            STS128(sb + FA_OQH + off + i * 16, hh[4*i], hh[4*i+1], hh[4*i+2], hh[4*i+3]);
            STS128(sb + FA_OQL + off + i * 16, ll[4*i], ll[4*i+1], ll[4*i+2], ll[4*i+3]);
        }
    }
    if (tid < 128) { mrow[tid] = -1e30f; lrow[tid] = 0.f; }

    float oacc[2][4][4];
#pragma unroll
    for (int i = 0; i < 2; i++)
#pragma unroll
        for (int j = 0; j < 4; j++)
#pragma unroll
            for (int e = 0; e < 4; e++) oacc[i][j][e] = 0.f;

    const float scale = 0.03125f;
    const uint32_t arow = (uint32_t)(wm * 64 + (lane & 15));
    const uint32_t acol = (uint32_t)((lane >> 4) * 8);
    const uint32_t brw  = (uint32_t)(wn * 32 + (lane & 7));
    const uint32_t bcl  = (uint32_t)(((lane >> 3) & 1) * 8);
    const uint32_t arv  = (uint32_t)(wmv * 32 + (lane & 15));
    const uint32_t klv  = (uint32_t)(lane & 15);
    const int lr4 = lane >> 2, lc4 = (lane & 3) * 2;

    for (int jt = 0; jt < 8; jt++) {
        const int j0 = jt * 128;
        __syncthreads();
        tab[tid] = __expf(-0.01f * fabsf((float)(i0 - j0 + tid - 128)));

        {
            const float* kp = Kc + (size_t)(b * SEQ + j0 + lr2) * ldk + h * HDIM + ls2 * 32;
            const float* vp = V  + (size_t)(b * SEQ + j0 + lr2) * ldv + h * HDIM + ls2 * 32;
            const uint32_t offk = (uint32_t)(lr2 * QSTR + ls2 * 32) * 2;
            const uint32_t offv = (uint32_t)(lr2 * VSTR + ls2 * 32) * 2;
            uint32_t hh[16], ll[16];
#pragma unroll
            for (int i = 0; i < 8; i++) {
                float4 x = *(const float4*)(kp + i * 4);
                uint32_t h0 = bfpack(x.x, x.y), h1 = bfpack(x.z, x.w);
                hh[2*i] = h0; hh[2*i+1] = h1;
                ll[2*i]   = bfpack(x.x - bflo(h0), x.y - bfhi(h0));
                ll[2*i+1] = bfpack(x.z - bflo(h1), x.w - bfhi(h1));
            }
#pragma unroll
            for (int i = 0; i < 4; i++) {
                STS128(sb + FA_OKH + offk + i * 16, hh[4*i], hh[4*i+1], hh[4*i+2], hh[4*i+3]);
                STS128(sb + FA_OKL + offk + i * 16, ll[4*i], ll[4*i+1], ll[4*i+2], ll[4*i+3]);
            }
#pragma unroll
            for (int i = 0; i < 8; i++) {
                float4 x = *(const float4*)(vp + i * 4);
                uint32_t h0 = bfpack(x.x, x.y), h1 = bfpack(x.z, x.w);
                hh[2*i] = h0; hh[2*i+1] = h1;
                ll[2*i]   = bfpack(x.x - bflo(h0), x.y - bfhi(h0));
                ll[2*i+1] = bfpack(x.z - bflo(h1), x.w - bfhi(h1));
            }
#pragma unroll
            for (int i = 0; i < 4; i++) {
                STS128(sb + FA_OVH + offv + i * 16, hh[4*i], hh[4*i+1], hh[4*i+2], hh[4*i+3]);
                STS128(sb + FA_OVL + offv + i * 16, ll[4*i], ll[4*i+1], ll[4*i+2], ll[4*i+3]);
            }
        }
        __syncthreads();

        float sacc[4][4][4];
#pragma unroll
        for (int i = 0; i < 4; i++)
#pragma unroll
            for (int j = 0; j < 4; j++)
#pragma unroll
                for (int e = 0; e < 4; e++) sacc[i][j][e] = 0.f;
#pragma unroll
        for (int ks = 0; ks < 4; ks++) {
            uint32_t ah[4][4], al[4][4];
#pragma unroll
            for (int mt = 0; mt < 4; mt++) {
                uint32_t aoff = ((arow + mt * 16) * QSTR + acol + ks * 16) * 2;
                LDSM_X4(ah[mt][0], ah[mt][1], ah[mt][2], ah[mt][3], sb + FA_OQH + aoff);
                LDSM_X4(al[mt][0], al[mt][1], al[mt][2], al[mt][3], sb + FA_OQL + aoff);
            }
#pragma unroll
            for (int nt = 0; nt < 4; nt++) {
                uint32_t boff = ((brw + nt * 8) * QSTR + bcl + ks * 16) * 2;
                uint32_t bh0, bh1, bl0, bl1;
                LDSM_X2(bh0, bh1, sb + FA_OKH + boff);
                LDSM_X2(bl0, bl1, sb + FA_OKL + boff);
#pragma unroll
                for (int mt = 0; mt < 4; mt++) {
                    MMA16816(sacc[mt][nt], ah[mt][0], ah[mt][1], ah[mt][2], ah[mt][3], bh0, bh1);
                    MMA16816(sacc[mt][nt], ah[mt][0], ah[mt][1], ah[mt][2], ah[mt][3], bl0, bl1);
                    MMA16816(sacc[mt][nt], al[mt][0], al[mt][1], al[mt][2], al[mt][3], bh0, bh1);
                }
            }
        }

#pragma unroll
        for (int mt = 0; mt < 4; mt++) {
            int ri = wm * 64 + mt * 16 + lr4;
            float mx0 = -1e30f, mx1 = -1e30f;
#pragma unroll
            for (int nt = 0; nt < 4; nt++) {
                int cj = wn * 32 + nt * 8 + lc4;
                int d0 = ri - cj + 128;
                sacc[mt][nt][0] *= scale * tab[d0];
                sacc[mt][nt][1] *= scale * tab[d0 - 1];
                sacc[mt][nt][2] *= scale * tab[d0 + 8];
                sacc[mt][nt][3] *= scale * tab[d0 + 7];
                mx0 = fmaxf(mx0, fmaxf(sacc[mt][nt][0], sacc[mt][nt][1]));
                mx1 = fmaxf(mx1, fmaxf(sacc[mt][nt][2], sacc[mt][nt][3]));
            }
            mx0 = fmaxf(mx0, __shfl_xor_sync(0xffffffffu, mx0, 1));
            mx0 = fmaxf(mx0, __shfl_xor_sync(0xffffffffu, mx0, 2));
            mx1 = fmaxf(mx1, __shfl_xor_sync(0xffffffffu, mx1, 1));
            mx1 = fmaxf(mx1, __shfl_xor_sync(0xffffffffu, mx1, 2));
            if ((lane & 3) == 0) {
                pmax[wn * 128 + ri] = mx0;
                pmax[wn * 128 + ri + 8] = mx1;
            }
        }
        __syncthreads();
        if (tid < 128) {
            float mo = mrow[tid];
            float mn = fmaxf(fmaxf(pmax[tid], pmax[128 + tid]),
                             fmaxf(pmax[256 + tid], pmax[384 + tid]));
            mn = fmaxf(mo, mn);
            rrow[tid] = __expf(mo - mn);
            mrow[tid] = mn;
        }
        __syncthreads();

#pragma unroll
        for (int mt = 0; mt < 4; mt++) {
            int row0 = wm * 64 + mt * 16 + lr4;
            int row1 = row0 + 8;
            float m0 = mrow[row0], m1 = mrow[row1];
            float s0 = 0.f, s1 = 0.f;
#pragma unroll
            for (int nt = 0; nt < 4; nt++) {
                int col = wn * 32 + nt * 8 + lc4;
                float p0 = __expf(sacc[mt][nt][0] - m0);
                float p1 = __expf(sacc[mt][nt][1] - m0);
                float p2 = __expf(sacc[mt][nt][2] - m1);
                float p3 = __expf(sacc[mt][nt][3] - m1);
                s0 += p0 + p1; s1 += p2 + p3;
                uint32_t ph0 = bfpack(p0, p1);
                uint32_t pl0 = bfpack(p0 - bflo(ph0), p1 - bfhi(ph0));
                uint32_t ph1 = bfpack(p2, p3);
                uint32_t pl1 = bfpack(p2 - bflo(ph1), p3 - bfhi(ph1));
                uint32_t a0 = (uint32_t)(row0 * PSTR + col) * 2;
                uint32_t a1 = (uint32_t)(row1 * PSTR + col) * 2;
                STS32(sb + FA_OPH + a0, ph0);
                STS32(sb + FA_OPL + a0, pl0);
                STS32(sb + FA_OPH + a1, ph1);
                STS32(sb + FA_OPL + a1, pl1);
            }
            s0 += __shfl_xor_sync(0xffffffffu, s0, 1);
            s0 += __shfl_xor_sync(0xffffffffu, s0, 2);
            s1 += __shfl_xor_sync(0xffffffffu, s1, 1);
            s1 += __shfl_xor_sync(0xffffffffu, s1, 2);
            if ((lane & 3) == 0) {
                psum[wn * 128 + row0] = s0;
                psum[wn * 128 + row1] = s1;
            }
        }
        __syncthreads();
        if (tid < 128)
            lrow[tid] = lrow[tid] * rrow[tid]
                      + psum[tid] + psum[128 + tid] + psum[256 + tid] + psum[384 + tid];

#pragma unroll
        for (int mt = 0; mt < 2; mt++) {
            int r0 = wmv * 32 + mt * 16 + lr4;
            float f0 = rrow[r0], f1 = rrow[r0 + 8];
#pragma unroll
            for (int nt = 0; nt < 4; nt++) {
                oacc[mt][nt][0] *= f0; oacc[mt][nt][1] *= f0;
                oacc[mt][nt][2] *= f1; oacc[mt][nt][3] *= f1;
            }
        }
#pragma unroll
        for (int ks = 0; ks < 8; ks++) {
            uint32_t ah[2][4], al[2][4];
#pragma unroll
            for (int mt = 0; mt < 2; mt++) {
                uint32_t aoff = ((arv + mt * 16) * PSTR + (uint32_t)((lane >> 4) * 8) + ks * 16) * 2;
                LDSM_X4(ah[mt][0], ah[mt][1], ah[mt][2], ah[mt][3], sb + FA_OPH + aoff);
                LDSM_X4(al[mt][0], al[mt][1], al[mt][2], al[mt][3], sb + FA_OPL + aoff);
            }
#pragma unroll
            for (int nt = 0; nt < 4; nt++) {
                uint32_t boff = ((ks * 16 + klv) * VSTR + wnv * 32 + nt * 8) * 2;
                uint32_t bh0, bh1, bl0, bl1;
                LDSM_X2T(bh0, bh1, sb + FA_OVH + boff);
                LDSM_X2T(bl0, bl1, sb + FA_OVL + boff);
#pragma unroll
                for (int mt = 0; mt < 2; mt++) {
                    MMA16816(oacc[mt][nt], ah[mt][0], ah[mt][1], ah[mt][2], ah[mt][3], bh0, bh1);
                    MMA16816(oacc[mt][nt], ah[mt][0], ah[mt][1], ah[mt][2], ah[mt][3], bl0, bl1);
                    MMA16816(oacc[mt][nt], al[mt][0], al[mt][1], al[mt][2], al[mt][3], bh0, bh1);
                }
            }
        }
    }

    __syncthreads();
    // ---- normalize + split-write O ----
#pragma unroll
    for (int mt = 0; mt < 2; mt++) {
        int r0 = wmv * 32 + mt * 16 + lr4;
        float inv0 = 1.0f / lrow[r0];
        float inv1 = 1.0f / lrow[r0 + 8];
#pragma unroll
        for (int nt = 0; nt < 4; nt++) {
            int c = h * HDIM + wnv * 32 + nt * 8 + lc4;
            float o00 = oacc[mt][nt][0] * inv0, o01 = oacc[mt][nt][1] * inv0;
            float o10 = oacc[mt][nt][2] * inv1, o11 = oacc[mt][nt][3] * inv1;
            uint32_t h0 = bfpack(o00, o01);
            uint32_t l0 = bfpack(o00 - bflo(h0), o01 - bfhi(h0));
            uint32_t h1 = bfpack(o10, o11);
            uint32_t l1 = bfpack(o10 - bflo(h1), o11 - bfhi(h1));
            size_t p0 = (size_t)(b * SEQ + i0 + r0) * DM + c;
            size_t p1 = (size_t)(b * SEQ + i0 + r0 + 8) * DM + c;
            *(uint32_t*)(Oh + p0) = h0;
            *(uint32_t*)(Ol + p0) = l0;
            *(uint32_t*)(Oh + p1) = h1;
            *(uint32_t*)(Ol + p1) = l1;
        }
    }
}

// ---------------- FFMA2 SGEMM (kept for the K=50 embedding GEMM) -----------
__global__ __launch_bounds__(256) void sgemm2_k(
    int M, int N, int K,
    const float* __restrict__ A, const float* __restrict__ B,
    const float* __restrict__ bias, float* __restrict__ C)
{
    __shared__ __align__(16) float As[KT][128];
    __shared__ __align__(16) float Bs[KT][128];
    const int tid  = threadIdx.x;
    const int brow = blockIdx.y * 128;
    const int bcol = blockIdx.x * 128;
    const int ty = tid >> 4, tx = tid & 15;
    const int ar = tid >> 1, aks = (tid & 1) * 8;

    unsigned long long acc[8][4];
#pragma unroll
    for (int i = 0; i < 8; i++)
#pragma unroll
        for (int j = 0; j < 4; j++) acc[i][j] = 0ULL;

    for (int k0 = 0; k0 < K; k0 += KT) {
#pragma unroll
        for (int i = 0; i < 8; i++) {
            int kk = aks + i;
            As[kk][ar] = (k0 + kk < K) ? A[(size_t)(brow + ar) * K + k0 + kk] : 0.f;
        }
#pragma unroll
        for (int p = 0; p < 2; p++) {
            int id = p * 256 + tid;
            int kk = id >> 5, c4 = (id & 31) * 4;
            float4 bv = make_float4(0.f, 0.f, 0.f, 0.f);
            if (k0 + kk < K) bv = *(const float4*)(B + (size_t)(k0 + kk) * N + bcol + c4);
            *(float4*)&Bs[kk][c4] = bv;
        }
        __syncthreads();
#pragma unroll
        for (int kk = 0; kk < KT; kk++) {
            float4 a0 = *(const float4*)&As[kk][ty * 4];
            float4 a1 = *(const float4*)&As[kk][64 + ty * 4];
            float4 b0 = *(const float4*)&Bs[kk][tx * 4];
            float4 b1 = *(const float4*)&Bs[kk][64 + tx * 4];
            unsigned long long rb[4] = { pk2(b0.x, b0.y), pk2(b0.z, b0.w),
                                         pk2(b1.x, b1.y), pk2(b1.z, b1.w) };
            float ra[8] = { a0.x, a0.y, a0.z, a0.w, a1.x, a1.y, a1.z, a1.w };
#pragma unroll
            for (int i = 0; i < 8; i++) {
                unsigned long long ad = pk2(ra[i], ra[i]);
#pragma unroll
                for (int j = 0; j < 4; j++) acc[i][j] = ffma2(ad, rb[j], acc[i][j]);
            }
        }
        __syncthreads();
    }
#pragma unroll
    for (int ih = 0; ih < 2; ih++)
#pragma unroll
    for (int ii = 0; ii < 4; ii++) {
        int i = ih * 4 + ii;
        int r = brow + ih * 64 + ty * 4 + ii;
#pragma unroll
        for (int jh = 0; jh < 2; jh++) {
            int c = bcol + jh * 64 + tx * 4;
            float2 p0 = up2(acc[i][jh * 2]);
            float2 p1 = up2(acc[i][jh * 2 + 1]);
            float4 o; o.x = p0.x; o.y = p0.y; o.z = p1.x; o.w = p1.y;
            if (bias) { o.x += bias[c]; o.y += bias[c+1]; o.z += bias[c+2]; o.w += bias[c+3]; }
            *(float4*)(C + (size_t)r * N + c) = o;
        }
    }
}

// ---------------- Fourier token features -----------------------------------
__global__ void fourier_k(const int* __restrict__ src, const float* __restrict__ a_n,
                          const float* __restrict__ b_n, float* __restrict__ F)
{
    int idx = blockIdx.x * blockDim.x + threadIdx.x;
    if (idx >= ROWS * NFR) return;
    int bs = idx / NFR, n = idx % NFR;
    int tok = src[bs];
    float x   = (float)tok * (1.0f / (float)VOC);
    float ang = 6.28318530717958647692f * (float)(n + 1) * x;
    F[idx] = a_n[tok * NFR + n] * cosf(ang) + b_n[tok * NFR + n] * sinf(ang);
}

// ---------------- h += sinusoidal PE ---------------------------------------
__global__ void addpe_k(float* __restrict__ h)
{
    int idx = blockIdx.x * blockDim.x + threadIdx.x;
    if (idx >= ROWS * DM) return;
    int d = idx & (DM - 1);
    int s = (idx / DM) & (SEQ - 1);
    float div = expf(-(float)(d & ~1) * 8.99447301948846e-3f);
    float ang = (float)s * div;
    h[idx] += (d & 1) ? cosf(ang) : sinf(ang);
}

// ---------------------------------------------------------------------------
extern "C" void kernel_launch(void* const* d_in, const int* in_sizes, int n_in,
                              void* d_out, int out_size)
{
    const int*   src    = (const int*)  d_in[0];
    const float* a_n    = (const float*)d_in[2];
    const float* b_n    = (const float*)d_in[3];
    const float* proj_w = (const float*)d_in[4];
    const float* proj_b = (const float*)d_in[5];
    const float* rule   = (const float*)d_in[6];
    const float* Wq     = (const float*)d_in[7];
    const float* Wk     = (const float*)d_in[8];
    const float* Wv     = (const float*)d_in[9];
    const float* Wo     = (const float*)d_in[10];
    const float* Wdown  = (const float*)d_in[11];
    const float* Wup_k  = (const float*)d_in[12];
    const float* Wup_v  = (const float*)d_in[13];
    const float* Wout   = (const float*)d_in[14];
    const float* bout   = (const float*)d_in[15];
    float* out = (float*)d_out;

    float *h, *t, *krvr, *four;
    __nv_bfloat16 *wbh, *wbl, *ah, *al, *hh, *hl, *lh, *ll;
    cudaGetSymbolAddress((void**)&h,    g_h);
    cudaGetSymbolAddress((void**)&t,    g_t);
    cudaGetSymbolAddress((void**)&krvr, g_krvr);
    cudaGetSymbolAddress((void**)&four, g_four);
    cudaGetSymbolAddress((void**)&wbh,  g_wbh);
    cudaGetSymbolAddress((void**)&wbl,  g_wbl);
    cudaGetSymbolAddress((void**)&ah,   g_ah);
    cudaGetSymbolAddress((void**)&al,   g_al);
    cudaGetSymbolAddress((void**)&hh,   g_hh);
    cudaGetSymbolAddress((void**)&hl,   g_hl);
    cudaGetSymbolAddress((void**)&lh,   g_lh);
    cudaGetSymbolAddress((void**)&ll,   g_ll);

    cudaFuncSetAttribute(gemm_mma, cudaFuncAttributeMaxDynamicSharedMemorySize, DSMG);
    cudaFuncSetAttribute(flash_k,  cudaFuncAttributeMaxDynamicSharedMemorySize, DSMF);

    // ---- transpose + split all weights (batched over layers) ----
    {
        const size_t SDD = (size_t)DM * DM, SDH = (size_t)DM * DLAT;
        wsplit_k<<<dim3(DM/64, DM/64, 1), 256>>>(rule, nullptr, DM, DM, 0, 0,
                                                 wbh + OFF_RULE, wbl + OFF_RULE);
        wsplit_k<<<dim3(DM/64, DM/64, NL), 256>>>(Wq, nullptr, DM, DM, SDD, LSTRIDE,
                                                  wbh + OFF_L(0) + LOFF_Q, wbl + OFF_L(0) + LOFF_Q);
        // kvsum = Wk + Wv (element-wise), split once
        wsplit_k<<<dim3(DM/64, DM/64, NL), 256>>>(Wk, Wv, DM, DM, SDD, LSTRIDE,
                                                  wbh + OFF_L(0) + LOFF_KV, wbl + OFF_L(0) + LOFF_KV);
        wsplit_k<<<dim3(DM/64, DM/64, NL), 256>>>(Wo, nullptr, DM, DM, SDD, LSTRIDE,
                                                  wbh + OFF_L(0) + LOFF_WO, wbl + OFF_L(0) + LOFF_WO);
        wsplit_k<<<dim3(DLAT/64, DM/64, NL), 256>>>(Wdown, nullptr, DM, DLAT, SDH, LSTRIDE,
                                                    wbh + OFF_L(0) + LOFF_DOWN, wbl + OFF_L(0) + LOFF_DOWN);
        wsplit_k<<<dim3(DM/64, DLAT/64, NL), 256>>>(Wup_k, nullptr, DLAT, DM, SDH, LSTRIDE,
                                                    wbh + OFF_L(0) + LOFF_UP, wbl + OFF_L(0) + LOFF_UP);
        wsplit_k<<<dim3(DM/64, DLAT/64, NL), 256>>>(Wup_v, nullptr, DLAT, DM, SDH, LSTRIDE,
                                                    wbh + OFF_L(0) + LOFF_UP + WSZ_HALF,
                                                    wbl + OFF_L(0) + LOFF_UP + WSZ_HALF);
        wsplit_k<<<dim3(VOC/64, DM/64, 1), 256>>>(Wout, nullptr, DM, VOC, 0, 0,
                                                  wbh + OFF_WOUT, wbl + OFF_WOUT);
    }

    const dim3 g_up (2*DM/128, ROWS/128);
    const dim3 g_d  (DM  /128, ROWS/128);
    const dim3 g_dl (DLAT/128, ROWS/128);
    const dim3 g_voc(VOC /128, ROWS/128);
    const int N8_DD = ROWS * (DM/8);

    // ---- embedding ----
    fourier_k<<<(ROWS * NFR + 255) / 256, 256>>>(src, a_n, b_n, four);
    sgemm2_k<<<g_d, 256>>>(ROWS, DM, NFR, four, proj_w, proj_b, t);
    asplit_k<<<(N8_DD + 255)/256, 256>>>(t, N8_DD, ah, al);
    gemm_mma<<<g_d, 256, DSMG>>>(ROWS, DM, DM, ah, al, wbh + OFF_RULE, wbl + OFF_RULE,
                                 nullptr, h, nullptr, nullptr);
    addpe_k<<<(ROWS * DM + 255) / 256, 256>>>(h);
    asplit_k<<<(N8_DD + 255)/256, 256>>>(h, N8_DD, hh, hl);

    // ---- layers ----
    for (int l = 0; l < NL; l++) {
        size_t o = OFF_L(l);
        const __nv_bfloat16 *qh = wbh+o+LOFF_Q,    *ql = wbl+o+LOFF_Q;
        const __nv_bfloat16 *kvh= wbh+o+LOFF_KV,   *kvl= wbl+o+LOFF_KV;
        const __nv_bfloat16 *oh = wbh+o+LOFF_WO,   *ol = wbl+o+LOFF_WO;
        const __nv_bfloat16 *dh = wbh+o+LOFF_DOWN, *dl = wbl+o+LOFF_DOWN;
        const __nv_bfloat16 *uh = wbh+o+LOFF_UP,   *ul = wbl+o+LOFF_UP;

        // q (fp32 for flash)
        gemm_mma<<<g_d, 256, DSMG>>>(ROWS, DM, DM, hh, hl, qh, ql,
                                     nullptr, t, nullptr, nullptr);
        // k+v via pre-added weights, split-out directly
        gemm_mma<<<g_d, 256, DSMG>>>(ROWS, DM, DM, hh, hl, kvh, kvl,
                                     nullptr, nullptr, ah, al);
        // down -> lat split-out
        gemm_mma<<<g_dl, 256, DSMG>>>(ROWS, DLAT, DM, ah, al, dh, dl,
                                      nullptr, nullptr, lh, ll);
        // fused up -> krvr fp32
        gemm_mma<<<g_up, 256, DSMG>>>(ROWS, 2*DM, DLAT, lh, ll, uh, ul,
                                      nullptr, krvr, nullptr, nullptr);
        // flash: split-out attention output
        flash_k<<<dim3(SEQ/128, BSZ*NH), 256, DSMF>>>(t, DM, krvr, 2*DM,
                                                      krvr + DM, 2*DM, ah, al);
        // Wo -> h split-out (feeds next layer / vocab)
        gemm_mma<<<g_d, 256, DSMG>>>(ROWS, DM, DM, ah, al, oh, ol,
                                     nullptr, nullptr, hh, hl);
    }

    // ---- vocab projection ----
    gemm_mma<<<g_voc, 256, DSMG>>>(ROWS, VOC, DM, hh, hl, wbh + OFF_WOUT, wbl + OFF_WOUT,
                                   bout, out, nullptr, nullptr);
}